// round 1
// baseline (speedup 1.0000x reference)
#include <cuda_runtime.h>
#include <math.h>

#define BB 2
#define NN 2048
#define CC 1024
#define HH 16
#define HD 64
#define M_ROWS (BB*NN)   // 4096

// Scratch (device globals: allocation-free, graph-capture safe)
__device__ float g_qkv[M_ROWS * 3 * CC];   // [b*N+n][3*C] ; d = part*1024 + h*64 + e
__device__ float g_ao [M_ROWS * CC];       // attention output in [B,N,C]

// ---------------------------------------------------------------------------
// SGEMM (NT): C[m][n] = sum_k A[m][k] * B[n][k] (+ bias[n])
// BM=BN=64, BK=16, 256 threads, 4x4 micro-tile per thread.
// ---------------------------------------------------------------------------
__global__ __launch_bounds__(256) void gemm_nt_kernel(
    const float* __restrict__ A, const float* __restrict__ Bm,
    const float* __restrict__ bias, float* __restrict__ C,
    int M, int Nn, int K)
{
    const int BK = 16;
    __shared__ float As[16][64];
    __shared__ float Bs[16][64];
    int tid = threadIdx.x;
    int tx = tid & 15;
    int ty = tid >> 4;
    int m0 = blockIdx.y * 64;
    int n0 = blockIdx.x * 64;

    float acc[4][4] = {};

    for (int k0 = 0; k0 < K; k0 += BK) {
        #pragma unroll
        for (int r = 0; r < 4; ++r) {
            int idx = tid + r * 256;
            int mm = idx >> 4;
            int kk = idx & 15;
            As[kk][mm] = A[(size_t)(m0 + mm) * K + k0 + kk];
            Bs[kk][mm] = Bm[(size_t)(n0 + mm) * K + k0 + kk];
        }
        __syncthreads();
        #pragma unroll
        for (int k = 0; k < BK; ++k) {
            float4 a = *reinterpret_cast<const float4*>(&As[k][ty * 4]);
            float4 b = *reinterpret_cast<const float4*>(&Bs[k][tx * 4]);
            float av[4] = {a.x, a.y, a.z, a.w};
            float bv[4] = {b.x, b.y, b.z, b.w};
            #pragma unroll
            for (int j = 0; j < 4; ++j)
                #pragma unroll
                for (int i = 0; i < 4; ++i)
                    acc[j][i] += av[j] * bv[i];
        }
        __syncthreads();
    }

    float bz[4] = {0.f, 0.f, 0.f, 0.f};
    if (bias) {
        #pragma unroll
        for (int i = 0; i < 4; ++i) bz[i] = bias[n0 + tx * 4 + i];
    }
    #pragma unroll
    for (int j = 0; j < 4; ++j) {
        int m = m0 + ty * 4 + j;
        float4 o = make_float4(acc[j][0] + bz[0], acc[j][1] + bz[1],
                               acc[j][2] + bz[2], acc[j][3] + bz[3]);
        *reinterpret_cast<float4*>(&C[(size_t)m * Nn + n0 + tx * 4]) = o;
    }
}

// ---------------------------------------------------------------------------
// L2-normalize q and k rows (hd=64) in place; fold scale=0.125 into q.
// One warp per (b,n,part,h) row. 131072 rows total.
// ---------------------------------------------------------------------------
__global__ __launch_bounds__(256) void norm_qk_kernel()
{
    int gw   = (blockIdx.x * blockDim.x + threadIdx.x) >> 5;
    int lane = threadIdx.x & 31;
    int bn   = gw >> 5;          // 0..4095
    int rem  = gw & 31;
    int part = rem >> 4;         // 0 = q, 1 = k
    int h    = rem & 15;

    float* p = g_qkv + (size_t)bn * 3072 + part * 1024 + h * 64;
    float x0 = p[lane];
    float x1 = p[lane + 32];
    float s = x0 * x0 + x1 * x1;
    #pragma unroll
    for (int o = 16; o; o >>= 1) s += __shfl_xor_sync(0xffffffffu, s, o);
    float inv = 1.0f / (sqrtf(s) + 1e-8f);
    if (part == 0) inv *= 0.125f;    // scale = hd^-0.5 folded into q
    p[lane]      = x0 * inv;
    p[lane + 32] = x1 * inv;
}

// ---------------------------------------------------------------------------
// Flash-style attention. Block = 64 queries of one (b,h). 256 threads.
// score(i,j) = (q_i . k_j) * s_j, masked to 0 if !(s_j > s_i - 0.1).
// Online softmax across 32 key tiles of 64. O accumulated in registers (4x4).
// ---------------------------------------------------------------------------
#define SS 65   // padded Ssh row stride (bank-conflict mitigation)

__global__ __launch_bounds__(256) void attn_kernel(
    const float* __restrict__ cls_score, const int* __restrict__ use_mask_p)
{
    extern __shared__ float sm[];
    float* Qs   = sm;                 // [e][q] 64x64 (e-major)
    float* Ks   = Qs + 4096;          // [e][k] 64x64 (e-major)
    float* Vs   = Ks + 4096;          // [k][e] 64x64
    float* Ssh  = Vs + 4096;          // [q][k] stride SS
    float* sq   = Ssh + 64 * SS;
    float* sk   = sq + 64;
    float* mrow = sk + 64;
    float* lrow = mrow + 64;
    float* arow = lrow + 64;

    int tid = threadIdx.x;
    int tx = tid & 15;
    int ty = tid >> 4;
    int q0 = blockIdx.x * 64;
    int bh = blockIdx.y;
    int b = bh >> 4, h = bh & 15;
    int um = use_mask_p[0];

    const float* qbase = g_qkv + (size_t)(b * NN + q0) * 3072 + h * 64;
    #pragma unroll
    for (int r = 0; r < 4; ++r) {
        int i4 = tid + r * 256;       // float4 index over 64x64
        int row = i4 >> 4;
        int e4 = (i4 & 15) << 2;
        float4 v = *reinterpret_cast<const float4*>(qbase + (size_t)row * 3072 + e4);
        Qs[(e4 + 0) * 64 + row] = v.x;
        Qs[(e4 + 1) * 64 + row] = v.y;
        Qs[(e4 + 2) * 64 + row] = v.z;
        Qs[(e4 + 3) * 64 + row] = v.w;
    }
    if (tid < 64) {
        sq[tid] = cls_score[q0 + tid];
        mrow[tid] = -1e30f;
        lrow[tid] = 0.0f;
    }
    __syncthreads();

    float sqj[4];
    #pragma unroll
    for (int j = 0; j < 4; ++j) sqj[j] = sq[ty * 4 + j];

    float o[4][4] = {};

    for (int kt = 0; kt < NN / 64; ++kt) {
        int k0g = kt * 64;
        const float* kbase = g_qkv + (size_t)(b * NN + k0g) * 3072 + 1024 + h * 64;
        const float* vbase = kbase + 1024;
        #pragma unroll
        for (int r = 0; r < 4; ++r) {
            int i4 = tid + r * 256;
            int row = i4 >> 4;
            int e4 = (i4 & 15) << 2;
            float4 kv = *reinterpret_cast<const float4*>(kbase + (size_t)row * 3072 + e4);
            Ks[(e4 + 0) * 64 + row] = kv.x;
            Ks[(e4 + 1) * 64 + row] = kv.y;
            Ks[(e4 + 2) * 64 + row] = kv.z;
            Ks[(e4 + 3) * 64 + row] = kv.w;
            float4 vv = *reinterpret_cast<const float4*>(vbase + (size_t)row * 3072 + e4);
            *reinterpret_cast<float4*>(&Vs[row * 64 + e4]) = vv;
        }
        if (tid < 64) sk[tid] = cls_score[k0g + tid];
        __syncthreads();

        // --- S = Q K^T (4x4 micro-tile) ---
        float acc[4][4] = {};
        #pragma unroll 16
        for (int e = 0; e < 64; ++e) {
            float4 a  = *reinterpret_cast<const float4*>(&Qs[e * 64 + ty * 4]);
            float4 bk = *reinterpret_cast<const float4*>(&Ks[e * 64 + tx * 4]);
            float av[4] = {a.x, a.y, a.z, a.w};
            float bv[4] = {bk.x, bk.y, bk.z, bk.w};
            #pragma unroll
            for (int j = 0; j < 4; ++j)
                #pragma unroll
                for (int i = 0; i < 4; ++i)
                    acc[j][i] += av[j] * bv[i];
        }
        // scale by s_k, apply multiplicative mask, stage in smem
        #pragma unroll
        for (int i = 0; i < 4; ++i) {
            float skv = sk[tx * 4 + i];
            #pragma unroll
            for (int j = 0; j < 4; ++j) {
                float v = acc[j][i] * skv;
                if (um && !(skv > sqj[j] - 0.1f)) v = 0.0f;
                Ssh[(ty * 4 + j) * SS + tx * 4 + i] = v;
            }
        }
        __syncthreads();

        // --- online softmax: 4 threads per query row ---
        {
            int row = tid >> 2, p = tid & 3;
            float* srow = &Ssh[row * SS + p * 16];
            float mx = -1e30f;
            #pragma unroll
            for (int t = 0; t < 16; ++t) mx = fmaxf(mx, srow[t]);
            mx = fmaxf(mx, __shfl_xor_sync(0xffffffffu, mx, 1));
            mx = fmaxf(mx, __shfl_xor_sync(0xffffffffu, mx, 2));
            float mold = mrow[row];
            float mnew = fmaxf(mold, mx);
            float sum = 0.0f;
            #pragma unroll
            for (int t = 0; t < 16; ++t) {
                float e = __expf(srow[t] - mnew);
                srow[t] = e;
                sum += e;
            }
            sum += __shfl_xor_sync(0xffffffffu, sum, 1);
            sum += __shfl_xor_sync(0xffffffffu, sum, 2);
            if (p == 0) {
                float al = __expf(mold - mnew);
                arow[row] = al;
                lrow[row] = lrow[row] * al + sum;
                mrow[row] = mnew;
            }
        }
        __syncthreads();

        // --- rescale O, then O += P V ---
        float al[4];
        #pragma unroll
        for (int j = 0; j < 4; ++j) al[j] = arow[ty * 4 + j];
        #pragma unroll
        for (int j = 0; j < 4; ++j)
            #pragma unroll
            for (int i = 0; i < 4; ++i) o[j][i] *= al[j];

        #pragma unroll 16
        for (int k = 0; k < 64; ++k) {
            float4 v = *reinterpret_cast<const float4*>(&Vs[k * 64 + tx * 4]);
            float vv[4] = {v.x, v.y, v.z, v.w};
            #pragma unroll
            for (int j = 0; j < 4; ++j) {
                float pp = Ssh[(ty * 4 + j) * SS + k];   // broadcast across tx
                #pragma unroll
                for (int i = 0; i < 4; ++i) o[j][i] += pp * vv[i];
            }
        }
        __syncthreads();
    }

    // finalize: divide by l, write to [B,N,C] layout
    #pragma unroll
    for (int j = 0; j < 4; ++j) {
        float linv = 1.0f / lrow[ty * 4 + j];
        float* dst = g_ao + (size_t)(b * NN + q0 + ty * 4 + j) * CC + h * 64 + tx * 4;
        float4 ov = make_float4(o[j][0] * linv, o[j][1] * linv,
                                o[j][2] * linv, o[j][3] * linv);
        *reinterpret_cast<float4*>(dst) = ov;
    }
}

// ---------------------------------------------------------------------------
// Launch
// ---------------------------------------------------------------------------
static const int ATTN_SMEM_BYTES = (3 * 4096 + 64 * SS + 5 * 64) * (int)sizeof(float);

extern "C" void kernel_launch(void* const* d_in, const int* in_sizes, int n_in,
                              void* d_out, int out_size)
{
    const float* x     = (const float*)d_in[0];
    const float* cls   = (const float*)d_in[1];
    const float* qkvw  = (const float*)d_in[2];
    const float* projw = (const float*)d_in[3];
    const float* projb = (const float*)d_in[4];
    const int*   um    = (const int*)d_in[5];
    float* out = (float*)d_out;

    float* qkv = nullptr;
    float* ao  = nullptr;
    cudaGetSymbolAddress((void**)&qkv, g_qkv);
    cudaGetSymbolAddress((void**)&ao,  g_ao);

    cudaFuncSetAttribute(attn_kernel,
                         cudaFuncAttributeMaxDynamicSharedMemorySize,
                         ATTN_SMEM_BYTES);

    dim3 blk(256);
    // 1) QKV projection: [4096,1024] x [3072,1024]^T
    gemm_nt_kernel<<<dim3(3072 / 64, 4096 / 64), blk>>>(x, qkvw, nullptr, qkv,
                                                        M_ROWS, 3 * CC, CC);
    // 2) normalize q,k (fold in scale)
    norm_qk_kernel<<<(M_ROWS * 32) / 8, blk>>>();
    // 3) attention: grid (q-tiles, b*h)
    attn_kernel<<<dim3(NN / 64, BB * HH), blk, ATTN_SMEM_BYTES>>>(cls, um);
    // 4) output projection + bias
    gemm_nt_kernel<<<dim3(CC / 64, 4096 / 64), blk>>>(ao, projw, projb, out,
                                                      M_ROWS, CC, CC);
}

// round 2
// speedup vs baseline: 1.7820x; 1.7820x over previous
#include <cuda_runtime.h>
#include <cuda_bf16.h>
#include <math.h>

#define BB 2
#define NN 2048
#define CC 1024
#define HH 16
#define HD 64
#define M_ROWS (BB*NN)   // 4096

// ---------------- device scratch (allocation-free) ----------------
__device__ float g_qkv[M_ROWS * 3 * CC];        // fp32 qkv, [b*N+n][3*C]
__device__ float g_ao [M_ROWS * CC];            // attention out [B,N,C]
__device__ __nv_bfloat16 g_x_hi[M_ROWS * CC];
__device__ __nv_bfloat16 g_x_lo[M_ROWS * CC];
__device__ __nv_bfloat16 g_w1_hi[3 * CC * CC];
__device__ __nv_bfloat16 g_w1_lo[3 * CC * CC];
__device__ __nv_bfloat16 g_w2_hi[CC * CC];
__device__ __nv_bfloat16 g_w2_lo[CC * CC];
__device__ __nv_bfloat16 g_ao_hi[M_ROWS * CC];
__device__ __nv_bfloat16 g_ao_lo[M_ROWS * CC];

// ---------------- split fp32 -> bf16 hi/lo ----------------
__global__ __launch_bounds__(256) void split_kernel(
    const float* __restrict__ in, __nv_bfloat16* __restrict__ hi,
    __nv_bfloat16* __restrict__ lo, int n)
{
    int i = blockIdx.x * blockDim.x + threadIdx.x;
    if (i < n) {
        float x = in[i];
        __nv_bfloat16 h = __float2bfloat16(x);
        float r = x - __bfloat162float(h);
        hi[i] = h;
        lo[i] = __float2bfloat16(r);
    }
}

// ---------------- mma helpers ----------------
__device__ __forceinline__ void ldsm4(unsigned r[4], const void* p) {
    unsigned a = (unsigned)__cvta_generic_to_shared(p);
    asm volatile("ldmatrix.sync.aligned.m8n8.x4.shared.b16 {%0,%1,%2,%3}, [%4];"
                 : "=r"(r[0]), "=r"(r[1]), "=r"(r[2]), "=r"(r[3]) : "r"(a));
}
__device__ __forceinline__ void mma16816(float c[4], const unsigned a[4],
                                         unsigned b0, unsigned b1) {
    asm volatile(
        "mma.sync.aligned.m16n8k16.row.col.f32.bf16.bf16.f32 "
        "{%0,%1,%2,%3}, {%4,%5,%6,%7}, {%8,%9}, {%0,%1,%2,%3};"
        : "+f"(c[0]), "+f"(c[1]), "+f"(c[2]), "+f"(c[3])
        : "r"(a[0]), "r"(a[1]), "r"(a[2]), "r"(a[3]), "r"(b0), "r"(b1));
}
__device__ __forceinline__ void cp16(void* smem, const void* gmem) {
    unsigned sa = (unsigned)__cvta_generic_to_shared(smem);
    asm volatile("cp.async.cg.shared.global [%0], [%1], 16;\n" :: "r"(sa), "l"(gmem));
}

// ---------------------------------------------------------------------------
// bf16x3 GEMM (NT): C[m][n] = sum_k A[m][k]*B[n][k] (+bias). K=1024.
// A = Ah+Al, B = Bh+Bl; C = Ah Bh + Ah Bl + Al Bh (fp32 accum).
// 128x128x32 tiles, cp.async double buffer, 8 warps (2m x 4n), m16n8k16.
// ---------------------------------------------------------------------------
#define GLDA 40              // smem row stride in bf16 (32 + 8 pad)
#define TILE_B (128 * GLDA * 2)  // one 128x32 bf16 tile = 10240 bytes
#define STAGE_B (4 * TILE_B)     // Ah, Al, Bh, Bl

__global__ __launch_bounds__(256, 1) void gemm_bf16x3_kernel(
    const __nv_bfloat16* __restrict__ a_hi, const __nv_bfloat16* __restrict__ a_lo,
    const __nv_bfloat16* __restrict__ b_hi, const __nv_bfloat16* __restrict__ b_lo,
    const float* __restrict__ bias, float* __restrict__ C, int Nn)
{
    extern __shared__ char sm_raw[];
    const int K = CC;
    int tid = threadIdx.x;
    int lane = tid & 31;
    int wid = tid >> 5;
    int warp_m = wid >> 2;          // 0..1 -> 64 rows each
    int warp_n = wid & 3;           // 0..3 -> 32 cols each
    int m0 = blockIdx.y * 128;
    int n0 = blockIdx.x * 128;

    const __nv_bfloat16* gptr[4] = {a_hi, a_lo, b_hi, b_lo};
    int rowbase[4] = {m0, m0, n0, n0};

    float acc[4][4][4];
    #pragma unroll
    for (int mi = 0; mi < 4; ++mi)
        #pragma unroll
        for (int j = 0; j < 4; ++j)
            #pragma unroll
            for (int e = 0; e < 4; ++e) acc[mi][j][e] = 0.0f;

    // stage loader: 2048 16B chunks, 8 per thread
    auto load_stage = [&](int kt, int stage) {
        char* sbase = sm_raw + stage * STAGE_B;
        int k0 = kt * 32;
        #pragma unroll
        for (int t = 0; t < 8; ++t) {
            int c = tid + t * 256;
            int arr = c >> 9;
            int r = (c >> 2) & 127;
            int c16 = c & 3;
            const __nv_bfloat16* g =
                gptr[arr] + (size_t)(rowbase[arr] + r) * K + k0 + c16 * 8;
            cp16(sbase + arr * TILE_B + r * (GLDA * 2) + c16 * 16, g);
        }
    };

    const int KT = K / 32;
    load_stage(0, 0);
    asm volatile("cp.async.commit_group;");

    for (int kt = 0; kt < KT; ++kt) {
        if (kt + 1 < KT) {
            load_stage(kt + 1, (kt + 1) & 1);
            asm volatile("cp.async.commit_group;");
            asm volatile("cp.async.wait_group 1;");
        } else {
            asm volatile("cp.async.wait_group 0;");
        }
        __syncthreads();

        char* sbase = sm_raw + (kt & 1) * STAGE_B;
        const char* As = sbase;                 // Ah at +0, Al at +TILE_B
        const char* Bs = sbase + 2 * TILE_B;    // Bh at +0, Bl at +TILE_B

        #pragma unroll
        for (int ks = 0; ks < 32; ks += 16) {
            int coloff = ks + ((lane >> 4) << 3);   // + 8 for lanes 16-31
            unsigned ah[4][4], al[4][4];
            #pragma unroll
            for (int mi = 0; mi < 4; ++mi) {
                int row = warp_m * 64 + mi * 16 + (lane & 15);
                const char* p = As + row * (GLDA * 2) + coloff * 2;
                ldsm4(ah[mi], p);
                ldsm4(al[mi], p + TILE_B);
            }
            unsigned bh[2][4], bl[2][4];
            #pragma unroll
            for (int ni = 0; ni < 2; ++ni) {
                int row = warp_n * 32 + ni * 16 + (lane & 15);
                const char* p = Bs + row * (GLDA * 2) + coloff * 2;
                ldsm4(bh[ni], p);
                ldsm4(bl[ni], p + TILE_B);
            }
            #pragma unroll
            for (int mi = 0; mi < 4; ++mi) {
                #pragma unroll
                for (int j = 0; j < 4; ++j) {
                    int ni = j >> 1, od = j & 1;
                    unsigned bh0 = bh[ni][od ? 1 : 0], bh1 = bh[ni][od ? 3 : 2];
                    unsigned bl0 = bl[ni][od ? 1 : 0], bl1 = bl[ni][od ? 3 : 2];
                    mma16816(acc[mi][j], ah[mi], bh0, bh1);   // hi*hi
                    mma16816(acc[mi][j], ah[mi], bl0, bl1);   // hi*lo
                    mma16816(acc[mi][j], al[mi], bh0, bh1);   // lo*hi
                }
            }
        }
        __syncthreads();
    }

    // epilogue
    int mb = m0 + warp_m * 64 + (lane >> 2);
    int nb = n0 + warp_n * 32 + 2 * (lane & 3);
    #pragma unroll
    for (int mi = 0; mi < 4; ++mi) {
        #pragma unroll
        for (int j = 0; j < 4; ++j) {
            int col = nb + j * 8;
            float b0 = 0.f, b1 = 0.f;
            if (bias) { b0 = bias[col]; b1 = bias[col + 1]; }
            int r0 = mb + mi * 16;
            float2 v0 = make_float2(acc[mi][j][0] + b0, acc[mi][j][1] + b1);
            float2 v1 = make_float2(acc[mi][j][2] + b0, acc[mi][j][3] + b1);
            *reinterpret_cast<float2*>(&C[(size_t)r0 * Nn + col]) = v0;
            *reinterpret_cast<float2*>(&C[(size_t)(r0 + 8) * Nn + col]) = v1;
        }
    }
}

// ---------------------------------------------------------------------------
// L2-normalize q and k rows (hd=64) in place; fold scale=0.125 into q.
// ---------------------------------------------------------------------------
__global__ __launch_bounds__(256) void norm_qk_kernel()
{
    int gw   = (blockIdx.x * blockDim.x + threadIdx.x) >> 5;
    int lane = threadIdx.x & 31;
    int bn   = gw >> 5;
    int rem  = gw & 31;
    int part = rem >> 4;
    int h    = rem & 15;

    float* p = g_qkv + (size_t)bn * 3072 + part * 1024 + h * 64;
    float x0 = p[lane];
    float x1 = p[lane + 32];
    float s = x0 * x0 + x1 * x1;
    #pragma unroll
    for (int o = 16; o; o >>= 1) s += __shfl_xor_sync(0xffffffffu, s, o);
    float inv = 1.0f / (sqrtf(s) + 1e-8f);
    if (part == 0) inv *= 0.125f;
    p[lane]      = x0 * inv;
    p[lane + 32] = x1 * inv;
}

// ---------------------------------------------------------------------------
// Flash-style attention (fp32) — unchanged from R1.
// ---------------------------------------------------------------------------
#define SS 65

__global__ __launch_bounds__(256) void attn_kernel(
    const float* __restrict__ cls_score, const int* __restrict__ use_mask_p)
{
    extern __shared__ float sm[];
    float* Qs   = sm;
    float* Ks   = Qs + 4096;
    float* Vs   = Ks + 4096;
    float* Ssh  = Vs + 4096;
    float* sq   = Ssh + 64 * SS;
    float* sk   = sq + 64;
    float* mrow = sk + 64;
    float* lrow = mrow + 64;
    float* arow = lrow + 64;

    int tid = threadIdx.x;
    int tx = tid & 15;
    int ty = tid >> 4;
    int q0 = blockIdx.x * 64;
    int bh = blockIdx.y;
    int b = bh >> 4, h = bh & 15;
    int um = use_mask_p[0];

    const float* qbase = g_qkv + (size_t)(b * NN + q0) * 3072 + h * 64;
    #pragma unroll
    for (int r = 0; r < 4; ++r) {
        int i4 = tid + r * 256;
        int row = i4 >> 4;
        int e4 = (i4 & 15) << 2;
        float4 v = *reinterpret_cast<const float4*>(qbase + (size_t)row * 3072 + e4);
        Qs[(e4 + 0) * 64 + row] = v.x;
        Qs[(e4 + 1) * 64 + row] = v.y;
        Qs[(e4 + 2) * 64 + row] = v.z;
        Qs[(e4 + 3) * 64 + row] = v.w;
    }
    if (tid < 64) {
        sq[tid] = cls_score[q0 + tid];
        mrow[tid] = -1e30f;
        lrow[tid] = 0.0f;
    }
    __syncthreads();

    float sqj[4];
    #pragma unroll
    for (int j = 0; j < 4; ++j) sqj[j] = sq[ty * 4 + j];

    float o[4][4] = {};

    for (int kt = 0; kt < NN / 64; ++kt) {
        int k0g = kt * 64;
        const float* kbase = g_qkv + (size_t)(b * NN + k0g) * 3072 + 1024 + h * 64;
        const float* vbase = kbase + 1024;
        #pragma unroll
        for (int r = 0; r < 4; ++r) {
            int i4 = tid + r * 256;
            int row = i4 >> 4;
            int e4 = (i4 & 15) << 2;
            float4 kv = *reinterpret_cast<const float4*>(kbase + (size_t)row * 3072 + e4);
            Ks[(e4 + 0) * 64 + row] = kv.x;
            Ks[(e4 + 1) * 64 + row] = kv.y;
            Ks[(e4 + 2) * 64 + row] = kv.z;
            Ks[(e4 + 3) * 64 + row] = kv.w;
            float4 vv = *reinterpret_cast<const float4*>(vbase + (size_t)row * 3072 + e4);
            *reinterpret_cast<float4*>(&Vs[row * 64 + e4]) = vv;
        }
        if (tid < 64) sk[tid] = cls_score[k0g + tid];
        __syncthreads();

        float acc[4][4] = {};
        #pragma unroll 16
        for (int e = 0; e < 64; ++e) {
            float4 a  = *reinterpret_cast<const float4*>(&Qs[e * 64 + ty * 4]);
            float4 bk = *reinterpret_cast<const float4*>(&Ks[e * 64 + tx * 4]);
            float av[4] = {a.x, a.y, a.z, a.w};
            float bv[4] = {bk.x, bk.y, bk.z, bk.w};
            #pragma unroll
            for (int j = 0; j < 4; ++j)
                #pragma unroll
                for (int i = 0; i < 4; ++i)
                    acc[j][i] += av[j] * bv[i];
        }
        #pragma unroll
        for (int i = 0; i < 4; ++i) {
            float skv = sk[tx * 4 + i];
            #pragma unroll
            for (int j = 0; j < 4; ++j) {
                float v = acc[j][i] * skv;
                if (um && !(skv > sqj[j] - 0.1f)) v = 0.0f;
                Ssh[(ty * 4 + j) * SS + tx * 4 + i] = v;
            }
        }
        __syncthreads();

        {
            int row = tid >> 2, p = tid & 3;
            float* srow = &Ssh[row * SS + p * 16];
            float mx = -1e30f;
            #pragma unroll
            for (int t = 0; t < 16; ++t) mx = fmaxf(mx, srow[t]);
            mx = fmaxf(mx, __shfl_xor_sync(0xffffffffu, mx, 1));
            mx = fmaxf(mx, __shfl_xor_sync(0xffffffffu, mx, 2));
            float mold = mrow[row];
            float mnew = fmaxf(mold, mx);
            float sum = 0.0f;
            #pragma unroll
            for (int t = 0; t < 16; ++t) {
                float e = __expf(srow[t] - mnew);
                srow[t] = e;
                sum += e;
            }
            sum += __shfl_xor_sync(0xffffffffu, sum, 1);
            sum += __shfl_xor_sync(0xffffffffu, sum, 2);
            if (p == 0) {
                float al = __expf(mold - mnew);
                arow[row] = al;
                lrow[row] = lrow[row] * al + sum;
                mrow[row] = mnew;
            }
        }
        __syncthreads();

        float al[4];
        #pragma unroll
        for (int j = 0; j < 4; ++j) al[j] = arow[ty * 4 + j];
        #pragma unroll
        for (int j = 0; j < 4; ++j)
            #pragma unroll
            for (int i = 0; i < 4; ++i) o[j][i] *= al[j];

        #pragma unroll 16
        for (int k = 0; k < 64; ++k) {
            float4 v = *reinterpret_cast<const float4*>(&Vs[k * 64 + tx * 4]);
            float vv[4] = {v.x, v.y, v.z, v.w};
            #pragma unroll
            for (int j = 0; j < 4; ++j) {
                float pp = Ssh[(ty * 4 + j) * SS + k];
                #pragma unroll
                for (int i = 0; i < 4; ++i) o[j][i] += pp * vv[i];
            }
        }
        __syncthreads();
    }

    #pragma unroll
    for (int j = 0; j < 4; ++j) {
        float linv = 1.0f / lrow[ty * 4 + j];
        float* dst = g_ao + (size_t)(b * NN + q0 + ty * 4 + j) * CC + h * 64 + tx * 4;
        float4 ov = make_float4(o[j][0] * linv, o[j][1] * linv,
                                o[j][2] * linv, o[j][3] * linv);
        *reinterpret_cast<float4*>(dst) = ov;
    }
}

// ---------------------------------------------------------------------------
// Launch
// ---------------------------------------------------------------------------
static const int ATTN_SMEM_BYTES = (3 * 4096 + 64 * SS + 5 * 64) * (int)sizeof(float);
static const int GEMM_SMEM_BYTES = 2 * STAGE_B;   // 81920

extern "C" void kernel_launch(void* const* d_in, const int* in_sizes, int n_in,
                              void* d_out, int out_size)
{
    const float* x     = (const float*)d_in[0];
    const float* cls   = (const float*)d_in[1];
    const float* qkvw  = (const float*)d_in[2];
    const float* projw = (const float*)d_in[3];
    const float* projb = (const float*)d_in[4];
    const int*   um    = (const int*)d_in[5];
    float* out = (float*)d_out;

    float *qkv = nullptr, *ao = nullptr;
    __nv_bfloat16 *xh, *xl, *w1h, *w1l, *w2h, *w2l, *aoh, *aol;
    cudaGetSymbolAddress((void**)&qkv, g_qkv);
    cudaGetSymbolAddress((void**)&ao,  g_ao);
    cudaGetSymbolAddress((void**)&xh,  g_x_hi);
    cudaGetSymbolAddress((void**)&xl,  g_x_lo);
    cudaGetSymbolAddress((void**)&w1h, g_w1_hi);
    cudaGetSymbolAddress((void**)&w1l, g_w1_lo);
    cudaGetSymbolAddress((void**)&w2h, g_w2_hi);
    cudaGetSymbolAddress((void**)&w2l, g_w2_lo);
    cudaGetSymbolAddress((void**)&aoh, g_ao_hi);
    cudaGetSymbolAddress((void**)&aol, g_ao_lo);

    cudaFuncSetAttribute(attn_kernel,
                         cudaFuncAttributeMaxDynamicSharedMemorySize, ATTN_SMEM_BYTES);
    cudaFuncSetAttribute(gemm_bf16x3_kernel,
                         cudaFuncAttributeMaxDynamicSharedMemorySize, GEMM_SMEM_BYTES);

    dim3 blk(256);

    // splits
    split_kernel<<<(M_ROWS * CC + 255) / 256, blk>>>(x, xh, xl, M_ROWS * CC);
    split_kernel<<<(3 * CC * CC + 255) / 256, blk>>>(qkvw, w1h, w1l, 3 * CC * CC);
    split_kernel<<<(CC * CC + 255) / 256, blk>>>(projw, w2h, w2l, CC * CC);

    // QKV projection: [4096,1024] x [3072,1024]^T -> g_qkv
    gemm_bf16x3_kernel<<<dim3(3 * CC / 128, M_ROWS / 128), blk, GEMM_SMEM_BYTES>>>(
        xh, xl, w1h, w1l, nullptr, qkv, 3 * CC);

    // normalize q,k
    norm_qk_kernel<<<(M_ROWS * 32) / 8, blk>>>();

    // attention
    attn_kernel<<<dim3(NN / 64, BB * HH), blk, ATTN_SMEM_BYTES>>>(cls, um);

    // split attention output, then output projection + bias
    split_kernel<<<(M_ROWS * CC + 255) / 256, blk>>>(ao, aoh, aol, M_ROWS * CC);
    gemm_bf16x3_kernel<<<dim3(CC / 128, M_ROWS / 128), blk, GEMM_SMEM_BYTES>>>(
        aoh, aol, w2h, w2l, projb, out, CC);
}

// round 3
// speedup vs baseline: 4.2333x; 2.3755x over previous
#include <cuda_runtime.h>
#include <cuda_bf16.h>
#include <math.h>

#define BB 2
#define NN 2048
#define CC 1024
#define HH 16
#define HD 64
#define M_ROWS (BB*NN)   // 4096

// ---------------- device scratch (allocation-free) ----------------
__device__ float g_qkv[M_ROWS * 3 * CC];              // fp32 qkv [bn][3C]
__device__ __nv_bfloat16 g_x_hi[M_ROWS * CC];
__device__ __nv_bfloat16 g_x_lo[M_ROWS * CC];
__device__ __nv_bfloat16 g_w1_hi[3 * CC * CC];
__device__ __nv_bfloat16 g_w1_lo[3 * CC * CC];
__device__ __nv_bfloat16 g_w2_hi[CC * CC];
__device__ __nv_bfloat16 g_w2_lo[CC * CC];
// head-major [b*H+h][n][64] bf16
__device__ __nv_bfloat16 g_qn[BB * HH * NN * HD];
__device__ __nv_bfloat16 g_kn[BB * HH * NN * HD];
__device__ __nv_bfloat16 g_vh[BB * HH * NN * HD];
__device__ __nv_bfloat16 g_vl[BB * HH * NN * HD];
// attention output split, [B,N,C] layout
__device__ __nv_bfloat16 g_ao_hi[M_ROWS * CC];
__device__ __nv_bfloat16 g_ao_lo[M_ROWS * CC];

// ---------------- helpers ----------------
__global__ __launch_bounds__(256) void split_kernel(
    const float* __restrict__ in, __nv_bfloat16* __restrict__ hi,
    __nv_bfloat16* __restrict__ lo, int n)
{
    int i = blockIdx.x * blockDim.x + threadIdx.x;
    if (i < n) {
        float x = in[i];
        __nv_bfloat16 h = __float2bfloat16(x);
        hi[i] = h;
        lo[i] = __float2bfloat16(x - __bfloat162float(h));
    }
}

__device__ __forceinline__ void ldsm4(unsigned r[4], const void* p) {
    unsigned a = (unsigned)__cvta_generic_to_shared(p);
    asm volatile("ldmatrix.sync.aligned.m8n8.x4.shared.b16 {%0,%1,%2,%3}, [%4];"
                 : "=r"(r[0]), "=r"(r[1]), "=r"(r[2]), "=r"(r[3]) : "r"(a));
}
__device__ __forceinline__ void ldsm4t(unsigned r[4], const void* p) {
    unsigned a = (unsigned)__cvta_generic_to_shared(p);
    asm volatile("ldmatrix.sync.aligned.m8n8.x4.trans.shared.b16 {%0,%1,%2,%3}, [%4];"
                 : "=r"(r[0]), "=r"(r[1]), "=r"(r[2]), "=r"(r[3]) : "r"(a));
}
__device__ __forceinline__ void mma16816(float c[4], const unsigned a[4],
                                         unsigned b0, unsigned b1) {
    asm volatile(
        "mma.sync.aligned.m16n8k16.row.col.f32.bf16.bf16.f32 "
        "{%0,%1,%2,%3}, {%4,%5,%6,%7}, {%8,%9}, {%0,%1,%2,%3};"
        : "+f"(c[0]), "+f"(c[1]), "+f"(c[2]), "+f"(c[3])
        : "r"(a[0]), "r"(a[1]), "r"(a[2]), "r"(a[3]), "r"(b0), "r"(b1));
}
__device__ __forceinline__ void cp16(void* smem, const void* gmem) {
    unsigned sa = (unsigned)__cvta_generic_to_shared(smem);
    asm volatile("cp.async.cg.shared.global [%0], [%1], 16;\n" :: "r"(sa), "l"(gmem));
}

// ---------------------------------------------------------------------------
// bf16x3 GEMM (NT) — unchanged from R2 (verified).
// ---------------------------------------------------------------------------
#define GLDA 40
#define TILE_B (128 * GLDA * 2)
#define STAGE_B (4 * TILE_B)

__global__ __launch_bounds__(256, 1) void gemm_bf16x3_kernel(
    const __nv_bfloat16* __restrict__ a_hi, const __nv_bfloat16* __restrict__ a_lo,
    const __nv_bfloat16* __restrict__ b_hi, const __nv_bfloat16* __restrict__ b_lo,
    const float* __restrict__ bias, float* __restrict__ C, int Nn)
{
    extern __shared__ char sm_raw[];
    const int K = CC;
    int tid = threadIdx.x;
    int lane = tid & 31;
    int wid = tid >> 5;
    int warp_m = wid >> 2;
    int warp_n = wid & 3;
    int m0 = blockIdx.y * 128;
    int n0 = blockIdx.x * 128;

    const __nv_bfloat16* gptr[4] = {a_hi, a_lo, b_hi, b_lo};
    int rowbase[4] = {m0, m0, n0, n0};

    float acc[4][4][4];
    #pragma unroll
    for (int mi = 0; mi < 4; ++mi)
        #pragma unroll
        for (int j = 0; j < 4; ++j)
            #pragma unroll
            for (int e = 0; e < 4; ++e) acc[mi][j][e] = 0.0f;

    auto load_stage = [&](int kt, int stage) {
        char* sbase = sm_raw + stage * STAGE_B;
        int k0 = kt * 32;
        #pragma unroll
        for (int t = 0; t < 8; ++t) {
            int c = tid + t * 256;
            int arr = c >> 9;
            int r = (c >> 2) & 127;
            int c16 = c & 3;
            const __nv_bfloat16* g =
                gptr[arr] + (size_t)(rowbase[arr] + r) * K + k0 + c16 * 8;
            cp16(sbase + arr * TILE_B + r * (GLDA * 2) + c16 * 16, g);
        }
    };

    const int KT = K / 32;
    load_stage(0, 0);
    asm volatile("cp.async.commit_group;");

    for (int kt = 0; kt < KT; ++kt) {
        if (kt + 1 < KT) {
            load_stage(kt + 1, (kt + 1) & 1);
            asm volatile("cp.async.commit_group;");
            asm volatile("cp.async.wait_group 1;");
        } else {
            asm volatile("cp.async.wait_group 0;");
        }
        __syncthreads();

        char* sbase = sm_raw + (kt & 1) * STAGE_B;
        const char* As = sbase;
        const char* Bs = sbase + 2 * TILE_B;

        #pragma unroll
        for (int ks = 0; ks < 32; ks += 16) {
            int coloff = ks + ((lane >> 4) << 3);
            unsigned ah[4][4], al[4][4];
            #pragma unroll
            for (int mi = 0; mi < 4; ++mi) {
                int row = warp_m * 64 + mi * 16 + (lane & 15);
                const char* p = As + row * (GLDA * 2) + coloff * 2;
                ldsm4(ah[mi], p);
                ldsm4(al[mi], p + TILE_B);
            }
            unsigned bh[2][4], bl[2][4];
            #pragma unroll
            for (int ni = 0; ni < 2; ++ni) {
                int row = warp_n * 32 + ni * 16 + (lane & 15);
                const char* p = Bs + row * (GLDA * 2) + coloff * 2;
                ldsm4(bh[ni], p);
                ldsm4(bl[ni], p + TILE_B);
            }
            #pragma unroll
            for (int mi = 0; mi < 4; ++mi) {
                #pragma unroll
                for (int j = 0; j < 4; ++j) {
                    int ni = j >> 1, od = j & 1;
                    unsigned bh0 = bh[ni][od ? 1 : 0], bh1 = bh[ni][od ? 3 : 2];
                    unsigned bl0 = bl[ni][od ? 1 : 0], bl1 = bl[ni][od ? 3 : 2];
                    mma16816(acc[mi][j], ah[mi], bh0, bh1);
                    mma16816(acc[mi][j], ah[mi], bl0, bl1);
                    mma16816(acc[mi][j], al[mi], bh0, bh1);
                }
            }
        }
        __syncthreads();
    }

    int mb = m0 + warp_m * 64 + (lane >> 2);
    int nb = n0 + warp_n * 32 + 2 * (lane & 3);
    #pragma unroll
    for (int mi = 0; mi < 4; ++mi) {
        #pragma unroll
        for (int j = 0; j < 4; ++j) {
            int col = nb + j * 8;
            float b0 = 0.f, b1 = 0.f;
            if (bias) { b0 = bias[col]; b1 = bias[col + 1]; }
            int r0 = mb + mi * 16;
            float2 v0 = make_float2(acc[mi][j][0] + b0, acc[mi][j][1] + b1);
            float2 v1 = make_float2(acc[mi][j][2] + b0, acc[mi][j][3] + b1);
            *reinterpret_cast<float2*>(&C[(size_t)r0 * Nn + col]) = v0;
            *reinterpret_cast<float2*>(&C[(size_t)(r0 + 8) * Nn + col]) = v1;
        }
    }
}

// ---------------------------------------------------------------------------
// Fused normalize + split: q,k -> unit bf16 (0.125 folded into q),
// v -> bf16 hi/lo. Head-major output [bh][n][64]. One warp per (bn,h).
// ---------------------------------------------------------------------------
__global__ __launch_bounds__(256) void norm_split_kernel()
{
    int gw   = (blockIdx.x * 256 + threadIdx.x) >> 5;   // 0..65535
    int lane = threadIdx.x & 31;
    int bn = gw >> 4;
    int h  = gw & 15;
    int b = bn >> 11, n = bn & 2047;
    size_t src  = (size_t)bn * 3072 + h * 64;
    size_t dst  = ((size_t)(b * HH + h) * NN + n) * 64 + 2 * lane;

    // q
    float2 q = *reinterpret_cast<const float2*>(&g_qkv[src + 2 * lane]);
    float s = q.x * q.x + q.y * q.y;
    #pragma unroll
    for (int o = 16; o; o >>= 1) s += __shfl_xor_sync(0xffffffffu, s, o);
    float inv = 0.125f / (sqrtf(s) + 1e-8f);
    *reinterpret_cast<__nv_bfloat162*>(&g_qn[dst]) =
        __floats2bfloat162_rn(q.x * inv, q.y * inv);
    // k
    float2 k = *reinterpret_cast<const float2*>(&g_qkv[src + 1024 + 2 * lane]);
    s = k.x * k.x + k.y * k.y;
    #pragma unroll
    for (int o = 16; o; o >>= 1) s += __shfl_xor_sync(0xffffffffu, s, o);
    inv = 1.0f / (sqrtf(s) + 1e-8f);
    *reinterpret_cast<__nv_bfloat162*>(&g_kn[dst]) =
        __floats2bfloat162_rn(k.x * inv, k.y * inv);
    // v split
    float2 v = *reinterpret_cast<const float2*>(&g_qkv[src + 2048 + 2 * lane]);
    __nv_bfloat162 H = __floats2bfloat162_rn(v.x, v.y);
    float2 Hf = __bfloat1622float2(H);
    __nv_bfloat162 L = __floats2bfloat162_rn(v.x - Hf.x, v.y - Hf.y);
    *reinterpret_cast<__nv_bfloat162*>(&g_vh[dst]) = H;
    *reinterpret_cast<__nv_bfloat162*>(&g_vl[dst]) = L;
}

// ---------------------------------------------------------------------------
// Tensor-core attention. Block = 128 queries of one (b,h), 256 threads.
// No max-tracking needed: logits in [-0.125,0.125]. P,V split bf16 for PV.
// ---------------------------------------------------------------------------
#define ATS 72                          // smem row stride (bf16)
#define KTB (128 * ATS * 2)             // 18432 B per 128x64 tile

__global__ __launch_bounds__(256) void attn_mma_kernel(
    const float* __restrict__ cls, const int* __restrict__ um_p)
{
    extern __shared__ char smem[];
    // [K s0|s1][Vh s0|s1][Vl s0|s1][sk s0|s1]
    float* sks = (float*)(smem + 6 * KTB);

    int tid = threadIdx.x;
    int lane = tid & 31;
    int warp = tid >> 5;
    int q0 = blockIdx.x * 128;
    int bh = blockIdx.y;
    int b = bh >> 4, h = bh & 15;
    int um = um_p[0];
    int r = lane >> 2;
    int c2 = 2 * (lane & 3);

    // Q fragments: direct LDG of bf16x2 in mma A-fragment layout
    const __nv_bfloat16* qg = g_qn + ((size_t)bh * NN + q0 + warp * 16) * 64;
    unsigned qa[4][4];
    #pragma unroll
    for (int dc = 0; dc < 4; ++dc) {
        qa[dc][0] = *(const unsigned*)(qg + (size_t)r * 64 + 16 * dc + c2);
        qa[dc][1] = *(const unsigned*)(qg + (size_t)(r + 8) * 64 + 16 * dc + c2);
        qa[dc][2] = *(const unsigned*)(qg + (size_t)r * 64 + 16 * dc + 8 + c2);
        qa[dc][3] = *(const unsigned*)(qg + (size_t)(r + 8) * 64 + 16 * dc + 8 + c2);
    }
    float sq0 = cls[q0 + warp * 16 + r] - 0.1f;
    float sq8 = cls[q0 + warp * 16 + r + 8] - 0.1f;

    const __nv_bfloat16* kg  = g_kn + (size_t)bh * NN * 64;
    const __nv_bfloat16* vhg = g_vh + (size_t)bh * NN * 64;
    const __nv_bfloat16* vlg = g_vl + (size_t)bh * NN * 64;

    float o[8][4];
    #pragma unroll
    for (int i = 0; i < 8; ++i)
        #pragma unroll
        for (int e = 0; e < 4; ++e) o[i][e] = 0.0f;
    float l0 = 0.0f, l8 = 0.0f;

    auto stage_load = [&](int kt, int s) {
        #pragma unroll
        for (int t = 0; t < 12; ++t) {
            int cix = tid + t * 256;               // 0..3071
            int arr = cix >> 10;                   // 0:K 1:Vh 2:Vl
            int rr  = (cix >> 3) & 127;
            int seg = cix & 7;
            const __nv_bfloat16* gb = (arr == 0) ? kg : (arr == 1) ? vhg : vlg;
            const __nv_bfloat16* g = gb + ((size_t)(kt * 128 + rr)) * 64 + seg * 8;
            cp16(smem + arr * 2 * KTB + s * KTB + rr * (ATS * 2) + seg * 16, g);
        }
        if (tid < 128) sks[s * 128 + tid] = cls[kt * 128 + tid];
    };

    stage_load(0, 0);
    asm volatile("cp.async.commit_group;");

    for (int kt = 0; kt < NN / 128; ++kt) {
        asm volatile("cp.async.wait_group 0;");
        __syncthreads();
        if (kt + 1 < NN / 128) {
            stage_load(kt + 1, (kt + 1) & 1);
            asm volatile("cp.async.commit_group;");
        }
        int s = kt & 1;
        const char* Kb  = smem + s * KTB;
        const char* Vhb = smem + 2 * KTB + s * KTB;
        const char* Vlb = smem + 4 * KTB + s * KTB;
        const float* sk = sks + s * 128;

        #pragma unroll
        for (int j = 0; j < 8; ++j) {
            // ---- S = Q K^T for keys [16j, 16j+16) ----
            float cc[2][4] = {{0, 0, 0, 0}, {0, 0, 0, 0}};
            int krow = 16 * j + (lane & 15);
            #pragma unroll
            for (int dc = 0; dc < 4; ++dc) {
                unsigned kb[4];
                ldsm4(kb, Kb + krow * (ATS * 2) + (16 * dc + ((lane >> 4) << 3)) * 2);
                mma16816(cc[0], qa[dc], kb[0], kb[2]);
                mma16816(cc[1], qa[dc], kb[1], kb[3]);
            }
            // ---- scale, mask, exp, sum, split-pack P ----
            unsigned ah[4], al[4];
            #pragma unroll
            for (int t = 0; t < 2; ++t) {
                float2 skv = *reinterpret_cast<const float2*>(&sk[16 * j + 8 * t + c2]);
                float fx0 = (um && !(skv.x > sq0)) ? 0.f : skv.x;
                float fy0 = (um && !(skv.y > sq0)) ? 0.f : skv.y;
                float fx8 = (um && !(skv.x > sq8)) ? 0.f : skv.x;
                float fy8 = (um && !(skv.y > sq8)) ? 0.f : skv.y;
                float p00 = __expf(cc[t][0] * fx0);
                float p01 = __expf(cc[t][1] * fy0);
                float p80 = __expf(cc[t][2] * fx8);
                float p81 = __expf(cc[t][3] * fy8);
                l0 += p00 + p01;
                l8 += p80 + p81;
                __nv_bfloat162 H0 = __floats2bfloat162_rn(p00, p01);
                float2 H0f = __bfloat1622float2(H0);
                __nv_bfloat162 L0 = __floats2bfloat162_rn(p00 - H0f.x, p01 - H0f.y);
                __nv_bfloat162 H8 = __floats2bfloat162_rn(p80, p81);
                float2 H8f = __bfloat1622float2(H8);
                __nv_bfloat162 L8 = __floats2bfloat162_rn(p80 - H8f.x, p81 - H8f.y);
                ah[2 * t]     = *reinterpret_cast<unsigned*>(&H0);
                ah[2 * t + 1] = *reinterpret_cast<unsigned*>(&H8);
                al[2 * t]     = *reinterpret_cast<unsigned*>(&L0);
                al[2 * t + 1] = *reinterpret_cast<unsigned*>(&L8);
            }
            // ---- O += P V (hi*hi + hi*lo + lo*hi) ----
            #pragma unroll
            for (int n2 = 0; n2 < 4; ++n2) {
                unsigned vb[4], vl[4];
                int voff = krow * (ATS * 2) + (16 * n2 + ((lane >> 4) << 3)) * 2;
                ldsm4t(vb, Vhb + voff);
                ldsm4t(vl, Vlb + voff);
                mma16816(o[2 * n2],     ah, vb[0], vb[1]);
                mma16816(o[2 * n2 + 1], ah, vb[2], vb[3]);
                mma16816(o[2 * n2],     ah, vl[0], vl[1]);
                mma16816(o[2 * n2 + 1], ah, vl[2], vl[3]);
                mma16816(o[2 * n2],     al, vb[0], vb[1]);
                mma16816(o[2 * n2 + 1], al, vb[2], vb[3]);
            }
        }
    }

    // normalize rows, split to bf16 hi/lo, write [B,N,C]
    l0 += __shfl_xor_sync(0xffffffffu, l0, 1);
    l0 += __shfl_xor_sync(0xffffffffu, l0, 2);
    l8 += __shfl_xor_sync(0xffffffffu, l8, 1);
    l8 += __shfl_xor_sync(0xffffffffu, l8, 2);
    float inv0 = 1.0f / l0, inv8 = 1.0f / l8;

    size_t row0 = ((size_t)(b * NN + q0 + warp * 16 + r)) * CC + h * 64;
    size_t row8 = ((size_t)(b * NN + q0 + warp * 16 + r + 8)) * CC + h * 64;
    #pragma unroll
    for (int nt = 0; nt < 8; ++nt) {
        int d = 8 * nt + c2;
        float v0 = o[nt][0] * inv0, v1 = o[nt][1] * inv0;
        __nv_bfloat162 H = __floats2bfloat162_rn(v0, v1);
        float2 Hf = __bfloat1622float2(H);
        __nv_bfloat162 L = __floats2bfloat162_rn(v0 - Hf.x, v1 - Hf.y);
        *reinterpret_cast<__nv_bfloat162*>(&g_ao_hi[row0 + d]) = H;
        *reinterpret_cast<__nv_bfloat162*>(&g_ao_lo[row0 + d]) = L;
        float w0 = o[nt][2] * inv8, w1 = o[nt][3] * inv8;
        __nv_bfloat162 H2 = __floats2bfloat162_rn(w0, w1);
        float2 H2f = __bfloat1622float2(H2);
        __nv_bfloat162 L2 = __floats2bfloat162_rn(w0 - H2f.x, w1 - H2f.y);
        *reinterpret_cast<__nv_bfloat162*>(&g_ao_hi[row8 + d]) = H2;
        *reinterpret_cast<__nv_bfloat162*>(&g_ao_lo[row8 + d]) = L2;
    }
}

// ---------------------------------------------------------------------------
// Launch
// ---------------------------------------------------------------------------
static const int GEMM_SMEM_BYTES = 2 * STAGE_B;
static const int ATTN_SMEM_BYTES = 6 * KTB + 2 * 128 * (int)sizeof(float); // 111616

extern "C" void kernel_launch(void* const* d_in, const int* in_sizes, int n_in,
                              void* d_out, int out_size)
{
    const float* x     = (const float*)d_in[0];
    const float* cls   = (const float*)d_in[1];
    const float* qkvw  = (const float*)d_in[2];
    const float* projw = (const float*)d_in[3];
    const float* projb = (const float*)d_in[4];
    const int*   um    = (const int*)d_in[5];
    float* out = (float*)d_out;

    float* qkv = nullptr;
    __nv_bfloat16 *xh, *xl, *w1h, *w1l, *w2h, *w2l, *aoh, *aol;
    cudaGetSymbolAddress((void**)&qkv, g_qkv);
    cudaGetSymbolAddress((void**)&xh,  g_x_hi);
    cudaGetSymbolAddress((void**)&xl,  g_x_lo);
    cudaGetSymbolAddress((void**)&w1h, g_w1_hi);
    cudaGetSymbolAddress((void**)&w1l, g_w1_lo);
    cudaGetSymbolAddress((void**)&w2h, g_w2_hi);
    cudaGetSymbolAddress((void**)&w2l, g_w2_lo);
    cudaGetSymbolAddress((void**)&aoh, g_ao_hi);
    cudaGetSymbolAddress((void**)&aol, g_ao_lo);

    cudaFuncSetAttribute(gemm_bf16x3_kernel,
                         cudaFuncAttributeMaxDynamicSharedMemorySize, GEMM_SMEM_BYTES);
    cudaFuncSetAttribute(attn_mma_kernel,
                         cudaFuncAttributeMaxDynamicSharedMemorySize, ATTN_SMEM_BYTES);

    dim3 blk(256);

    split_kernel<<<(M_ROWS * CC + 255) / 256, blk>>>(x, xh, xl, M_ROWS * CC);
    split_kernel<<<(3 * CC * CC + 255) / 256, blk>>>(qkvw, w1h, w1l, 3 * CC * CC);
    split_kernel<<<(CC * CC + 255) / 256, blk>>>(projw, w2h, w2l, CC * CC);

    // QKV projection
    gemm_bf16x3_kernel<<<dim3(3 * CC / 128, M_ROWS / 128), blk, GEMM_SMEM_BYTES>>>(
        xh, xl, w1h, w1l, nullptr, qkv, 3 * CC);

    // normalize + split to head-major bf16
    norm_split_kernel<<<(M_ROWS * HH) / 8, blk>>>();

    // tensor-core attention
    attn_mma_kernel<<<dim3(NN / 128, BB * HH), blk, ATTN_SMEM_BYTES>>>(cls, um);

    // output projection + bias
    gemm_bf16x3_kernel<<<dim3(CC / 128, M_ROWS / 128), blk, GEMM_SMEM_BYTES>>>(
        aoh, aol, w2h, w2l, projb, out, CC);
}

// round 4
// speedup vs baseline: 5.3118x; 1.2548x over previous
#include <cuda_runtime.h>
#include <cuda_bf16.h>
#include <math.h>

#define BB 2
#define NN 2048
#define CC 1024
#define HH 16
#define HD 64
#define M_ROWS (BB*NN)   // 4096

// ---------------- device scratch (allocation-free) ----------------
__device__ float g_qkv[M_ROWS * 3 * CC];              // fp32 qkv [bn][3C]
__device__ __nv_bfloat16 g_x_hi[M_ROWS * CC];
__device__ __nv_bfloat16 g_x_lo[M_ROWS * CC];
__device__ __nv_bfloat16 g_w1_hi[3 * CC * CC];
__device__ __nv_bfloat16 g_w1_lo[3 * CC * CC];
__device__ __nv_bfloat16 g_w2_hi[CC * CC];
__device__ __nv_bfloat16 g_w2_lo[CC * CC];
// head-major [b*H+h][n][64] bf16
__device__ __nv_bfloat16 g_qn[BB * HH * NN * HD];
__device__ __nv_bfloat16 g_kn[BB * HH * NN * HD];
__device__ __nv_bfloat16 g_vh[BB * HH * NN * HD];
__device__ __nv_bfloat16 g_vl[BB * HH * NN * HD];
// attention output split, [B,N,C] layout
__device__ __nv_bfloat16 g_ao_hi[M_ROWS * CC];
__device__ __nv_bfloat16 g_ao_lo[M_ROWS * CC];

// ---------------- helpers ----------------
__global__ __launch_bounds__(256) void split_kernel(
    const float* __restrict__ in, __nv_bfloat16* __restrict__ hi,
    __nv_bfloat16* __restrict__ lo, int n)
{
    int i = blockIdx.x * blockDim.x + threadIdx.x;
    if (i < n) {
        float x = in[i];
        __nv_bfloat16 h = __float2bfloat16(x);
        hi[i] = h;
        lo[i] = __float2bfloat16(x - __bfloat162float(h));
    }
}

__device__ __forceinline__ void ldsm4(unsigned r[4], const void* p) {
    unsigned a = (unsigned)__cvta_generic_to_shared(p);
    asm volatile("ldmatrix.sync.aligned.m8n8.x4.shared.b16 {%0,%1,%2,%3}, [%4];"
                 : "=r"(r[0]), "=r"(r[1]), "=r"(r[2]), "=r"(r[3]) : "r"(a));
}
__device__ __forceinline__ void ldsm4t(unsigned r[4], const void* p) {
    unsigned a = (unsigned)__cvta_generic_to_shared(p);
    asm volatile("ldmatrix.sync.aligned.m8n8.x4.trans.shared.b16 {%0,%1,%2,%3}, [%4];"
                 : "=r"(r[0]), "=r"(r[1]), "=r"(r[2]), "=r"(r[3]) : "r"(a));
}
__device__ __forceinline__ void mma16816(float c[4], const unsigned a[4],
                                         unsigned b0, unsigned b1) {
    asm volatile(
        "mma.sync.aligned.m16n8k16.row.col.f32.bf16.bf16.f32 "
        "{%0,%1,%2,%3}, {%4,%5,%6,%7}, {%8,%9}, {%0,%1,%2,%3};"
        : "+f"(c[0]), "+f"(c[1]), "+f"(c[2]), "+f"(c[3])
        : "r"(a[0]), "r"(a[1]), "r"(a[2]), "r"(a[3]), "r"(b0), "r"(b1));
}
__device__ __forceinline__ void cp16(void* smem, const void* gmem) {
    unsigned sa = (unsigned)__cvta_generic_to_shared(smem);
    asm volatile("cp.async.cg.shared.global [%0], [%1], 16;\n" :: "r"(sa), "l"(gmem));
}

// ---------------------------------------------------------------------------
// Templated tensor-core GEMM (NT): C[m][n] = sum_k A[m][k]*B[n][k] (+bias).
// NARR==4: bf16x3 (hi*hi + hi*lo + lo*hi).  NARR==2: single-pass hi*hi.
// 128x128x32 tiles, cp.async double buffer, 8 warps, m16n8k16, 2 CTAs/SM.
// ---------------------------------------------------------------------------
#define GLDA 40
#define TILE_B (128 * GLDA * 2)   // 10240 B per 128x32 bf16 tile

template<int NARR>
__global__ __launch_bounds__(256, 2) void gemm_tc_kernel(
    const __nv_bfloat16* __restrict__ a_hi, const __nv_bfloat16* __restrict__ a_lo,
    const __nv_bfloat16* __restrict__ b_hi, const __nv_bfloat16* __restrict__ b_lo,
    const float* __restrict__ bias, float* __restrict__ C, int Nn)
{
    extern __shared__ char sm_raw[];
    const int K = CC;
    const int STAGE = NARR * TILE_B;
    int tid = threadIdx.x;
    int lane = tid & 31;
    int wid = tid >> 5;
    int warp_m = wid >> 2;
    int warp_n = wid & 3;
    int m0 = blockIdx.y * 128;
    int n0 = blockIdx.x * 128;

    const __nv_bfloat16* gptr[NARR];
    int rowbase[NARR];
    gptr[0] = a_hi; rowbase[0] = m0;
    if (NARR == 4) {
        gptr[1] = a_lo; rowbase[1] = m0;
        gptr[2] = b_hi; rowbase[2] = n0;
        gptr[3] = b_lo; rowbase[3] = n0;
    } else {
        gptr[1] = b_hi; rowbase[1] = n0;
    }

    float acc[4][4][4];
    #pragma unroll
    for (int mi = 0; mi < 4; ++mi)
        #pragma unroll
        for (int j = 0; j < 4; ++j)
            #pragma unroll
            for (int e = 0; e < 4; ++e) acc[mi][j][e] = 0.0f;

    auto load_stage = [&](int kt, int stage) {
        char* sbase = sm_raw + stage * STAGE;
        int k0 = kt * 32;
        #pragma unroll
        for (int t = 0; t < 2 * NARR; ++t) {
            int c = tid + t * 256;
            int arr = c >> 9;
            int r = (c >> 2) & 127;
            int c16 = c & 3;
            const __nv_bfloat16* g =
                gptr[arr] + (size_t)(rowbase[arr] + r) * K + k0 + c16 * 8;
            cp16(sbase + arr * TILE_B + r * (GLDA * 2) + c16 * 16, g);
        }
    };

    const int KT = K / 32;
    load_stage(0, 0);
    asm volatile("cp.async.commit_group;");

    for (int kt = 0; kt < KT; ++kt) {
        if (kt + 1 < KT) {
            load_stage(kt + 1, (kt + 1) & 1);
            asm volatile("cp.async.commit_group;");
            asm volatile("cp.async.wait_group 1;");
        } else {
            asm volatile("cp.async.wait_group 0;");
        }
        __syncthreads();

        char* sbase = sm_raw + (kt & 1) * STAGE;
        const char* As = sbase;
        const char* Bs = sbase + (NARR == 4 ? 2 : 1) * TILE_B;

        #pragma unroll
        for (int ks = 0; ks < 32; ks += 16) {
            int coloff = ks + ((lane >> 4) << 3);
            unsigned ah[4][4], al[4][4];
            #pragma unroll
            for (int mi = 0; mi < 4; ++mi) {
                int row = warp_m * 64 + mi * 16 + (lane & 15);
                const char* p = As + row * (GLDA * 2) + coloff * 2;
                ldsm4(ah[mi], p);
                if (NARR == 4) ldsm4(al[mi], p + TILE_B);
            }
            unsigned bh[2][4], bl[2][4];
            #pragma unroll
            for (int ni = 0; ni < 2; ++ni) {
                int row = warp_n * 32 + ni * 16 + (lane & 15);
                const char* p = Bs + row * (GLDA * 2) + coloff * 2;
                ldsm4(bh[ni], p);
                if (NARR == 4) ldsm4(bl[ni], p + TILE_B);
            }
            #pragma unroll
            for (int mi = 0; mi < 4; ++mi) {
                #pragma unroll
                for (int j = 0; j < 4; ++j) {
                    int ni = j >> 1, od = j & 1;
                    unsigned bh0 = bh[ni][od ? 1 : 0], bh1 = bh[ni][od ? 3 : 2];
                    mma16816(acc[mi][j], ah[mi], bh0, bh1);
                    if (NARR == 4) {
                        unsigned bl0 = bl[ni][od ? 1 : 0], bl1 = bl[ni][od ? 3 : 2];
                        mma16816(acc[mi][j], ah[mi], bl0, bl1);
                        mma16816(acc[mi][j], al[mi], bh0, bh1);
                    }
                }
            }
        }
        __syncthreads();
    }

    int mb = m0 + warp_m * 64 + (lane >> 2);
    int nb = n0 + warp_n * 32 + 2 * (lane & 3);
    #pragma unroll
    for (int mi = 0; mi < 4; ++mi) {
        #pragma unroll
        for (int j = 0; j < 4; ++j) {
            int col = nb + j * 8;
            float b0 = 0.f, b1 = 0.f;
            if (bias) { b0 = bias[col]; b1 = bias[col + 1]; }
            int r0 = mb + mi * 16;
            float2 v0 = make_float2(acc[mi][j][0] + b0, acc[mi][j][1] + b1);
            float2 v1 = make_float2(acc[mi][j][2] + b0, acc[mi][j][3] + b1);
            *reinterpret_cast<float2*>(&C[(size_t)r0 * Nn + col]) = v0;
            *reinterpret_cast<float2*>(&C[(size_t)(r0 + 8) * Nn + col]) = v1;
        }
    }
}

// ---------------------------------------------------------------------------
// Fused normalize + split (head-major outputs).
// ---------------------------------------------------------------------------
__global__ __launch_bounds__(256) void norm_split_kernel()
{
    int gw   = (blockIdx.x * 256 + threadIdx.x) >> 5;
    int lane = threadIdx.x & 31;
    int bn = gw >> 4;
    int h  = gw & 15;
    int b = bn >> 11, n = bn & 2047;
    size_t src  = (size_t)bn * 3072 + h * 64;
    size_t dst  = ((size_t)(b * HH + h) * NN + n) * 64 + 2 * lane;

    float2 q = *reinterpret_cast<const float2*>(&g_qkv[src + 2 * lane]);
    float s = q.x * q.x + q.y * q.y;
    #pragma unroll
    for (int o = 16; o; o >>= 1) s += __shfl_xor_sync(0xffffffffu, s, o);
    float inv = 0.125f / (sqrtf(s) + 1e-8f);
    *reinterpret_cast<__nv_bfloat162*>(&g_qn[dst]) =
        __floats2bfloat162_rn(q.x * inv, q.y * inv);

    float2 k = *reinterpret_cast<const float2*>(&g_qkv[src + 1024 + 2 * lane]);
    s = k.x * k.x + k.y * k.y;
    #pragma unroll
    for (int o = 16; o; o >>= 1) s += __shfl_xor_sync(0xffffffffu, s, o);
    inv = 1.0f / (sqrtf(s) + 1e-8f);
    *reinterpret_cast<__nv_bfloat162*>(&g_kn[dst]) =
        __floats2bfloat162_rn(k.x * inv, k.y * inv);

    float2 v = *reinterpret_cast<const float2*>(&g_qkv[src + 2048 + 2 * lane]);
    __nv_bfloat162 H = __floats2bfloat162_rn(v.x, v.y);
    float2 Hf = __bfloat1622float2(H);
    __nv_bfloat162 L = __floats2bfloat162_rn(v.x - Hf.x, v.y - Hf.y);
    *reinterpret_cast<__nv_bfloat162*>(&g_vh[dst]) = H;
    *reinterpret_cast<__nv_bfloat162*>(&g_vl[dst]) = L;
}

// ---------------------------------------------------------------------------
// Tensor-core attention (as R3) + 2 CTAs/SM.
// ---------------------------------------------------------------------------
#define ATS 72
#define KTB (128 * ATS * 2)

__global__ __launch_bounds__(256, 2) void attn_mma_kernel(
    const float* __restrict__ cls, const int* __restrict__ um_p)
{
    extern __shared__ char smem[];
    float* sks = (float*)(smem + 6 * KTB);

    int tid = threadIdx.x;
    int lane = tid & 31;
    int warp = tid >> 5;
    int q0 = blockIdx.x * 128;
    int bh = blockIdx.y;
    int b = bh >> 4, h = bh & 15;
    int um = um_p[0];
    int r = lane >> 2;
    int c2 = 2 * (lane & 3);

    const __nv_bfloat16* qg = g_qn + ((size_t)bh * NN + q0 + warp * 16) * 64;
    unsigned qa[4][4];
    #pragma unroll
    for (int dc = 0; dc < 4; ++dc) {
        qa[dc][0] = *(const unsigned*)(qg + (size_t)r * 64 + 16 * dc + c2);
        qa[dc][1] = *(const unsigned*)(qg + (size_t)(r + 8) * 64 + 16 * dc + c2);
        qa[dc][2] = *(const unsigned*)(qg + (size_t)r * 64 + 16 * dc + 8 + c2);
        qa[dc][3] = *(const unsigned*)(qg + (size_t)(r + 8) * 64 + 16 * dc + 8 + c2);
    }
    float sq0 = cls[q0 + warp * 16 + r] - 0.1f;
    float sq8 = cls[q0 + warp * 16 + r + 8] - 0.1f;

    const __nv_bfloat16* kg  = g_kn + (size_t)bh * NN * 64;
    const __nv_bfloat16* vhg = g_vh + (size_t)bh * NN * 64;
    const __nv_bfloat16* vlg = g_vl + (size_t)bh * NN * 64;

    float o[8][4];
    #pragma unroll
    for (int i = 0; i < 8; ++i)
        #pragma unroll
        for (int e = 0; e < 4; ++e) o[i][e] = 0.0f;
    float l0 = 0.0f, l8 = 0.0f;

    auto stage_load = [&](int kt, int s) {
        #pragma unroll
        for (int t = 0; t < 12; ++t) {
            int cix = tid + t * 256;
            int arr = cix >> 10;
            int rr  = (cix >> 3) & 127;
            int seg = cix & 7;
            const __nv_bfloat16* gb = (arr == 0) ? kg : (arr == 1) ? vhg : vlg;
            const __nv_bfloat16* g = gb + ((size_t)(kt * 128 + rr)) * 64 + seg * 8;
            cp16(smem + arr * 2 * KTB + s * KTB + rr * (ATS * 2) + seg * 16, g);
        }
        if (tid < 128) sks[s * 128 + tid] = cls[kt * 128 + tid];
    };

    stage_load(0, 0);
    asm volatile("cp.async.commit_group;");

    for (int kt = 0; kt < NN / 128; ++kt) {
        asm volatile("cp.async.wait_group 0;");
        __syncthreads();
        if (kt + 1 < NN / 128) {
            stage_load(kt + 1, (kt + 1) & 1);
            asm volatile("cp.async.commit_group;");
        }
        int s = kt & 1;
        const char* Kb  = smem + s * KTB;
        const char* Vhb = smem + 2 * KTB + s * KTB;
        const char* Vlb = smem + 4 * KTB + s * KTB;
        const float* sk = sks + s * 128;

        #pragma unroll
        for (int j = 0; j < 8; ++j) {
            float cc[2][4] = {{0, 0, 0, 0}, {0, 0, 0, 0}};
            int krow = 16 * j + (lane & 15);
            #pragma unroll
            for (int dc = 0; dc < 4; ++dc) {
                unsigned kb[4];
                ldsm4(kb, Kb + krow * (ATS * 2) + (16 * dc + ((lane >> 4) << 3)) * 2);
                mma16816(cc[0], qa[dc], kb[0], kb[2]);
                mma16816(cc[1], qa[dc], kb[1], kb[3]);
            }
            unsigned ah[4], al[4];
            #pragma unroll
            for (int t = 0; t < 2; ++t) {
                float2 skv = *reinterpret_cast<const float2*>(&sk[16 * j + 8 * t + c2]);
                float fx0 = (um && !(skv.x > sq0)) ? 0.f : skv.x;
                float fy0 = (um && !(skv.y > sq0)) ? 0.f : skv.y;
                float fx8 = (um && !(skv.x > sq8)) ? 0.f : skv.x;
                float fy8 = (um && !(skv.y > sq8)) ? 0.f : skv.y;
                float p00 = __expf(cc[t][0] * fx0);
                float p01 = __expf(cc[t][1] * fy0);
                float p80 = __expf(cc[t][2] * fx8);
                float p81 = __expf(cc[t][3] * fy8);
                l0 += p00 + p01;
                l8 += p80 + p81;
                __nv_bfloat162 H0 = __floats2bfloat162_rn(p00, p01);
                float2 H0f = __bfloat1622float2(H0);
                __nv_bfloat162 L0 = __floats2bfloat162_rn(p00 - H0f.x, p01 - H0f.y);
                __nv_bfloat162 H8 = __floats2bfloat162_rn(p80, p81);
                float2 H8f = __bfloat1622float2(H8);
                __nv_bfloat162 L8 = __floats2bfloat162_rn(p80 - H8f.x, p81 - H8f.y);
                ah[2 * t]     = *reinterpret_cast<unsigned*>(&H0);
                ah[2 * t + 1] = *reinterpret_cast<unsigned*>(&H8);
                al[2 * t]     = *reinterpret_cast<unsigned*>(&L0);
                al[2 * t + 1] = *reinterpret_cast<unsigned*>(&L8);
            }
            #pragma unroll
            for (int n2 = 0; n2 < 4; ++n2) {
                unsigned vb[4], vl[4];
                int voff = krow * (ATS * 2) + (16 * n2 + ((lane >> 4) << 3)) * 2;
                ldsm4t(vb, Vhb + voff);
                ldsm4t(vl, Vlb + voff);
                mma16816(o[2 * n2],     ah, vb[0], vb[1]);
                mma16816(o[2 * n2 + 1], ah, vb[2], vb[3]);
                mma16816(o[2 * n2],     ah, vl[0], vl[1]);
                mma16816(o[2 * n2 + 1], ah, vl[2], vl[3]);
                mma16816(o[2 * n2],     al, vb[0], vb[1]);
                mma16816(o[2 * n2 + 1], al, vb[2], vb[3]);
            }
        }
    }

    l0 += __shfl_xor_sync(0xffffffffu, l0, 1);
    l0 += __shfl_xor_sync(0xffffffffu, l0, 2);
    l8 += __shfl_xor_sync(0xffffffffu, l8, 1);
    l8 += __shfl_xor_sync(0xffffffffu, l8, 2);
    float inv0 = 1.0f / l0, inv8 = 1.0f / l8;

    size_t row0 = ((size_t)(b * NN + q0 + warp * 16 + r)) * CC + h * 64;
    size_t row8 = ((size_t)(b * NN + q0 + warp * 16 + r + 8)) * CC + h * 64;
    #pragma unroll
    for (int nt = 0; nt < 8; ++nt) {
        int d = 8 * nt + c2;
        float v0 = o[nt][0] * inv0, v1 = o[nt][1] * inv0;
        __nv_bfloat162 H = __floats2bfloat162_rn(v0, v1);
        float2 Hf = __bfloat1622float2(H);
        __nv_bfloat162 L = __floats2bfloat162_rn(v0 - Hf.x, v1 - Hf.y);
        *reinterpret_cast<__nv_bfloat162*>(&g_ao_hi[row0 + d]) = H;
        *reinterpret_cast<__nv_bfloat162*>(&g_ao_lo[row0 + d]) = L;
        float w0 = o[nt][2] * inv8, w1 = o[nt][3] * inv8;
        __nv_bfloat162 H2 = __floats2bfloat162_rn(w0, w1);
        float2 H2f = __bfloat1622float2(H2);
        __nv_bfloat162 L2 = __floats2bfloat162_rn(w0 - H2f.x, w1 - H2f.y);
        *reinterpret_cast<__nv_bfloat162*>(&g_ao_hi[row8 + d]) = H2;
        *reinterpret_cast<__nv_bfloat162*>(&g_ao_lo[row8 + d]) = L2;
    }
}

// ---------------------------------------------------------------------------
// Launch
// ---------------------------------------------------------------------------
static const int GEMM3_SMEM = 2 * 4 * TILE_B;   // 81920
static const int GEMM1_SMEM = 2 * 2 * TILE_B;   // 40960
static const int ATTN_SMEM_BYTES = 6 * KTB + 2 * 128 * (int)sizeof(float);

extern "C" void kernel_launch(void* const* d_in, const int* in_sizes, int n_in,
                              void* d_out, int out_size)
{
    const float* x     = (const float*)d_in[0];
    const float* cls   = (const float*)d_in[1];
    const float* qkvw  = (const float*)d_in[2];
    const float* projw = (const float*)d_in[3];
    const float* projb = (const float*)d_in[4];
    const int*   um    = (const int*)d_in[5];
    float* out = (float*)d_out;

    float* qkv = nullptr;
    __nv_bfloat16 *xh, *xl, *w1h, *w1l, *w2h, *w2l, *aoh, *aol;
    cudaGetSymbolAddress((void**)&qkv, g_qkv);
    cudaGetSymbolAddress((void**)&xh,  g_x_hi);
    cudaGetSymbolAddress((void**)&xl,  g_x_lo);
    cudaGetSymbolAddress((void**)&w1h, g_w1_hi);
    cudaGetSymbolAddress((void**)&w1l, g_w1_lo);
    cudaGetSymbolAddress((void**)&w2h, g_w2_hi);
    cudaGetSymbolAddress((void**)&w2l, g_w2_lo);
    cudaGetSymbolAddress((void**)&aoh, g_ao_hi);
    cudaGetSymbolAddress((void**)&aol, g_ao_lo);

    cudaFuncSetAttribute(gemm_tc_kernel<4>,
                         cudaFuncAttributeMaxDynamicSharedMemorySize, GEMM3_SMEM);
    cudaFuncSetAttribute(gemm_tc_kernel<2>,
                         cudaFuncAttributeMaxDynamicSharedMemorySize, GEMM1_SMEM);
    cudaFuncSetAttribute(attn_mma_kernel,
                         cudaFuncAttributeMaxDynamicSharedMemorySize, ATTN_SMEM_BYTES);

    dim3 blk(256);

    split_kernel<<<(M_ROWS * CC + 255) / 256, blk>>>(x, xh, xl, M_ROWS * CC);
    split_kernel<<<(3 * CC * CC + 255) / 256, blk>>>(qkvw, w1h, w1l, 3 * CC * CC);
    split_kernel<<<(CC * CC + 255) / 256, blk>>>(projw, w2h, w2l, CC * CC);

    // q,k projection: single-pass bf16 (precision analysis: ~1e-4 output impact)
    gemm_tc_kernel<2><<<dim3(2048 / 128, M_ROWS / 128), blk, GEMM1_SMEM>>>(
        xh, nullptr, w1h, nullptr, nullptr, qkv, 3 * CC);
    // v projection: bf16x3
    gemm_tc_kernel<4><<<dim3(1024 / 128, M_ROWS / 128), blk, GEMM3_SMEM>>>(
        xh, xl, w1h + (size_t)2048 * CC, w1l + (size_t)2048 * CC,
        nullptr, qkv + 2048, 3 * CC);

    norm_split_kernel<<<(M_ROWS * HH) / 8, blk>>>();

    attn_mma_kernel<<<dim3(NN / 128, BB * HH), blk, ATTN_SMEM_BYTES>>>(cls, um);

    // output projection + bias: bf16x3
    gemm_tc_kernel<4><<<dim3(CC / 128, M_ROWS / 128), blk, GEMM3_SMEM>>>(
        aoh, aol, w2h, w2l, projb, out, CC);
}

// round 6
// speedup vs baseline: 6.1578x; 1.1593x over previous
#include <cuda_runtime.h>
#include <cuda_bf16.h>
#include <math.h>

#define BB 2
#define NN 2048
#define CC 1024
#define HH 16
#define HD 64
#define M_ROWS (BB*NN)   // 4096

// ---------------- device scratch (allocation-free) ----------------
__device__ float g_qkv[M_ROWS * 3 * CC];              // fp32 qkv [bn][3C]
__device__ __nv_bfloat16 g_x_hi[M_ROWS * CC];
__device__ __nv_bfloat16 g_x_lo[M_ROWS * CC];
__device__ __nv_bfloat16 g_w1_hi[3 * CC * CC];
__device__ __nv_bfloat16 g_w1_lo[3 * CC * CC];
__device__ __nv_bfloat16 g_w2_hi[CC * CC];
__device__ __nv_bfloat16 g_w2_lo[CC * CC];
// head-major [b*H+h][n][64] bf16
__device__ __nv_bfloat16 g_qn[BB * HH * NN * HD];
__device__ __nv_bfloat16 g_kn[BB * HH * NN * HD];
__device__ __nv_bfloat16 g_vh[BB * HH * NN * HD];
__device__ float g_vsum[BB * HH * HD];                // per-head V col sums (fp32 V!)
// attention output split, [B,N,C] layout
__device__ __nv_bfloat16 g_ao_hi[M_ROWS * CC];
__device__ __nv_bfloat16 g_ao_lo[M_ROWS * CC];

// ---------------- helpers ----------------
__global__ __launch_bounds__(256) void split_kernel(
    const float* __restrict__ in, __nv_bfloat16* __restrict__ hi,
    __nv_bfloat16* __restrict__ lo, int n)
{
    int i = blockIdx.x * blockDim.x + threadIdx.x;
    if (i < n) {
        float x = in[i];
        __nv_bfloat16 h = __float2bfloat16(x);
        hi[i] = h;
        lo[i] = __float2bfloat16(x - __bfloat162float(h));
    }
}

__device__ __forceinline__ void ldsm4(unsigned r[4], const void* p) {
    unsigned a = (unsigned)__cvta_generic_to_shared(p);
    asm volatile("ldmatrix.sync.aligned.m8n8.x4.shared.b16 {%0,%1,%2,%3}, [%4];"
                 : "=r"(r[0]), "=r"(r[1]), "=r"(r[2]), "=r"(r[3]) : "r"(a));
}
__device__ __forceinline__ void ldsm4t(unsigned r[4], const void* p) {
    unsigned a = (unsigned)__cvta_generic_to_shared(p);
    asm volatile("ldmatrix.sync.aligned.m8n8.x4.trans.shared.b16 {%0,%1,%2,%3}, [%4];"
                 : "=r"(r[0]), "=r"(r[1]), "=r"(r[2]), "=r"(r[3]) : "r"(a));
}
__device__ __forceinline__ void mma16816(float c[4], const unsigned a[4],
                                         unsigned b0, unsigned b1) {
    asm volatile(
        "mma.sync.aligned.m16n8k16.row.col.f32.bf16.bf16.f32 "
        "{%0,%1,%2,%3}, {%4,%5,%6,%7}, {%8,%9}, {%0,%1,%2,%3};"
        : "+f"(c[0]), "+f"(c[1]), "+f"(c[2]), "+f"(c[3])
        : "r"(a[0]), "r"(a[1]), "r"(a[2]), "r"(a[3]), "r"(b0), "r"(b1));
}
__device__ __forceinline__ void cp16(void* smem, const void* gmem) {
    unsigned sa = (unsigned)__cvta_generic_to_shared(smem);
    asm volatile("cp.async.cg.shared.global [%0], [%1], 16;\n" :: "r"(sa), "l"(gmem));
}

// ---------------------------------------------------------------------------
// Templated tensor-core GEMM (NT) — unchanged (verified R4).
// ---------------------------------------------------------------------------
#define GLDA 40
#define TILE_B (128 * GLDA * 2)   // 10240 B per 128x32 bf16 tile

template<int NARR>
__global__ __launch_bounds__(256, 2) void gemm_tc_kernel(
    const __nv_bfloat16* __restrict__ a_hi, const __nv_bfloat16* __restrict__ a_lo,
    const __nv_bfloat16* __restrict__ b_hi, const __nv_bfloat16* __restrict__ b_lo,
    const float* __restrict__ bias, float* __restrict__ C, int Nn)
{
    extern __shared__ char sm_raw[];
    const int K = CC;
    const int STAGE = NARR * TILE_B;
    int tid = threadIdx.x;
    int lane = tid & 31;
    int wid = tid >> 5;
    int warp_m = wid >> 2;
    int warp_n = wid & 3;
    int m0 = blockIdx.y * 128;
    int n0 = blockIdx.x * 128;

    const __nv_bfloat16* gptr[NARR];
    int rowbase[NARR];
    gptr[0] = a_hi; rowbase[0] = m0;
    if (NARR == 4) {
        gptr[1] = a_lo; rowbase[1] = m0;
        gptr[2] = b_hi; rowbase[2] = n0;
        gptr[3] = b_lo; rowbase[3] = n0;
    } else {
        gptr[1] = b_hi; rowbase[1] = n0;
    }

    float acc[4][4][4];
    #pragma unroll
    for (int mi = 0; mi < 4; ++mi)
        #pragma unroll
        for (int j = 0; j < 4; ++j)
            #pragma unroll
            for (int e = 0; e < 4; ++e) acc[mi][j][e] = 0.0f;

    auto load_stage = [&](int kt, int stage) {
        char* sbase = sm_raw + stage * STAGE;
        int k0 = kt * 32;
        #pragma unroll
        for (int t = 0; t < 2 * NARR; ++t) {
            int c = tid + t * 256;
            int arr = c >> 9;
            int r = (c >> 2) & 127;
            int c16 = c & 3;
            const __nv_bfloat16* g =
                gptr[arr] + (size_t)(rowbase[arr] + r) * K + k0 + c16 * 8;
            cp16(sbase + arr * TILE_B + r * (GLDA * 2) + c16 * 16, g);
        }
    };

    const int KT = K / 32;
    load_stage(0, 0);
    asm volatile("cp.async.commit_group;");

    for (int kt = 0; kt < KT; ++kt) {
        if (kt + 1 < KT) {
            load_stage(kt + 1, (kt + 1) & 1);
            asm volatile("cp.async.commit_group;");
            asm volatile("cp.async.wait_group 1;");
        } else {
            asm volatile("cp.async.wait_group 0;");
        }
        __syncthreads();

        char* sbase = sm_raw + (kt & 1) * STAGE;
        const char* As = sbase;
        const char* Bs = sbase + (NARR == 4 ? 2 : 1) * TILE_B;

        #pragma unroll
        for (int ks = 0; ks < 32; ks += 16) {
            int coloff = ks + ((lane >> 4) << 3);
            unsigned ah[4][4], al[4][4];
            #pragma unroll
            for (int mi = 0; mi < 4; ++mi) {
                int row = warp_m * 64 + mi * 16 + (lane & 15);
                const char* p = As + row * (GLDA * 2) + coloff * 2;
                ldsm4(ah[mi], p);
                if (NARR == 4) ldsm4(al[mi], p + TILE_B);
            }
            unsigned bh[2][4], bl[2][4];
            #pragma unroll
            for (int ni = 0; ni < 2; ++ni) {
                int row = warp_n * 32 + ni * 16 + (lane & 15);
                const char* p = Bs + row * (GLDA * 2) + coloff * 2;
                ldsm4(bh[ni], p);
                if (NARR == 4) ldsm4(bl[ni], p + TILE_B);
            }
            #pragma unroll
            for (int mi = 0; mi < 4; ++mi) {
                #pragma unroll
                for (int j = 0; j < 4; ++j) {
                    int ni = j >> 1, od = j & 1;
                    unsigned bh0 = bh[ni][od ? 1 : 0], bh1 = bh[ni][od ? 3 : 2];
                    mma16816(acc[mi][j], ah[mi], bh0, bh1);
                    if (NARR == 4) {
                        unsigned bl0 = bl[ni][od ? 1 : 0], bl1 = bl[ni][od ? 3 : 2];
                        mma16816(acc[mi][j], ah[mi], bl0, bl1);
                        mma16816(acc[mi][j], al[mi], bh0, bh1);
                    }
                }
            }
        }
        __syncthreads();
    }

    int mb = m0 + warp_m * 64 + (lane >> 2);
    int nb = n0 + warp_n * 32 + 2 * (lane & 3);
    #pragma unroll
    for (int mi = 0; mi < 4; ++mi) {
        #pragma unroll
        for (int j = 0; j < 4; ++j) {
            int col = nb + j * 8;
            float b0 = 0.f, b1 = 0.f;
            if (bias) { b0 = bias[col]; b1 = bias[col + 1]; }
            int r0 = mb + mi * 16;
            float2 v0 = make_float2(acc[mi][j][0] + b0, acc[mi][j][1] + b1);
            float2 v1 = make_float2(acc[mi][j][2] + b0, acc[mi][j][3] + b1);
            *reinterpret_cast<float2*>(&C[(size_t)r0 * Nn + col]) = v0;
            *reinterpret_cast<float2*>(&C[(size_t)(r0 + 8) * Nn + col]) = v1;
        }
    }
}

// ---------------------------------------------------------------------------
// Fused normalize + split (head-major outputs). V: single bf16 (hi only).
// ---------------------------------------------------------------------------
__global__ __launch_bounds__(256) void norm_split_kernel()
{
    int gw   = (blockIdx.x * 256 + threadIdx.x) >> 5;
    int lane = threadIdx.x & 31;
    int bn = gw >> 4;
    int h  = gw & 15;
    int b = bn >> 11, n = bn & 2047;
    size_t src  = (size_t)bn * 3072 + h * 64;
    size_t dst  = ((size_t)(b * HH + h) * NN + n) * 64 + 2 * lane;

    float2 q = *reinterpret_cast<const float2*>(&g_qkv[src + 2 * lane]);
    float s = q.x * q.x + q.y * q.y;
    #pragma unroll
    for (int o = 16; o; o >>= 1) s += __shfl_xor_sync(0xffffffffu, s, o);
    float inv = 0.125f / (sqrtf(s) + 1e-8f);
    *reinterpret_cast<__nv_bfloat162*>(&g_qn[dst]) =
        __floats2bfloat162_rn(q.x * inv, q.y * inv);

    float2 k = *reinterpret_cast<const float2*>(&g_qkv[src + 1024 + 2 * lane]);
    s = k.x * k.x + k.y * k.y;
    #pragma unroll
    for (int o = 16; o; o >>= 1) s += __shfl_xor_sync(0xffffffffu, s, o);
    inv = 1.0f / (sqrtf(s) + 1e-8f);
    *reinterpret_cast<__nv_bfloat162*>(&g_kn[dst]) =
        __floats2bfloat162_rn(k.x * inv, k.y * inv);

    float2 v = *reinterpret_cast<const float2*>(&g_qkv[src + 2048 + 2 * lane]);
    *reinterpret_cast<__nv_bfloat162*>(&g_vh[dst]) =
        __floats2bfloat162_rn(v.x, v.y);
}

// ---------------------------------------------------------------------------
// Per-head V column sums from FP32 V in g_qkv (precision-critical:
// bf16-V colsum alone costs ~1e-3 rel err — measured R5 failure).
// One block per bh; 256 threads = 64 d-columns x 4 k-chunks of 512.
// ---------------------------------------------------------------------------
__global__ __launch_bounds__(256) void vsum_kernel()
{
    __shared__ float part[4][64];
    int bh = blockIdx.x;
    int b = bh >> 4, h = bh & 15;
    int d = threadIdx.x & 63;
    int kc = threadIdx.x >> 6;
    const float* vb = g_qkv + (size_t)b * NN * 3072 + 2048 + h * 64 + d;
    float s = 0.0f;
    for (int k = kc * 512; k < (kc + 1) * 512; ++k)
        s += vb[(size_t)k * 3072];
    part[kc][d] = s;
    __syncthreads();
    if (kc == 0)
        g_vsum[bh * HD + d] = part[0][d] + part[1][d] + part[2][d] + part[3][d];
}

// ---------------------------------------------------------------------------
// Tensor-core attention with delta-trick:
//   p = exp(s) = 1 + delta;  sum_k p v = colsum_f32(V) + sum_k delta v_bf16
// PV is a SINGLE bf16 mma pass (delta x Vh). K,Vh double-buffered.
// ---------------------------------------------------------------------------
#define ATS 72
#define KTB (128 * ATS * 2)

__global__ __launch_bounds__(256, 2) void attn_mma_kernel(
    const float* __restrict__ cls, const int* __restrict__ um_p)
{
    extern __shared__ char smem[];
    // [K s0|s1][Vh s0|s1][sk s0|s1]
    float* sks = (float*)(smem + 4 * KTB);

    int tid = threadIdx.x;
    int lane = tid & 31;
    int warp = tid >> 5;
    int q0 = blockIdx.x * 128;
    int bh = blockIdx.y;
    int b = bh >> 4, h = bh & 15;
    int um = um_p[0];
    int r = lane >> 2;
    int c2 = 2 * (lane & 3);

    const __nv_bfloat16* qg = g_qn + ((size_t)bh * NN + q0 + warp * 16) * 64;
    unsigned qa[4][4];
    #pragma unroll
    for (int dc = 0; dc < 4; ++dc) {
        qa[dc][0] = *(const unsigned*)(qg + (size_t)r * 64 + 16 * dc + c2);
        qa[dc][1] = *(const unsigned*)(qg + (size_t)(r + 8) * 64 + 16 * dc + c2);
        qa[dc][2] = *(const unsigned*)(qg + (size_t)r * 64 + 16 * dc + 8 + c2);
        qa[dc][3] = *(const unsigned*)(qg + (size_t)(r + 8) * 64 + 16 * dc + 8 + c2);
    }
    float sq0 = cls[q0 + warp * 16 + r] - 0.1f;
    float sq8 = cls[q0 + warp * 16 + r + 8] - 0.1f;

    const __nv_bfloat16* kg  = g_kn + (size_t)bh * NN * 64;
    const __nv_bfloat16* vhg = g_vh + (size_t)bh * NN * 64;

    float o[8][4];
    #pragma unroll
    for (int i = 0; i < 8; ++i)
        #pragma unroll
        for (int e = 0; e < 4; ++e) o[i][e] = 0.0f;
    float l0 = 0.0f, l8 = 0.0f;

    auto stage_load = [&](int kt, int s) {
        #pragma unroll
        for (int t = 0; t < 8; ++t) {
            int cix = tid + t * 256;               // 0..2047
            int arr = cix >> 10;                   // 0:K 1:Vh
            int rr  = (cix >> 3) & 127;
            int seg = cix & 7;
            const __nv_bfloat16* gb = (arr == 0) ? kg : vhg;
            const __nv_bfloat16* g = gb + ((size_t)(kt * 128 + rr)) * 64 + seg * 8;
            cp16(smem + arr * 2 * KTB + s * KTB + rr * (ATS * 2) + seg * 16, g);
        }
        if (tid < 128) sks[s * 128 + tid] = cls[kt * 128 + tid];
    };

    stage_load(0, 0);
    asm volatile("cp.async.commit_group;");

    for (int kt = 0; kt < NN / 128; ++kt) {
        asm volatile("cp.async.wait_group 0;");
        __syncthreads();
        if (kt + 1 < NN / 128) {
            stage_load(kt + 1, (kt + 1) & 1);
            asm volatile("cp.async.commit_group;");
        }
        int s = kt & 1;
        const char* Kb  = smem + s * KTB;
        const char* Vhb = smem + 2 * KTB + s * KTB;
        const float* sk = sks + s * 128;

        #pragma unroll
        for (int j = 0; j < 8; ++j) {
            // ---- S = Q K^T for keys [16j, 16j+16) ----
            float cc[2][4] = {{0, 0, 0, 0}, {0, 0, 0, 0}};
            int krow = 16 * j + (lane & 15);
            #pragma unroll
            for (int dc = 0; dc < 4; ++dc) {
                unsigned kb[4];
                ldsm4(kb, Kb + krow * (ATS * 2) + (16 * dc + ((lane >> 4) << 3)) * 2);
                mma16816(cc[0], qa[dc], kb[0], kb[2]);
                mma16816(cc[1], qa[dc], kb[1], kb[3]);
            }
            // ---- scale, mask, p = exp, delta = p-1 packed to bf16 ----
            unsigned ad[4];
            #pragma unroll
            for (int t = 0; t < 2; ++t) {
                float2 skv = *reinterpret_cast<const float2*>(&sk[16 * j + 8 * t + c2]);
                float fx0 = (um && !(skv.x > sq0)) ? 0.f : skv.x;
                float fy0 = (um && !(skv.y > sq0)) ? 0.f : skv.y;
                float fx8 = (um && !(skv.x > sq8)) ? 0.f : skv.x;
                float fy8 = (um && !(skv.y > sq8)) ? 0.f : skv.y;
                float p00 = __expf(cc[t][0] * fx0);
                float p01 = __expf(cc[t][1] * fy0);
                float p80 = __expf(cc[t][2] * fx8);
                float p81 = __expf(cc[t][3] * fy8);
                l0 += p00 + p01;
                l8 += p80 + p81;
                __nv_bfloat162 D0 = __floats2bfloat162_rn(p00 - 1.0f, p01 - 1.0f);
                __nv_bfloat162 D8 = __floats2bfloat162_rn(p80 - 1.0f, p81 - 1.0f);
                ad[2 * t]     = *reinterpret_cast<unsigned*>(&D0);
                ad[2 * t + 1] = *reinterpret_cast<unsigned*>(&D8);
            }
            // ---- O += delta * Vh (single pass) ----
            #pragma unroll
            for (int n2 = 0; n2 < 4; ++n2) {
                unsigned vb[4];
                int voff = krow * (ATS * 2) + (16 * n2 + ((lane >> 4) << 3)) * 2;
                ldsm4t(vb, Vhb + voff);
                mma16816(o[2 * n2],     ad, vb[0], vb[1]);
                mma16816(o[2 * n2 + 1], ad, vb[2], vb[3]);
            }
        }
    }

    l0 += __shfl_xor_sync(0xffffffffu, l0, 1);
    l0 += __shfl_xor_sync(0xffffffffu, l0, 2);
    l8 += __shfl_xor_sync(0xffffffffu, l8, 1);
    l8 += __shfl_xor_sync(0xffffffffu, l8, 2);
    float inv0 = 1.0f / l0, inv8 = 1.0f / l8;

    const float* vs = g_vsum + bh * HD;
    size_t row0 = ((size_t)(b * NN + q0 + warp * 16 + r)) * CC + h * 64;
    size_t row8 = ((size_t)(b * NN + q0 + warp * 16 + r + 8)) * CC + h * 64;
    #pragma unroll
    for (int nt = 0; nt < 8; ++nt) {
        int d = 8 * nt + c2;
        float2 vsd = *reinterpret_cast<const float2*>(&vs[d]);
        float v0 = (o[nt][0] + vsd.x) * inv0, v1 = (o[nt][1] + vsd.y) * inv0;
        __nv_bfloat162 H = __floats2bfloat162_rn(v0, v1);
        float2 Hf = __bfloat1622float2(H);
        __nv_bfloat162 L = __floats2bfloat162_rn(v0 - Hf.x, v1 - Hf.y);
        *reinterpret_cast<__nv_bfloat162*>(&g_ao_hi[row0 + d]) = H;
        *reinterpret_cast<__nv_bfloat162*>(&g_ao_lo[row0 + d]) = L;
        float w0 = (o[nt][2] + vsd.x) * inv8, w1 = (o[nt][3] + vsd.y) * inv8;
        __nv_bfloat162 H2 = __floats2bfloat162_rn(w0, w1);
        float2 H2f = __bfloat1622float2(H2);
        __nv_bfloat162 L2 = __floats2bfloat162_rn(w0 - H2f.x, w1 - H2f.y);
        *reinterpret_cast<__nv_bfloat162*>(&g_ao_hi[row8 + d]) = H2;
        *reinterpret_cast<__nv_bfloat162*>(&g_ao_lo[row8 + d]) = L2;
    }
}

// ---------------------------------------------------------------------------
// Launch
// ---------------------------------------------------------------------------
static const int GEMM3_SMEM = 2 * 4 * TILE_B;   // 81920
static const int GEMM1_SMEM = 2 * 2 * TILE_B;   // 40960
static const int ATTN_SMEM_BYTES = 4 * KTB + 2 * 128 * (int)sizeof(float); // 74752

extern "C" void kernel_launch(void* const* d_in, const int* in_sizes, int n_in,
                              void* d_out, int out_size)
{
    const float* x     = (const float*)d_in[0];
    const float* cls   = (const float*)d_in[1];
    const float* qkvw  = (const float*)d_in[2];
    const float* projw = (const float*)d_in[3];
    const float* projb = (const float*)d_in[4];
    const int*   um    = (const int*)d_in[5];
    float* out = (float*)d_out;

    float* qkv = nullptr;
    __nv_bfloat16 *xh, *xl, *w1h, *w1l, *w2h, *w2l, *aoh, *aol;
    cudaGetSymbolAddress((void**)&qkv, g_qkv);
    cudaGetSymbolAddress((void**)&xh,  g_x_hi);
    cudaGetSymbolAddress((void**)&xl,  g_x_lo);
    cudaGetSymbolAddress((void**)&w1h, g_w1_hi);
    cudaGetSymbolAddress((void**)&w1l, g_w1_lo);
    cudaGetSymbolAddress((void**)&w2h, g_w2_hi);
    cudaGetSymbolAddress((void**)&w2l, g_w2_lo);
    cudaGetSymbolAddress((void**)&aoh, g_ao_hi);
    cudaGetSymbolAddress((void**)&aol, g_ao_lo);

    cudaFuncSetAttribute(gemm_tc_kernel<4>,
                         cudaFuncAttributeMaxDynamicSharedMemorySize, GEMM3_SMEM);
    cudaFuncSetAttribute(gemm_tc_kernel<2>,
                         cudaFuncAttributeMaxDynamicSharedMemorySize, GEMM1_SMEM);
    cudaFuncSetAttribute(attn_mma_kernel,
                         cudaFuncAttributeMaxDynamicSharedMemorySize, ATTN_SMEM_BYTES);

    dim3 blk(256);

    split_kernel<<<(M_ROWS * CC + 255) / 256, blk>>>(x, xh, xl, M_ROWS * CC);
    split_kernel<<<(3 * CC * CC + 255) / 256, blk>>>(qkvw, w1h, w1l, 3 * CC * CC);
    split_kernel<<<(CC * CC + 255) / 256, blk>>>(projw, w2h, w2l, CC * CC);

    // q,k projection: single-pass bf16
    gemm_tc_kernel<2><<<dim3(2048 / 128, M_ROWS / 128), blk, GEMM1_SMEM>>>(
        xh, nullptr, w1h, nullptr, nullptr, qkv, 3 * CC);
    // v projection: bf16x3
    gemm_tc_kernel<4><<<dim3(1024 / 128, M_ROWS / 128), blk, GEMM3_SMEM>>>(
        xh, xl, w1h + (size_t)2048 * CC, w1l + (size_t)2048 * CC,
        nullptr, qkv + 2048, 3 * CC);

    norm_split_kernel<<<(M_ROWS * HH) / 8, blk>>>();
    vsum_kernel<<<BB * HH, blk>>>();    // fp32 V colsum

    attn_mma_kernel<<<dim3(NN / 128, BB * HH), blk, ATTN_SMEM_BYTES>>>(cls, um);

    // output projection + bias: bf16x3
    gemm_tc_kernel<4><<<dim3(CC / 128, M_ROWS / 128), blk, GEMM3_SMEM>>>(
        aoh, aol, w2h, w2l, projb, out, CC);
}

// round 7
// speedup vs baseline: 6.6122x; 1.0738x over previous
#include <cuda_runtime.h>
#include <cuda_bf16.h>
#include <math.h>

#define BB 2
#define NN 2048
#define CC 1024
#define HH 16
#define HD 64
#define M_ROWS (BB*NN)   // 4096

// ---------------- device scratch (allocation-free) ----------------
__device__ float g_qkv[M_ROWS * 3 * CC];              // fp32 qkv [bn][3C]
__device__ __nv_bfloat16 g_x_hi[M_ROWS * CC];
__device__ __nv_bfloat16 g_w1_hi[3 * CC * CC];
__device__ __nv_bfloat16 g_w2_hi[CC * CC];
__device__ __nv_bfloat16 g_w2_lo[CC * CC];
// head-major [b*H+h][n][64] bf16
__device__ __nv_bfloat16 g_qn[BB * HH * NN * HD];
__device__ __nv_bfloat16 g_kn[BB * HH * NN * HD];
__device__ __nv_bfloat16 g_vh[BB * HH * NN * HD];
__device__ float g_xsum[BB * CC];                     // colsum of x (fp32 exact)
__device__ float g_vsum[BB * HH * HD];                // exact colsum of V
// attention output split, [B,N,C] layout
__device__ __nv_bfloat16 g_ao_hi[M_ROWS * CC];
__device__ __nv_bfloat16 g_ao_lo[M_ROWS * CC];

// ---------------- elementwise kernels ----------------
__global__ __launch_bounds__(256) void split_kernel(
    const float* __restrict__ in, __nv_bfloat16* __restrict__ hi,
    __nv_bfloat16* __restrict__ lo, int n)
{
    int i = blockIdx.x * blockDim.x + threadIdx.x;
    if (i < n) {
        float x = in[i];
        __nv_bfloat16 h = __float2bfloat16(x);
        hi[i] = h;
        lo[i] = __float2bfloat16(x - __bfloat162float(h));
    }
}
__global__ __launch_bounds__(256) void tobf16_kernel(
    const float* __restrict__ in, __nv_bfloat16* __restrict__ out, int n)
{
    int i = blockIdx.x * blockDim.x + threadIdx.x;
    if (i < n) out[i] = __float2bfloat16(in[i]);
}

// colsum of x over tokens: g_xsum[b*CC + c] = sum_n x[b,n,c]  (fp32 exact)
__global__ __launch_bounds__(256) void xsum_kernel(const float* __restrict__ x)
{
    int c = blockIdx.x * 256 + threadIdx.x;     // 0..2047 (b*1024+c)
    int b = c >> 10, cc = c & 1023;
    const float* p = x + (size_t)b * NN * CC + cc;
    float s = 0.0f;
    for (int n = 0; n < NN; ++n) s += p[(size_t)n * CC];
    g_xsum[c] = s;
}

// exact V colsum via GEMV: g_vsum[b*1024 + dfull] = xsum[b,:] . Wv[dfull,:]
__global__ __launch_bounds__(256) void vsumx_kernel(const float* __restrict__ w)
{
    int gw = (blockIdx.x * 256 + threadIdx.x) >> 5;   // 0..2047
    int lane = threadIdx.x & 31;
    int b = gw >> 10, dfull = gw & 1023;
    const float* wr = w + (size_t)(2048 + dfull) * CC;
    const float* xs = g_xsum + b * CC;
    float s = 0.0f;
    #pragma unroll 8
    for (int i = lane; i < CC; i += 32) s += xs[i] * wr[i];
    #pragma unroll
    for (int o = 16; o; o >>= 1) s += __shfl_xor_sync(0xffffffffu, s, o);
    if (lane == 0) g_vsum[b * CC + dfull] = s;
}

// ---------------- mma helpers ----------------
__device__ __forceinline__ void ldsm4(unsigned r[4], const void* p) {
    unsigned a = (unsigned)__cvta_generic_to_shared(p);
    asm volatile("ldmatrix.sync.aligned.m8n8.x4.shared.b16 {%0,%1,%2,%3}, [%4];"
                 : "=r"(r[0]), "=r"(r[1]), "=r"(r[2]), "=r"(r[3]) : "r"(a));
}
__device__ __forceinline__ void ldsm4t(unsigned r[4], const void* p) {
    unsigned a = (unsigned)__cvta_generic_to_shared(p);
    asm volatile("ldmatrix.sync.aligned.m8n8.x4.trans.shared.b16 {%0,%1,%2,%3}, [%4];"
                 : "=r"(r[0]), "=r"(r[1]), "=r"(r[2]), "=r"(r[3]) : "r"(a));
}
__device__ __forceinline__ void mma16816(float c[4], const unsigned a[4],
                                         unsigned b0, unsigned b1) {
    asm volatile(
        "mma.sync.aligned.m16n8k16.row.col.f32.bf16.bf16.f32 "
        "{%0,%1,%2,%3}, {%4,%5,%6,%7}, {%8,%9}, {%0,%1,%2,%3};"
        : "+f"(c[0]), "+f"(c[1]), "+f"(c[2]), "+f"(c[3])
        : "r"(a[0]), "r"(a[1]), "r"(a[2]), "r"(a[3]), "r"(b0), "r"(b1));
}
__device__ __forceinline__ void cp16(void* smem, const void* gmem) {
    unsigned sa = (unsigned)__cvta_generic_to_shared(smem);
    asm volatile("cp.async.cg.shared.global [%0], [%1], 16;\n" :: "r"(sa), "l"(gmem));
}

#define GLDA 40
#define TILE_B (128 * GLDA * 2)   // 10240 B per 128x32 bf16 tile

// ---------------------------------------------------------------------------
// Single-pass bf16 GEMM (NT), 4-stage cp.async pipeline, 2 CTAs/SM.
// C[m][n] = sum_k A[m][k]*B[n][k].  K=1024 fixed.
// ---------------------------------------------------------------------------
__global__ __launch_bounds__(256, 2) void gemm1p_kernel(
    const __nv_bfloat16* __restrict__ A, const __nv_bfloat16* __restrict__ Bm,
    float* __restrict__ C, int Nn)
{
    extern __shared__ char sm_raw[];
    const int STAGE = 2 * TILE_B;   // A tile + B tile = 20480 B
    int tid = threadIdx.x;
    int lane = tid & 31;
    int wid = tid >> 5;
    int warp_m = wid >> 2;
    int warp_n = wid & 3;
    int m0 = blockIdx.y * 128;
    int n0 = blockIdx.x * 128;

    float acc[4][4][4];
    #pragma unroll
    for (int mi = 0; mi < 4; ++mi)
        #pragma unroll
        for (int j = 0; j < 4; ++j)
            #pragma unroll
            for (int e = 0; e < 4; ++e) acc[mi][j][e] = 0.0f;

    auto load_stage = [&](int kt, int s) {
        char* sb = sm_raw + s * STAGE;
        int k0 = kt * 32;
        #pragma unroll
        for (int t = 0; t < 4; ++t) {
            int c = tid + t * 256;        // 0..1023
            int arr = c >> 9;             // 0:A 1:B
            int r = (c >> 2) & 127;
            int c16 = c & 3;
            const __nv_bfloat16* g =
                (arr ? Bm : A) + (size_t)((arr ? n0 : m0) + r) * CC + k0 + c16 * 8;
            cp16(sb + arr * TILE_B + r * (GLDA * 2) + c16 * 16, g);
        }
    };

    const int KT = CC / 32;   // 32
    load_stage(0, 0); asm volatile("cp.async.commit_group;");
    load_stage(1, 1); asm volatile("cp.async.commit_group;");
    load_stage(2, 2); asm volatile("cp.async.commit_group;");

    for (int kt = 0; kt < KT; ++kt) {
        asm volatile("cp.async.wait_group 2;");
        __syncthreads();
        const char* As = sm_raw + (kt & 3) * STAGE;
        const char* Bs = As + TILE_B;

        #pragma unroll
        for (int ks = 0; ks < 32; ks += 16) {
            int coloff = ks + ((lane >> 4) << 3);
            unsigned ah[4][4];
            #pragma unroll
            for (int mi = 0; mi < 4; ++mi)
                ldsm4(ah[mi], As + (warp_m * 64 + mi * 16 + (lane & 15)) * (GLDA * 2)
                               + coloff * 2);
            unsigned bh[2][4];
            #pragma unroll
            for (int ni = 0; ni < 2; ++ni)
                ldsm4(bh[ni], Bs + (warp_n * 32 + ni * 16 + (lane & 15)) * (GLDA * 2)
                               + coloff * 2);
            #pragma unroll
            for (int mi = 0; mi < 4; ++mi)
                #pragma unroll
                for (int j = 0; j < 4; ++j) {
                    int ni = j >> 1, od = j & 1;
                    mma16816(acc[mi][j], ah[mi],
                             bh[ni][od ? 1 : 0], bh[ni][od ? 3 : 2]);
                }
        }
        if (kt + 3 < KT) {
            load_stage(kt + 3, (kt + 3) & 3);
            asm volatile("cp.async.commit_group;");
        }
    }

    int mb = m0 + warp_m * 64 + (lane >> 2);
    int nb = n0 + warp_n * 32 + 2 * (lane & 3);
    #pragma unroll
    for (int mi = 0; mi < 4; ++mi)
        #pragma unroll
        for (int j = 0; j < 4; ++j) {
            int col = nb + j * 8;
            int r0 = mb + mi * 16;
            float2 v0 = make_float2(acc[mi][j][0], acc[mi][j][1]);
            float2 v1 = make_float2(acc[mi][j][2], acc[mi][j][3]);
            *reinterpret_cast<float2*>(&C[(size_t)r0 * Nn + col]) = v0;
            *reinterpret_cast<float2*>(&C[(size_t)(r0 + 8) * Nn + col]) = v1;
        }
}

// ---------------------------------------------------------------------------
// bf16x3 GEMM (NT) for the output projection — unchanged (verified R4).
// ---------------------------------------------------------------------------
__global__ __launch_bounds__(256, 2) void gemm3p_kernel(
    const __nv_bfloat16* __restrict__ a_hi, const __nv_bfloat16* __restrict__ a_lo,
    const __nv_bfloat16* __restrict__ b_hi, const __nv_bfloat16* __restrict__ b_lo,
    const float* __restrict__ bias, float* __restrict__ C, int Nn)
{
    extern __shared__ char sm_raw[];
    const int STAGE = 4 * TILE_B;
    int tid = threadIdx.x;
    int lane = tid & 31;
    int wid = tid >> 5;
    int warp_m = wid >> 2;
    int warp_n = wid & 3;
    int m0 = blockIdx.y * 128;
    int n0 = blockIdx.x * 128;

    const __nv_bfloat16* gptr[4] = {a_hi, a_lo, b_hi, b_lo};
    int rowbase[4] = {m0, m0, n0, n0};

    float acc[4][4][4];
    #pragma unroll
    for (int mi = 0; mi < 4; ++mi)
        #pragma unroll
        for (int j = 0; j < 4; ++j)
            #pragma unroll
            for (int e = 0; e < 4; ++e) acc[mi][j][e] = 0.0f;

    auto load_stage = [&](int kt, int stage) {
        char* sbase = sm_raw + stage * STAGE;
        int k0 = kt * 32;
        #pragma unroll
        for (int t = 0; t < 8; ++t) {
            int c = tid + t * 256;
            int arr = c >> 9;
            int r = (c >> 2) & 127;
            int c16 = c & 3;
            const __nv_bfloat16* g =
                gptr[arr] + (size_t)(rowbase[arr] + r) * CC + k0 + c16 * 8;
            cp16(sbase + arr * TILE_B + r * (GLDA * 2) + c16 * 16, g);
        }
    };

    const int KT = CC / 32;
    load_stage(0, 0);
    asm volatile("cp.async.commit_group;");

    for (int kt = 0; kt < KT; ++kt) {
        if (kt + 1 < KT) {
            load_stage(kt + 1, (kt + 1) & 1);
            asm volatile("cp.async.commit_group;");
            asm volatile("cp.async.wait_group 1;");
        } else {
            asm volatile("cp.async.wait_group 0;");
        }
        __syncthreads();

        char* sbase = sm_raw + (kt & 1) * STAGE;
        const char* As = sbase;
        const char* Bs = sbase + 2 * TILE_B;

        #pragma unroll
        for (int ks = 0; ks < 32; ks += 16) {
            int coloff = ks + ((lane >> 4) << 3);
            unsigned ah[4][4], al[4][4];
            #pragma unroll
            for (int mi = 0; mi < 4; ++mi) {
                const char* p = As + (warp_m * 64 + mi * 16 + (lane & 15)) * (GLDA * 2)
                                 + coloff * 2;
                ldsm4(ah[mi], p);
                ldsm4(al[mi], p + TILE_B);
            }
            unsigned bh[2][4], bl[2][4];
            #pragma unroll
            for (int ni = 0; ni < 2; ++ni) {
                const char* p = Bs + (warp_n * 32 + ni * 16 + (lane & 15)) * (GLDA * 2)
                                 + coloff * 2;
                ldsm4(bh[ni], p);
                ldsm4(bl[ni], p + TILE_B);
            }
            #pragma unroll
            for (int mi = 0; mi < 4; ++mi)
                #pragma unroll
                for (int j = 0; j < 4; ++j) {
                    int ni = j >> 1, od = j & 1;
                    unsigned b0 = bh[ni][od ? 1 : 0], b1 = bh[ni][od ? 3 : 2];
                    unsigned c0 = bl[ni][od ? 1 : 0], c1 = bl[ni][od ? 3 : 2];
                    mma16816(acc[mi][j], ah[mi], b0, b1);
                    mma16816(acc[mi][j], ah[mi], c0, c1);
                    mma16816(acc[mi][j], al[mi], b0, b1);
                }
        }
        __syncthreads();
    }

    int mb = m0 + warp_m * 64 + (lane >> 2);
    int nb = n0 + warp_n * 32 + 2 * (lane & 3);
    #pragma unroll
    for (int mi = 0; mi < 4; ++mi)
        #pragma unroll
        for (int j = 0; j < 4; ++j) {
            int col = nb + j * 8;
            float b0 = bias[col], b1 = bias[col + 1];
            int r0 = mb + mi * 16;
            float2 v0 = make_float2(acc[mi][j][0] + b0, acc[mi][j][1] + b1);
            float2 v1 = make_float2(acc[mi][j][2] + b0, acc[mi][j][3] + b1);
            *reinterpret_cast<float2*>(&C[(size_t)r0 * Nn + col]) = v0;
            *reinterpret_cast<float2*>(&C[(size_t)(r0 + 8) * Nn + col]) = v1;
        }
}

// ---------------------------------------------------------------------------
// Fused normalize + split (head-major outputs). V: single bf16.
// ---------------------------------------------------------------------------
__global__ __launch_bounds__(256) void norm_split_kernel()
{
    int gw   = (blockIdx.x * 256 + threadIdx.x) >> 5;
    int lane = threadIdx.x & 31;
    int bn = gw >> 4;
    int h  = gw & 15;
    int b = bn >> 11, n = bn & 2047;
    size_t src  = (size_t)bn * 3072 + h * 64;
    size_t dst  = ((size_t)(b * HH + h) * NN + n) * 64 + 2 * lane;

    float2 q = *reinterpret_cast<const float2*>(&g_qkv[src + 2 * lane]);
    float s = q.x * q.x + q.y * q.y;
    #pragma unroll
    for (int o = 16; o; o >>= 1) s += __shfl_xor_sync(0xffffffffu, s, o);
    float inv = 0.125f / (sqrtf(s) + 1e-8f);
    *reinterpret_cast<__nv_bfloat162*>(&g_qn[dst]) =
        __floats2bfloat162_rn(q.x * inv, q.y * inv);

    float2 k = *reinterpret_cast<const float2*>(&g_qkv[src + 1024 + 2 * lane]);
    s = k.x * k.x + k.y * k.y;
    #pragma unroll
    for (int o = 16; o; o >>= 1) s += __shfl_xor_sync(0xffffffffu, s, o);
    inv = 1.0f / (sqrtf(s) + 1e-8f);
    *reinterpret_cast<__nv_bfloat162*>(&g_kn[dst]) =
        __floats2bfloat162_rn(k.x * inv, k.y * inv);

    float2 v = *reinterpret_cast<const float2*>(&g_qkv[src + 2048 + 2 * lane]);
    *reinterpret_cast<__nv_bfloat162*>(&g_vh[dst]) =
        __floats2bfloat162_rn(v.x, v.y);
}

// ---------------------------------------------------------------------------
// Tensor-core attention with delta-trick (unchanged R6, verified).
// ---------------------------------------------------------------------------
#define ATS 72
#define KTB (128 * ATS * 2)

__global__ __launch_bounds__(256, 2) void attn_mma_kernel(
    const float* __restrict__ cls, const int* __restrict__ um_p)
{
    extern __shared__ char smem[];
    float* sks = (float*)(smem + 4 * KTB);

    int tid = threadIdx.x;
    int lane = tid & 31;
    int warp = tid >> 5;
    int q0 = blockIdx.x * 128;
    int bh = blockIdx.y;
    int b = bh >> 4, h = bh & 15;
    int um = um_p[0];
    int r = lane >> 2;
    int c2 = 2 * (lane & 3);

    const __nv_bfloat16* qg = g_qn + ((size_t)bh * NN + q0 + warp * 16) * 64;
    unsigned qa[4][4];
    #pragma unroll
    for (int dc = 0; dc < 4; ++dc) {
        qa[dc][0] = *(const unsigned*)(qg + (size_t)r * 64 + 16 * dc + c2);
        qa[dc][1] = *(const unsigned*)(qg + (size_t)(r + 8) * 64 + 16 * dc + c2);
        qa[dc][2] = *(const unsigned*)(qg + (size_t)r * 64 + 16 * dc + 8 + c2);
        qa[dc][3] = *(const unsigned*)(qg + (size_t)(r + 8) * 64 + 16 * dc + 8 + c2);
    }
    float sq0 = cls[q0 + warp * 16 + r] - 0.1f;
    float sq8 = cls[q0 + warp * 16 + r + 8] - 0.1f;

    const __nv_bfloat16* kg  = g_kn + (size_t)bh * NN * 64;
    const __nv_bfloat16* vhg = g_vh + (size_t)bh * NN * 64;

    float o[8][4];
    #pragma unroll
    for (int i = 0; i < 8; ++i)
        #pragma unroll
        for (int e = 0; e < 4; ++e) o[i][e] = 0.0f;
    float l0 = 0.0f, l8 = 0.0f;

    auto stage_load = [&](int kt, int s) {
        #pragma unroll
        for (int t = 0; t < 8; ++t) {
            int cix = tid + t * 256;
            int arr = cix >> 10;
            int rr  = (cix >> 3) & 127;
            int seg = cix & 7;
            const __nv_bfloat16* gb = (arr == 0) ? kg : vhg;
            const __nv_bfloat16* g = gb + ((size_t)(kt * 128 + rr)) * 64 + seg * 8;
            cp16(smem + arr * 2 * KTB + s * KTB + rr * (ATS * 2) + seg * 16, g);
        }
        if (tid < 128) sks[s * 128 + tid] = cls[kt * 128 + tid];
    };

    stage_load(0, 0);
    asm volatile("cp.async.commit_group;");

    for (int kt = 0; kt < NN / 128; ++kt) {
        asm volatile("cp.async.wait_group 0;");
        __syncthreads();
        if (kt + 1 < NN / 128) {
            stage_load(kt + 1, (kt + 1) & 1);
            asm volatile("cp.async.commit_group;");
        }
        int s = kt & 1;
        const char* Kb  = smem + s * KTB;
        const char* Vhb = smem + 2 * KTB + s * KTB;
        const float* sk = sks + s * 128;

        #pragma unroll
        for (int j = 0; j < 8; ++j) {
            float cc[2][4] = {{0, 0, 0, 0}, {0, 0, 0, 0}};
            int krow = 16 * j + (lane & 15);
            #pragma unroll
            for (int dc = 0; dc < 4; ++dc) {
                unsigned kb[4];
                ldsm4(kb, Kb + krow * (ATS * 2) + (16 * dc + ((lane >> 4) << 3)) * 2);
                mma16816(cc[0], qa[dc], kb[0], kb[2]);
                mma16816(cc[1], qa[dc], kb[1], kb[3]);
            }
            unsigned ad[4];
            #pragma unroll
            for (int t = 0; t < 2; ++t) {
                float2 skv = *reinterpret_cast<const float2*>(&sk[16 * j + 8 * t + c2]);
                float fx0 = (um && !(skv.x > sq0)) ? 0.f : skv.x;
                float fy0 = (um && !(skv.y > sq0)) ? 0.f : skv.y;
                float fx8 = (um && !(skv.x > sq8)) ? 0.f : skv.x;
                float fy8 = (um && !(skv.y > sq8)) ? 0.f : skv.y;
                float p00 = __expf(cc[t][0] * fx0);
                float p01 = __expf(cc[t][1] * fy0);
                float p80 = __expf(cc[t][2] * fx8);
                float p81 = __expf(cc[t][3] * fy8);
                l0 += p00 + p01;
                l8 += p80 + p81;
                __nv_bfloat162 D0 = __floats2bfloat162_rn(p00 - 1.0f, p01 - 1.0f);
                __nv_bfloat162 D8 = __floats2bfloat162_rn(p80 - 1.0f, p81 - 1.0f);
                ad[2 * t]     = *reinterpret_cast<unsigned*>(&D0);
                ad[2 * t + 1] = *reinterpret_cast<unsigned*>(&D8);
            }
            #pragma unroll
            for (int n2 = 0; n2 < 4; ++n2) {
                unsigned vb[4];
                int voff = krow * (ATS * 2) + (16 * n2 + ((lane >> 4) << 3)) * 2;
                ldsm4t(vb, Vhb + voff);
                mma16816(o[2 * n2],     ad, vb[0], vb[1]);
                mma16816(o[2 * n2 + 1], ad, vb[2], vb[3]);
            }
        }
    }

    l0 += __shfl_xor_sync(0xffffffffu, l0, 1);
    l0 += __shfl_xor_sync(0xffffffffu, l0, 2);
    l8 += __shfl_xor_sync(0xffffffffu, l8, 1);
    l8 += __shfl_xor_sync(0xffffffffu, l8, 2);
    float inv0 = 1.0f / l0, inv8 = 1.0f / l8;

    const float* vs = g_vsum + bh * HD;
    size_t row0 = ((size_t)(b * NN + q0 + warp * 16 + r)) * CC + h * 64;
    size_t row8 = ((size_t)(b * NN + q0 + warp * 16 + r + 8)) * CC + h * 64;
    #pragma unroll
    for (int nt = 0; nt < 8; ++nt) {
        int d = 8 * nt + c2;
        float2 vsd = *reinterpret_cast<const float2*>(&vs[d]);
        float v0 = (o[nt][0] + vsd.x) * inv0, v1 = (o[nt][1] + vsd.y) * inv0;
        __nv_bfloat162 H = __floats2bfloat162_rn(v0, v1);
        float2 Hf = __bfloat1622float2(H);
        __nv_bfloat162 L = __floats2bfloat162_rn(v0 - Hf.x, v1 - Hf.y);
        *reinterpret_cast<__nv_bfloat162*>(&g_ao_hi[row0 + d]) = H;
        *reinterpret_cast<__nv_bfloat162*>(&g_ao_lo[row0 + d]) = L;
        float w0 = (o[nt][2] + vsd.x) * inv8, w1 = (o[nt][3] + vsd.y) * inv8;
        __nv_bfloat162 H2 = __floats2bfloat162_rn(w0, w1);
        float2 H2f = __bfloat1622float2(H2);
        __nv_bfloat162 L2 = __floats2bfloat162_rn(w0 - H2f.x, w1 - H2f.y);
        *reinterpret_cast<__nv_bfloat162*>(&g_ao_hi[row8 + d]) = H2;
        *reinterpret_cast<__nv_bfloat162*>(&g_ao_lo[row8 + d]) = L2;
    }
}

// ---------------------------------------------------------------------------
// Launch
// ---------------------------------------------------------------------------
static const int GEMM1P_SMEM = 4 * 2 * TILE_B;   // 81920 (4 stages)
static const int GEMM3P_SMEM = 2 * 4 * TILE_B;   // 81920 (2 stages)
static const int ATTN_SMEM_BYTES = 4 * KTB + 2 * 128 * (int)sizeof(float); // 74752

extern "C" void kernel_launch(void* const* d_in, const int* in_sizes, int n_in,
                              void* d_out, int out_size)
{
    const float* x     = (const float*)d_in[0];
    const float* cls   = (const float*)d_in[1];
    const float* qkvw  = (const float*)d_in[2];
    const float* projw = (const float*)d_in[3];
    const float* projb = (const float*)d_in[4];
    const int*   um    = (const int*)d_in[5];
    float* out = (float*)d_out;

    float* qkv = nullptr;
    __nv_bfloat16 *xh, *w1h, *w2h, *w2l, *aoh, *aol;
    cudaGetSymbolAddress((void**)&qkv, g_qkv);
    cudaGetSymbolAddress((void**)&xh,  g_x_hi);
    cudaGetSymbolAddress((void**)&w1h, g_w1_hi);
    cudaGetSymbolAddress((void**)&w2h, g_w2_hi);
    cudaGetSymbolAddress((void**)&w2l, g_w2_lo);
    cudaGetSymbolAddress((void**)&aoh, g_ao_hi);
    cudaGetSymbolAddress((void**)&aol, g_ao_lo);

    cudaFuncSetAttribute(gemm1p_kernel,
                         cudaFuncAttributeMaxDynamicSharedMemorySize, GEMM1P_SMEM);
    cudaFuncSetAttribute(gemm3p_kernel,
                         cudaFuncAttributeMaxDynamicSharedMemorySize, GEMM3P_SMEM);
    cudaFuncSetAttribute(attn_mma_kernel,
                         cudaFuncAttributeMaxDynamicSharedMemorySize, ATTN_SMEM_BYTES);

    dim3 blk(256);

    // converts / splits
    tobf16_kernel<<<(M_ROWS * CC + 255) / 256, blk>>>(x, xh, M_ROWS * CC);
    tobf16_kernel<<<(3 * CC * CC + 255) / 256, blk>>>(qkvw, w1h, 3 * CC * CC);
    split_kernel<<<(CC * CC + 255) / 256, blk>>>(projw, w2h, w2l, CC * CC);

    // exact V colsum from fp32 inputs: colsum(V) = colsum(X) . Wv^T
    xsum_kernel<<<BB * CC / 256, blk>>>(x);
    vsumx_kernel<<<BB * CC / 8, blk>>>(qkvw);

    // q,k projection: single-pass bf16, 4-stage pipeline
    gemm1p_kernel<<<dim3(2048 / 128, M_ROWS / 128), blk, GEMM1P_SMEM>>>(
        xh, w1h, qkv, 3 * CC);
    // v projection: single-pass bf16 (colsum is exact; v only enters via delta)
    gemm1p_kernel<<<dim3(1024 / 128, M_ROWS / 128), blk, GEMM1P_SMEM>>>(
        xh, w1h + (size_t)2048 * CC, qkv + 2048, 3 * CC);

    norm_split_kernel<<<(M_ROWS * HH) / 8, blk>>>();

    attn_mma_kernel<<<dim3(NN / 128, BB * HH), blk, ATTN_SMEM_BYTES>>>(cls, um);

    // output projection + bias: bf16x3 (weight-1 path, keeps full precision)
    gemm3p_kernel<<<dim3(CC / 128, M_ROWS / 128), blk, GEMM3P_SMEM>>>(
        aoh, aol, w2h, w2l, projb, out, CC);
}

// round 8
// speedup vs baseline: 8.3744x; 1.2665x over previous
#include <cuda_runtime.h>
#include <cuda_bf16.h>
#include <math.h>

#define BB 2
#define NN 2048
#define CC 1024
#define HH 16
#define HD 64
#define M_ROWS (BB*NN)   // 4096

// ---------------- device scratch (allocation-free) ----------------
__device__ float g_qkv[M_ROWS * 3 * CC];              // fp32 qkv [bn][3C]
__device__ __nv_bfloat16 g_x_hi[M_ROWS * CC];
__device__ __nv_bfloat16 g_w1_hi[3 * CC * CC];
__device__ __nv_bfloat16 g_w2_hi[CC * CC];
// head-major [b*H+h][n][64] bf16
__device__ __nv_bfloat16 g_qn[BB * HH * NN * HD];
__device__ __nv_bfloat16 g_kn[BB * HH * NN * HD];
__device__ __nv_bfloat16 g_vh[BB * HH * NN * HD];
__device__ float g_xpart[16 * BB * CC];               // xsum partials
__device__ float g_xsum[BB * CC];                     // colsum of x (fp32 exact)
__device__ float g_vsum[BB * CC];                     // exact colsum of V
__device__ float g_vsumw[BB * CC];                    // vsum . W2^T (fp32 exact)
// attention deviation output (bf16) + per-row 1/l
__device__ __nv_bfloat16 g_dev[M_ROWS * CC];
__device__ float g_invl[M_ROWS];

// ---------------- elementwise kernels ----------------
__global__ __launch_bounds__(256) void tobf16_kernel(
    const float* __restrict__ in, __nv_bfloat16* __restrict__ out, int n)
{
    int i = blockIdx.x * blockDim.x + threadIdx.x;
    if (i < n) out[i] = __float2bfloat16(in[i]);
}

// xsum phase 1: 16 row-chunks of 128 rows each; grid (BB*CC/256, 16)
__global__ __launch_bounds__(256) void xsum_part_kernel(const float* __restrict__ x)
{
    int c = blockIdx.x * 256 + threadIdx.x;     // 0..2047 (b*1024+cc)
    int chunk = blockIdx.y;                      // 0..15
    int b = c >> 10, cc = c & 1023;
    const float* p = x + (size_t)b * NN * CC + (size_t)chunk * 128 * CC + cc;
    float s = 0.0f;
    #pragma unroll 8
    for (int n = 0; n < 128; ++n) s += p[(size_t)n * CC];
    g_xpart[chunk * (BB * CC) + c] = s;
}
// xsum phase 2: reduce 16 partials (fixed order -> deterministic)
__global__ __launch_bounds__(256) void xsum_final_kernel()
{
    int c = blockIdx.x * 256 + threadIdx.x;
    float s = 0.0f;
    #pragma unroll
    for (int t = 0; t < 16; ++t) s += g_xpart[t * (BB * CC) + c];
    g_xsum[c] = s;
}

// exact V colsum via GEMV: g_vsum[b*1024 + d] = xsum[b,:] . Wv[d,:]
__global__ __launch_bounds__(256) void vsumx_kernel(const float* __restrict__ w)
{
    int gw = (blockIdx.x * 256 + threadIdx.x) >> 5;   // 0..2047
    int lane = threadIdx.x & 31;
    int b = gw >> 10, dfull = gw & 1023;
    const float* wr = w + (size_t)(2048 + dfull) * CC;
    const float* xs = g_xsum + b * CC;
    float s = 0.0f;
    #pragma unroll 8
    for (int i = lane; i < CC; i += 32) s += xs[i] * wr[i];
    #pragma unroll
    for (int o = 16; o; o >>= 1) s += __shfl_xor_sync(0xffffffffu, s, o);
    if (lane == 0) g_vsum[b * CC + dfull] = s;
}

// g_vsumw[b*1024 + cout] = vsum[b,:] . W2[cout,:]   (fp32 exact GEMV)
__global__ __launch_bounds__(256) void vsumw_kernel(const float* __restrict__ w2)
{
    int gw = (blockIdx.x * 256 + threadIdx.x) >> 5;   // 0..2047
    int lane = threadIdx.x & 31;
    int b = gw >> 10, cout = gw & 1023;
    const float* wr = w2 + (size_t)cout * CC;
    const float* vs = g_vsum + b * CC;
    float s = 0.0f;
    #pragma unroll 8
    for (int i = lane; i < CC; i += 32) s += vs[i] * wr[i];
    #pragma unroll
    for (int o = 16; o; o >>= 1) s += __shfl_xor_sync(0xffffffffu, s, o);
    if (lane == 0) g_vsumw[b * CC + cout] = s;
}

// ---------------- mma helpers ----------------
__device__ __forceinline__ void ldsm4(unsigned r[4], const void* p) {
    unsigned a = (unsigned)__cvta_generic_to_shared(p);
    asm volatile("ldmatrix.sync.aligned.m8n8.x4.shared.b16 {%0,%1,%2,%3}, [%4];"
                 : "=r"(r[0]), "=r"(r[1]), "=r"(r[2]), "=r"(r[3]) : "r"(a));
}
__device__ __forceinline__ void ldsm4t(unsigned r[4], const void* p) {
    unsigned a = (unsigned)__cvta_generic_to_shared(p);
    asm volatile("ldmatrix.sync.aligned.m8n8.x4.trans.shared.b16 {%0,%1,%2,%3}, [%4];"
                 : "=r"(r[0]), "=r"(r[1]), "=r"(r[2]), "=r"(r[3]) : "r"(a));
}
__device__ __forceinline__ void mma16816(float c[4], const unsigned a[4],
                                         unsigned b0, unsigned b1) {
    asm volatile(
        "mma.sync.aligned.m16n8k16.row.col.f32.bf16.bf16.f32 "
        "{%0,%1,%2,%3}, {%4,%5,%6,%7}, {%8,%9}, {%0,%1,%2,%3};"
        : "+f"(c[0]), "+f"(c[1]), "+f"(c[2]), "+f"(c[3])
        : "r"(a[0]), "r"(a[1]), "r"(a[2]), "r"(a[3]), "r"(b0), "r"(b1));
}
__device__ __forceinline__ void cp16(void* smem, const void* gmem) {
    unsigned sa = (unsigned)__cvta_generic_to_shared(smem);
    asm volatile("cp.async.cg.shared.global [%0], [%1], 16;\n" :: "r"(sa), "l"(gmem));
}

#define GLDA 40
#define TILE_B (128 * GLDA * 2)   // 10240 B per 128x32 bf16 tile

// ---------------------------------------------------------------------------
// Single-pass bf16 GEMM (NT), 4-stage cp.async pipeline, 2 CTAs/SM.
// EPI=0: C = A B^T.   EPI=1: C = A B^T + invl[m]*vsumw[b][n] + bias[n].
// ---------------------------------------------------------------------------
template<int EPI>
__global__ __launch_bounds__(256, 2) void gemm1p_kernel(
    const __nv_bfloat16* __restrict__ A, const __nv_bfloat16* __restrict__ Bm,
    float* __restrict__ C, int Nn,
    const float* __restrict__ invl, const float* __restrict__ vsumw,
    const float* __restrict__ bias)
{
    extern __shared__ char sm_raw[];
    const int STAGE = 2 * TILE_B;
    int tid = threadIdx.x;
    int lane = tid & 31;
    int wid = tid >> 5;
    int warp_m = wid >> 2;
    int warp_n = wid & 3;
    int m0 = blockIdx.y * 128;
    int n0 = blockIdx.x * 128;

    float acc[4][4][4];
    #pragma unroll
    for (int mi = 0; mi < 4; ++mi)
        #pragma unroll
        for (int j = 0; j < 4; ++j)
            #pragma unroll
            for (int e = 0; e < 4; ++e) acc[mi][j][e] = 0.0f;

    auto load_stage = [&](int kt, int s) {
        char* sb = sm_raw + s * STAGE;
        int k0 = kt * 32;
        #pragma unroll
        for (int t = 0; t < 4; ++t) {
            int c = tid + t * 256;
            int arr = c >> 9;
            int r = (c >> 2) & 127;
            int c16 = c & 3;
            const __nv_bfloat16* g =
                (arr ? Bm : A) + (size_t)((arr ? n0 : m0) + r) * CC + k0 + c16 * 8;
            cp16(sb + arr * TILE_B + r * (GLDA * 2) + c16 * 16, g);
        }
    };

    const int KT = CC / 32;
    load_stage(0, 0); asm volatile("cp.async.commit_group;");
    load_stage(1, 1); asm volatile("cp.async.commit_group;");
    load_stage(2, 2); asm volatile("cp.async.commit_group;");

    for (int kt = 0; kt < KT; ++kt) {
        asm volatile("cp.async.wait_group 2;");
        __syncthreads();
        const char* As = sm_raw + (kt & 3) * STAGE;
        const char* Bs = As + TILE_B;

        #pragma unroll
        for (int ks = 0; ks < 32; ks += 16) {
            int coloff = ks + ((lane >> 4) << 3);
            unsigned ah[4][4];
            #pragma unroll
            for (int mi = 0; mi < 4; ++mi)
                ldsm4(ah[mi], As + (warp_m * 64 + mi * 16 + (lane & 15)) * (GLDA * 2)
                               + coloff * 2);
            unsigned bh[2][4];
            #pragma unroll
            for (int ni = 0; ni < 2; ++ni)
                ldsm4(bh[ni], Bs + (warp_n * 32 + ni * 16 + (lane & 15)) * (GLDA * 2)
                               + coloff * 2);
            #pragma unroll
            for (int mi = 0; mi < 4; ++mi)
                #pragma unroll
                for (int j = 0; j < 4; ++j) {
                    int ni = j >> 1, od = j & 1;
                    mma16816(acc[mi][j], ah[mi],
                             bh[ni][od ? 1 : 0], bh[ni][od ? 3 : 2]);
                }
        }
        if (kt + 3 < KT) {
            load_stage(kt + 3, (kt + 3) & 3);
            asm volatile("cp.async.commit_group;");
        }
    }

    int mb = m0 + warp_m * 64 + (lane >> 2);
    int nb = n0 + warp_n * 32 + 2 * (lane & 3);
    #pragma unroll
    for (int mi = 0; mi < 4; ++mi)
        #pragma unroll
        for (int j = 0; j < 4; ++j) {
            int col = nb + j * 8;
            int r0 = mb + mi * 16;
            float a0 = acc[mi][j][0], a1 = acc[mi][j][1];
            float a2 = acc[mi][j][2], a3 = acc[mi][j][3];
            if (EPI) {
                int b = r0 >> 11;            // rows 64-block aligned: same b for r0,r0+8
                float b0 = bias[col], b1 = bias[col + 1];
                float vw0 = vsumw[b * CC + col], vw1 = vsumw[b * CC + col + 1];
                float il0 = invl[r0], il8 = invl[r0 + 8];
                a0 += il0 * vw0 + b0;  a1 += il0 * vw1 + b1;
                a2 += il8 * vw0 + b0;  a3 += il8 * vw1 + b1;
            }
            *reinterpret_cast<float2*>(&C[(size_t)r0 * Nn + col]) =
                make_float2(a0, a1);
            *reinterpret_cast<float2*>(&C[(size_t)(r0 + 8) * Nn + col]) =
                make_float2(a2, a3);
        }
}

// ---------------------------------------------------------------------------
// Fused normalize + split (head-major outputs). V: single bf16.
// ---------------------------------------------------------------------------
__global__ __launch_bounds__(256) void norm_split_kernel()
{
    int gw   = (blockIdx.x * 256 + threadIdx.x) >> 5;
    int lane = threadIdx.x & 31;
    int bn = gw >> 4;
    int h  = gw & 15;
    int b = bn >> 11, n = bn & 2047;
    size_t src  = (size_t)bn * 3072 + h * 64;
    size_t dst  = ((size_t)(b * HH + h) * NN + n) * 64 + 2 * lane;

    float2 q = *reinterpret_cast<const float2*>(&g_qkv[src + 2 * lane]);
    float s = q.x * q.x + q.y * q.y;
    #pragma unroll
    for (int o = 16; o; o >>= 1) s += __shfl_xor_sync(0xffffffffu, s, o);
    float inv = 0.125f / (sqrtf(s) + 1e-8f);
    *reinterpret_cast<__nv_bfloat162*>(&g_qn[dst]) =
        __floats2bfloat162_rn(q.x * inv, q.y * inv);

    float2 k = *reinterpret_cast<const float2*>(&g_qkv[src + 1024 + 2 * lane]);
    s = k.x * k.x + k.y * k.y;
    #pragma unroll
    for (int o = 16; o; o >>= 1) s += __shfl_xor_sync(0xffffffffu, s, o);
    inv = 1.0f / (sqrtf(s) + 1e-8f);
    *reinterpret_cast<__nv_bfloat162*>(&g_kn[dst]) =
        __floats2bfloat162_rn(k.x * inv, k.y * inv);

    float2 v = *reinterpret_cast<const float2*>(&g_qkv[src + 2048 + 2 * lane]);
    *reinterpret_cast<__nv_bfloat162*>(&g_vh[dst]) =
        __floats2bfloat162_rn(v.x, v.y);
}

// ---------------------------------------------------------------------------
// Tensor-core attention with delta-trick. Epilogue writes dev = o/l (bf16)
// and 1/l per row; colsum correction folded into proj epilogue.
// ---------------------------------------------------------------------------
#define ATS 72
#define KTB (128 * ATS * 2)

__global__ __launch_bounds__(256, 2) void attn_mma_kernel(
    const float* __restrict__ cls, const int* __restrict__ um_p)
{
    extern __shared__ char smem[];
    float* sks = (float*)(smem + 4 * KTB);

    int tid = threadIdx.x;
    int lane = tid & 31;
    int warp = tid >> 5;
    int q0 = blockIdx.x * 128;
    int bh = blockIdx.y;
    int b = bh >> 4, h = bh & 15;
    int um = um_p[0];
    int r = lane >> 2;
    int c2 = 2 * (lane & 3);

    const __nv_bfloat16* qg = g_qn + ((size_t)bh * NN + q0 + warp * 16) * 64;
    unsigned qa[4][4];
    #pragma unroll
    for (int dc = 0; dc < 4; ++dc) {
        qa[dc][0] = *(const unsigned*)(qg + (size_t)r * 64 + 16 * dc + c2);
        qa[dc][1] = *(const unsigned*)(qg + (size_t)(r + 8) * 64 + 16 * dc + c2);
        qa[dc][2] = *(const unsigned*)(qg + (size_t)r * 64 + 16 * dc + 8 + c2);
        qa[dc][3] = *(const unsigned*)(qg + (size_t)(r + 8) * 64 + 16 * dc + 8 + c2);
    }
    float sq0 = cls[q0 + warp * 16 + r] - 0.1f;
    float sq8 = cls[q0 + warp * 16 + r + 8] - 0.1f;

    const __nv_bfloat16* kg  = g_kn + (size_t)bh * NN * 64;
    const __nv_bfloat16* vhg = g_vh + (size_t)bh * NN * 64;

    float o[8][4];
    #pragma unroll
    for (int i = 0; i < 8; ++i)
        #pragma unroll
        for (int e = 0; e < 4; ++e) o[i][e] = 0.0f;
    float l0 = 0.0f, l8 = 0.0f;

    auto stage_load = [&](int kt, int s) {
        #pragma unroll
        for (int t = 0; t < 8; ++t) {
            int cix = tid + t * 256;
            int arr = cix >> 10;
            int rr  = (cix >> 3) & 127;
            int seg = cix & 7;
            const __nv_bfloat16* gb = (arr == 0) ? kg : vhg;
            const __nv_bfloat16* g = gb + ((size_t)(kt * 128 + rr)) * 64 + seg * 8;
            cp16(smem + arr * 2 * KTB + s * KTB + rr * (ATS * 2) + seg * 16, g);
        }
        if (tid < 128) sks[s * 128 + tid] = cls[kt * 128 + tid];
    };

    stage_load(0, 0);
    asm volatile("cp.async.commit_group;");

    for (int kt = 0; kt < NN / 128; ++kt) {
        asm volatile("cp.async.wait_group 0;");
        __syncthreads();
        if (kt + 1 < NN / 128) {
            stage_load(kt + 1, (kt + 1) & 1);
            asm volatile("cp.async.commit_group;");
        }
        int s = kt & 1;
        const char* Kb  = smem + s * KTB;
        const char* Vhb = smem + 2 * KTB + s * KTB;
        const float* sk = sks + s * 128;

        #pragma unroll
        for (int j = 0; j < 8; ++j) {
            float cc[2][4] = {{0, 0, 0, 0}, {0, 0, 0, 0}};
            int krow = 16 * j + (lane & 15);
            #pragma unroll
            for (int dc = 0; dc < 4; ++dc) {
                unsigned kb[4];
                ldsm4(kb, Kb + krow * (ATS * 2) + (16 * dc + ((lane >> 4) << 3)) * 2);
                mma16816(cc[0], qa[dc], kb[0], kb[2]);
                mma16816(cc[1], qa[dc], kb[1], kb[3]);
            }
            unsigned ad[4];
            #pragma unroll
            for (int t = 0; t < 2; ++t) {
                float2 skv = *reinterpret_cast<const float2*>(&sk[16 * j + 8 * t + c2]);
                float fx0 = (um && !(skv.x > sq0)) ? 0.f : skv.x;
                float fy0 = (um && !(skv.y > sq0)) ? 0.f : skv.y;
                float fx8 = (um && !(skv.x > sq8)) ? 0.f : skv.x;
                float fy8 = (um && !(skv.y > sq8)) ? 0.f : skv.y;
                float p00 = __expf(cc[t][0] * fx0);
                float p01 = __expf(cc[t][1] * fy0);
                float p80 = __expf(cc[t][2] * fx8);
                float p81 = __expf(cc[t][3] * fy8);
                l0 += p00 + p01;
                l8 += p80 + p81;
                __nv_bfloat162 D0 = __floats2bfloat162_rn(p00 - 1.0f, p01 - 1.0f);
                __nv_bfloat162 D8 = __floats2bfloat162_rn(p80 - 1.0f, p81 - 1.0f);
                ad[2 * t]     = *reinterpret_cast<unsigned*>(&D0);
                ad[2 * t + 1] = *reinterpret_cast<unsigned*>(&D8);
            }
            #pragma unroll
            for (int n2 = 0; n2 < 4; ++n2) {
                unsigned vb[4];
                int voff = krow * (ATS * 2) + (16 * n2 + ((lane >> 4) << 3)) * 2;
                ldsm4t(vb, Vhb + voff);
                mma16816(o[2 * n2],     ad, vb[0], vb[1]);
                mma16816(o[2 * n2 + 1], ad, vb[2], vb[3]);
            }
        }
    }

    l0 += __shfl_xor_sync(0xffffffffu, l0, 1);
    l0 += __shfl_xor_sync(0xffffffffu, l0, 2);
    l8 += __shfl_xor_sync(0xffffffffu, l8, 1);
    l8 += __shfl_xor_sync(0xffffffffu, l8, 2);
    float inv0 = 1.0f / l0, inv8 = 1.0f / l8;

    size_t tok0 = (size_t)(b * NN + q0 + warp * 16 + r);
    if ((lane & 3) == 0) {
        g_invl[tok0] = inv0;
        g_invl[tok0 + 8] = inv8;
    }
    size_t row0 = tok0 * CC + h * 64;
    size_t row8 = (tok0 + 8) * CC + h * 64;
    #pragma unroll
    for (int nt = 0; nt < 8; ++nt) {
        int d = 8 * nt + c2;
        *reinterpret_cast<__nv_bfloat162*>(&g_dev[row0 + d]) =
            __floats2bfloat162_rn(o[nt][0] * inv0, o[nt][1] * inv0);
        *reinterpret_cast<__nv_bfloat162*>(&g_dev[row8 + d]) =
            __floats2bfloat162_rn(o[nt][2] * inv8, o[nt][3] * inv8);
    }
}

// ---------------------------------------------------------------------------
// Launch
// ---------------------------------------------------------------------------
static const int GEMM1P_SMEM = 4 * 2 * TILE_B;   // 81920 (4 stages)
static const int ATTN_SMEM_BYTES = 4 * KTB + 2 * 128 * (int)sizeof(float); // 74752

extern "C" void kernel_launch(void* const* d_in, const int* in_sizes, int n_in,
                              void* d_out, int out_size)
{
    const float* x     = (const float*)d_in[0];
    const float* cls   = (const float*)d_in[1];
    const float* qkvw  = (const float*)d_in[2];
    const float* projw = (const float*)d_in[3];
    const float* projb = (const float*)d_in[4];
    const int*   um    = (const int*)d_in[5];
    float* out = (float*)d_out;

    float* qkv = nullptr;
    float *invl, *vsumw;
    __nv_bfloat16 *xh, *w1h, *w2h, *dev;
    cudaGetSymbolAddress((void**)&qkv,   g_qkv);
    cudaGetSymbolAddress((void**)&xh,    g_x_hi);
    cudaGetSymbolAddress((void**)&w1h,   g_w1_hi);
    cudaGetSymbolAddress((void**)&w2h,   g_w2_hi);
    cudaGetSymbolAddress((void**)&dev,   g_dev);
    cudaGetSymbolAddress((void**)&invl,  g_invl);
    cudaGetSymbolAddress((void**)&vsumw, g_vsumw);

    cudaFuncSetAttribute(gemm1p_kernel<0>,
                         cudaFuncAttributeMaxDynamicSharedMemorySize, GEMM1P_SMEM);
    cudaFuncSetAttribute(gemm1p_kernel<1>,
                         cudaFuncAttributeMaxDynamicSharedMemorySize, GEMM1P_SMEM);
    cudaFuncSetAttribute(attn_mma_kernel,
                         cudaFuncAttributeMaxDynamicSharedMemorySize, ATTN_SMEM_BYTES);

    dim3 blk(256);

    // converts
    tobf16_kernel<<<(M_ROWS * CC + 255) / 256, blk>>>(x, xh, M_ROWS * CC);
    tobf16_kernel<<<(3 * CC * CC + 255) / 256, blk>>>(qkvw, w1h, 3 * CC * CC);
    tobf16_kernel<<<(CC * CC + 255) / 256, blk>>>(projw, w2h, CC * CC);

    // exact colsum chain: xsum -> vsum = xsum.Wv^T -> vsumw = vsum.W2^T
    xsum_part_kernel<<<dim3(BB * CC / 256, 16), blk>>>(x);
    xsum_final_kernel<<<BB * CC / 256, blk>>>();
    vsumx_kernel<<<BB * CC / 8, blk>>>(qkvw);
    vsumw_kernel<<<BB * CC / 8, blk>>>(projw);

    // q,k projection: single-pass bf16, 4-stage pipeline
    gemm1p_kernel<0><<<dim3(2048 / 128, M_ROWS / 128), blk, GEMM1P_SMEM>>>(
        xh, w1h, qkv, 3 * CC, nullptr, nullptr, nullptr);
    // v projection: single-pass bf16
    gemm1p_kernel<0><<<dim3(1024 / 128, M_ROWS / 128), blk, GEMM1P_SMEM>>>(
        xh, w1h + (size_t)2048 * CC, qkv + 2048, 3 * CC, nullptr, nullptr, nullptr);

    norm_split_kernel<<<(M_ROWS * HH) / 8, blk>>>();

    attn_mma_kernel<<<dim3(NN / 128, BB * HH), blk, ATTN_SMEM_BYTES>>>(cls, um);

    // output projection: out = dev.W2^T + invl*vsumw + bias  (single pass bf16)
    gemm1p_kernel<1><<<dim3(CC / 128, M_ROWS / 128), blk, GEMM1P_SMEM>>>(
        dev, w2h, out, CC, invl, vsumw, projb);
}

// round 11
// speedup vs baseline: 8.8244x; 1.0537x over previous
#include <cuda_runtime.h>
#include <cuda_bf16.h>
#include <stdint.h>
#include <math.h>

#define BB 2
#define NN 2048
#define CC 1024
#define HH 16
#define HD 64
#define M_ROWS (BB*NN)   // 4096

// ---------------- device scratch (allocation-free) ----------------
__device__ float g_qkv[M_ROWS * 3 * CC];              // fp32 qkv [bn][3C]
__device__ __nv_bfloat16 g_x_hi[M_ROWS * CC];
__device__ __nv_bfloat16 g_w1_hi[3 * CC * CC];
__device__ __nv_bfloat16 g_w2_hi[CC * CC];
// head-major [b*H+h][n][64] bf16
__device__ __nv_bfloat16 g_qn[BB * HH * NN * HD];
__device__ __nv_bfloat16 g_kn[BB * HH * NN * HD];
__device__ __nv_bfloat16 g_vh[BB * HH * NN * HD];
__device__ float g_xpart[64 * BB * CC];               // xsum partials
__device__ float g_xsum[BB * CC];
__device__ float g_vsum[BB * CC];                     // exact colsum of V
__device__ float g_vsumw[BB * CC];                    // vsum . W2^T
// attention deviation output (bf16) + per-row 1/l
__device__ __nv_bfloat16 g_dev[M_ROWS * CC];
__device__ float g_invl[M_ROWS];

// ---------------- elementwise / reduction kernels ----------------
__global__ __launch_bounds__(256) void tobf16_kernel(
    const float* __restrict__ in, __nv_bfloat16* __restrict__ out, int n)
{
    int i = blockIdx.x * blockDim.x + threadIdx.x;
    if (i < n) out[i] = __float2bfloat16(in[i]);
}

// Fused: x -> bf16 copy + column-sum partials.
// grid (BB*CC/256, 64); block handles 32 rows x 256 cols.
__global__ __launch_bounds__(256) void xcvt_sum_kernel(const float* __restrict__ x)
{
    int c = blockIdx.x * 256 + threadIdx.x;     // 0..2047 (b*1024+cc)
    int chunk = blockIdx.y;                      // 0..63
    int b = c >> 10, cc = c & 1023;
    size_t base = (size_t)b * NN * CC + (size_t)chunk * 32 * CC + cc;
    float s = 0.0f;
    #pragma unroll 8
    for (int n = 0; n < 32; ++n) {
        float v = x[base + (size_t)n * CC];
        g_x_hi[base + (size_t)n * CC] = __float2bfloat16(v);
        s += v;
    }
    g_xpart[chunk * (BB * CC) + c] = s;
}
__global__ __launch_bounds__(256) void xsum_final_kernel()
{
    int c = blockIdx.x * 256 + threadIdx.x;
    float s = 0.0f;
    #pragma unroll
    for (int t = 0; t < 64; ++t) s += g_xpart[t * (BB * CC) + c];
    g_xsum[c] = s;
}

__global__ __launch_bounds__(256) void vsumx_kernel(const float* __restrict__ w)
{
    int gw = (blockIdx.x * 256 + threadIdx.x) >> 5;
    int lane = threadIdx.x & 31;
    int b = gw >> 10, dfull = gw & 1023;
    const float* wr = w + (size_t)(2048 + dfull) * CC;
    const float* xs = g_xsum + b * CC;
    float s = 0.0f;
    #pragma unroll 8
    for (int i = lane; i < CC; i += 32) s += xs[i] * wr[i];
    #pragma unroll
    for (int o = 16; o; o >>= 1) s += __shfl_xor_sync(0xffffffffu, s, o);
    if (lane == 0) g_vsum[b * CC + dfull] = s;
}

__global__ __launch_bounds__(256) void vsumw_kernel(const float* __restrict__ w2)
{
    int gw = (blockIdx.x * 256 + threadIdx.x) >> 5;
    int lane = threadIdx.x & 31;
    int b = gw >> 10, cout = gw & 1023;
    const float* wr = w2 + (size_t)cout * CC;
    const float* vs = g_vsum + b * CC;
    float s = 0.0f;
    #pragma unroll 8
    for (int i = lane; i < CC; i += 32) s += vs[i] * wr[i];
    #pragma unroll
    for (int o = 16; o; o >>= 1) s += __shfl_xor_sync(0xffffffffu, s, o);
    if (lane == 0) g_vsumw[b * CC + cout] = s;
}

// ---------------- mma helpers ----------------
__device__ __forceinline__ unsigned smem_u32(const void* p) {
    return (unsigned)__cvta_generic_to_shared(p);
}
__device__ __forceinline__ void cp16(void* smem, const void* gmem) {
    unsigned sa = smem_u32(smem);
    asm volatile("cp.async.cg.shared.global [%0], [%1], 16;\n" :: "r"(sa), "l"(gmem));
}
__device__ __forceinline__ void ldsm4(unsigned r[4], const void* p) {
    unsigned a = smem_u32(p);
    asm volatile("ldmatrix.sync.aligned.m8n8.x4.shared.b16 {%0,%1,%2,%3}, [%4];"
                 : "=r"(r[0]), "=r"(r[1]), "=r"(r[2]), "=r"(r[3]) : "r"(a));
}
__device__ __forceinline__ void ldsm4t(unsigned r[4], const void* p) {
    unsigned a = smem_u32(p);
    asm volatile("ldmatrix.sync.aligned.m8n8.x4.trans.shared.b16 {%0,%1,%2,%3}, [%4];"
                 : "=r"(r[0]), "=r"(r[1]), "=r"(r[2]), "=r"(r[3]) : "r"(a));
}
__device__ __forceinline__ void mma16816(float c[4], const unsigned a[4],
                                         unsigned b0, unsigned b1) {
    asm volatile(
        "mma.sync.aligned.m16n8k16.row.col.f32.bf16.bf16.f32 "
        "{%0,%1,%2,%3}, {%4,%5,%6,%7}, {%8,%9}, {%0,%1,%2,%3};"
        : "+f"(c[0]), "+f"(c[1]), "+f"(c[2]), "+f"(c[3])
        : "r"(a[0]), "r"(a[1]), "r"(a[2]), "r"(a[3]), "r"(b0), "r"(b1));
}

#define GLDA 40
#define TILE_B (128 * GLDA * 2)   // 10240 B per 128x32 bf16 tile

// ---------------------------------------------------------------------------
// Single-pass bf16 GEMM (NT), 4-stage cp.async pipeline, 2 CTAs/SM.
// EPI=0: C = A B^T.   EPI=1: C = A B^T + invl[m]*vsumw[b][n] + bias[n].
// ---------------------------------------------------------------------------
template<int EPI>
__global__ __launch_bounds__(256, 2) void gemm1p_kernel(
    const __nv_bfloat16* __restrict__ A, const __nv_bfloat16* __restrict__ Bm,
    float* __restrict__ C, int Nn,
    const float* __restrict__ invl, const float* __restrict__ vsumw,
    const float* __restrict__ bias)
{
    extern __shared__ char sm_raw[];
    const int STAGE = 2 * TILE_B;
    int tid = threadIdx.x;
    int lane = tid & 31;
    int wid = tid >> 5;
    int warp_m = wid >> 2;
    int warp_n = wid & 3;
    int m0 = blockIdx.y * 128;
    int n0 = blockIdx.x * 128;

    float acc[4][4][4];
    #pragma unroll
    for (int mi = 0; mi < 4; ++mi)
        #pragma unroll
        for (int j = 0; j < 4; ++j)
            #pragma unroll
            for (int e = 0; e < 4; ++e) acc[mi][j][e] = 0.0f;

    auto load_stage = [&](int kt, int s) {
        char* sb = sm_raw + s * STAGE;
        int k0 = kt * 32;
        #pragma unroll
        for (int t = 0; t < 4; ++t) {
            int c = tid + t * 256;
            int arr = c >> 9;
            int r = (c >> 2) & 127;
            int c16 = c & 3;
            const __nv_bfloat16* g =
                (arr ? Bm : A) + (size_t)((arr ? n0 : m0) + r) * CC + k0 + c16 * 8;
            cp16(sb + arr * TILE_B + r * (GLDA * 2) + c16 * 16, g);
        }
    };

    const int KT = CC / 32;
    load_stage(0, 0); asm volatile("cp.async.commit_group;");
    load_stage(1, 1); asm volatile("cp.async.commit_group;");
    load_stage(2, 2); asm volatile("cp.async.commit_group;");

    for (int kt = 0; kt < KT; ++kt) {
        asm volatile("cp.async.wait_group 2;");
        __syncthreads();
        const char* As = sm_raw + (kt & 3) * STAGE;
        const char* Bs = As + TILE_B;

        #pragma unroll
        for (int ks = 0; ks < 32; ks += 16) {
            int coloff = ks + ((lane >> 4) << 3);
            unsigned ah[4][4];
            #pragma unroll
            for (int mi = 0; mi < 4; ++mi)
                ldsm4(ah[mi], As + (warp_m * 64 + mi * 16 + (lane & 15)) * (GLDA * 2)
                               + coloff * 2);
            unsigned bh[2][4];
            #pragma unroll
            for (int ni = 0; ni < 2; ++ni)
                ldsm4(bh[ni], Bs + (warp_n * 32 + ni * 16 + (lane & 15)) * (GLDA * 2)
                               + coloff * 2);
            #pragma unroll
            for (int mi = 0; mi < 4; ++mi)
                #pragma unroll
                for (int j = 0; j < 4; ++j) {
                    int ni = j >> 1, od = j & 1;
                    mma16816(acc[mi][j], ah[mi],
                             bh[ni][od ? 1 : 0], bh[ni][od ? 3 : 2]);
                }
        }
        if (kt + 3 < KT) {
            load_stage(kt + 3, (kt + 3) & 3);
            asm volatile("cp.async.commit_group;");
        }
    }

    int mb = m0 + warp_m * 64 + (lane >> 2);
    int nb = n0 + warp_n * 32 + 2 * (lane & 3);
    #pragma unroll
    for (int mi = 0; mi < 4; ++mi)
        #pragma unroll
        for (int j = 0; j < 4; ++j) {
            int col = nb + j * 8;
            int r0 = mb + mi * 16;
            float a0 = acc[mi][j][0], a1 = acc[mi][j][1];
            float a2 = acc[mi][j][2], a3 = acc[mi][j][3];
            if (EPI) {
                int b = r0 >> 11;
                float b0 = bias[col], b1 = bias[col + 1];
                float vw0 = vsumw[b * CC + col], vw1 = vsumw[b * CC + col + 1];
                float il0 = invl[r0], il8 = invl[r0 + 8];
                a0 += il0 * vw0 + b0;  a1 += il0 * vw1 + b1;
                a2 += il8 * vw0 + b0;  a3 += il8 * vw1 + b1;
            }
            *reinterpret_cast<float2*>(&C[(size_t)r0 * Nn + col]) =
                make_float2(a0, a1);
            *reinterpret_cast<float2*>(&C[(size_t)(r0 + 8) * Nn + col]) =
                make_float2(a2, a3);
        }
}

// ---------------------------------------------------------------------------
// Fused normalize + split (head-major outputs). Unchanged (verified).
// ---------------------------------------------------------------------------
__global__ __launch_bounds__(256) void norm_split_kernel()
{
    int gw   = (blockIdx.x * 256 + threadIdx.x) >> 5;
    int lane = threadIdx.x & 31;
    int bn = gw >> 4;
    int h  = gw & 15;
    int b = bn >> 11, n = bn & 2047;
    size_t src  = (size_t)bn * 3072 + h * 64;
    size_t dst  = ((size_t)(b * HH + h) * NN + n) * 64 + 2 * lane;

    float2 q = *reinterpret_cast<const float2*>(&g_qkv[src + 2 * lane]);
    float s = q.x * q.x + q.y * q.y;
    #pragma unroll
    for (int o = 16; o; o >>= 1) s += __shfl_xor_sync(0xffffffffu, s, o);
    float inv = 0.125f / (sqrtf(s) + 1e-8f);
    *reinterpret_cast<__nv_bfloat162*>(&g_qn[dst]) =
        __floats2bfloat162_rn(q.x * inv, q.y * inv);

    float2 k = *reinterpret_cast<const float2*>(&g_qkv[src + 1024 + 2 * lane]);
    s = k.x * k.x + k.y * k.y;
    #pragma unroll
    for (int o = 16; o; o >>= 1) s += __shfl_xor_sync(0xffffffffu, s, o);
    inv = 1.0f / (sqrtf(s) + 1e-8f);
    *reinterpret_cast<__nv_bfloat162*>(&g_kn[dst]) =
        __floats2bfloat162_rn(k.x * inv, k.y * inv);

    float2 v = *reinterpret_cast<const float2*>(&g_qkv[src + 2048 + 2 * lane]);
    *reinterpret_cast<__nv_bfloat162*>(&g_vh[dst]) =
        __floats2bfloat162_rn(v.x, v.y);
}

// ---------------------------------------------------------------------------
// Tensor-core attention with delta-trick (unchanged R8, verified).
// ---------------------------------------------------------------------------
#define ATS 72
#define KTB (128 * ATS * 2)

__global__ __launch_bounds__(256, 2) void attn_mma_kernel(
    const float* __restrict__ cls, const int* __restrict__ um_p)
{
    extern __shared__ char smem[];
    float* sks = (float*)(smem + 4 * KTB);

    int tid = threadIdx.x;
    int lane = tid & 31;
    int warp = tid >> 5;
    int q0 = blockIdx.x * 128;
    int bh = blockIdx.y;
    int b = bh >> 4, h = bh & 15;
    int um = um_p[0];
    int r = lane >> 2;
    int c2 = 2 * (lane & 3);

    const __nv_bfloat16* qg = g_qn + ((size_t)bh * NN + q0 + warp * 16) * 64;
    unsigned qa[4][4];
    #pragma unroll
    for (int dc = 0; dc < 4; ++dc) {
        qa[dc][0] = *(const unsigned*)(qg + (size_t)r * 64 + 16 * dc + c2);
        qa[dc][1] = *(const unsigned*)(qg + (size_t)(r + 8) * 64 + 16 * dc + c2);
        qa[dc][2] = *(const unsigned*)(qg + (size_t)r * 64 + 16 * dc + 8 + c2);
        qa[dc][3] = *(const unsigned*)(qg + (size_t)(r + 8) * 64 + 16 * dc + 8 + c2);
    }
    float sq0 = cls[q0 + warp * 16 + r] - 0.1f;
    float sq8 = cls[q0 + warp * 16 + r + 8] - 0.1f;

    const __nv_bfloat16* kg  = g_kn + (size_t)bh * NN * 64;
    const __nv_bfloat16* vhg = g_vh + (size_t)bh * NN * 64;

    float o[8][4];
    #pragma unroll
    for (int i = 0; i < 8; ++i)
        #pragma unroll
        for (int e = 0; e < 4; ++e) o[i][e] = 0.0f;
    float l0 = 0.0f, l8 = 0.0f;

    auto stage_load = [&](int kt, int s) {
        #pragma unroll
        for (int t = 0; t < 8; ++t) {
            int cix = tid + t * 256;
            int arr = cix >> 10;
            int rr  = (cix >> 3) & 127;
            int seg = cix & 7;
            const __nv_bfloat16* gb = (arr == 0) ? kg : vhg;
            const __nv_bfloat16* g = gb + ((size_t)(kt * 128 + rr)) * 64 + seg * 8;
            cp16(smem + arr * 2 * KTB + s * KTB + rr * (ATS * 2) + seg * 16, g);
        }
        if (tid < 128) sks[s * 128 + tid] = cls[kt * 128 + tid];
    };

    stage_load(0, 0);
    asm volatile("cp.async.commit_group;");

    for (int kt = 0; kt < NN / 128; ++kt) {
        asm volatile("cp.async.wait_group 0;");
        __syncthreads();
        if (kt + 1 < NN / 128) {
            stage_load(kt + 1, (kt + 1) & 1);
            asm volatile("cp.async.commit_group;");
        }
        int s = kt & 1;
        const char* Kb  = smem + s * KTB;
        const char* Vhb = smem + 2 * KTB + s * KTB;
        const float* sk = sks + s * 128;

        #pragma unroll
        for (int j = 0; j < 8; ++j) {
            float cc[2][4] = {{0, 0, 0, 0}, {0, 0, 0, 0}};
            int krow = 16 * j + (lane & 15);
            #pragma unroll
            for (int dc = 0; dc < 4; ++dc) {
                unsigned kb[4];
                ldsm4(kb, Kb + krow * (ATS * 2) + (16 * dc + ((lane >> 4) << 3)) * 2);
                mma16816(cc[0], qa[dc], kb[0], kb[2]);
                mma16816(cc[1], qa[dc], kb[1], kb[3]);
            }
            unsigned ad[4];
            #pragma unroll
            for (int t = 0; t < 2; ++t) {
                float2 skv = *reinterpret_cast<const float2*>(&sk[16 * j + 8 * t + c2]);
                float fx0 = (um && !(skv.x > sq0)) ? 0.f : skv.x;
                float fy0 = (um && !(skv.y > sq0)) ? 0.f : skv.y;
                float fx8 = (um && !(skv.x > sq8)) ? 0.f : skv.x;
                float fy8 = (um && !(skv.y > sq8)) ? 0.f : skv.y;
                float p00 = __expf(cc[t][0] * fx0);
                float p01 = __expf(cc[t][1] * fy0);
                float p80 = __expf(cc[t][2] * fx8);
                float p81 = __expf(cc[t][3] * fy8);
                l0 += p00 + p01;
                l8 += p80 + p81;
                __nv_bfloat162 D0 = __floats2bfloat162_rn(p00 - 1.0f, p01 - 1.0f);
                __nv_bfloat162 D8 = __floats2bfloat162_rn(p80 - 1.0f, p81 - 1.0f);
                ad[2 * t]     = *reinterpret_cast<unsigned*>(&D0);
                ad[2 * t + 1] = *reinterpret_cast<unsigned*>(&D8);
            }
            #pragma unroll
            for (int n2 = 0; n2 < 4; ++n2) {
                unsigned vb[4];
                int voff = krow * (ATS * 2) + (16 * n2 + ((lane >> 4) << 3)) * 2;
                ldsm4t(vb, Vhb + voff);
                mma16816(o[2 * n2],     ad, vb[0], vb[1]);
                mma16816(o[2 * n2 + 1], ad, vb[2], vb[3]);
            }
        }
    }

    l0 += __shfl_xor_sync(0xffffffffu, l0, 1);
    l0 += __shfl_xor_sync(0xffffffffu, l0, 2);
    l8 += __shfl_xor_sync(0xffffffffu, l8, 1);
    l8 += __shfl_xor_sync(0xffffffffu, l8, 2);
    float inv0 = 1.0f / l0, inv8 = 1.0f / l8;

    size_t tok0 = (size_t)(b * NN + q0 + warp * 16 + r);
    if ((lane & 3) == 0) {
        g_invl[tok0] = inv0;
        g_invl[tok0 + 8] = inv8;
    }
    size_t row0 = tok0 * CC + h * 64;
    size_t row8 = (tok0 + 8) * CC + h * 64;
    #pragma unroll
    for (int nt = 0; nt < 8; ++nt) {
        int d = 8 * nt + c2;
        *reinterpret_cast<__nv_bfloat162*>(&g_dev[row0 + d]) =
            __floats2bfloat162_rn(o[nt][0] * inv0, o[nt][1] * inv0);
        *reinterpret_cast<__nv_bfloat162*>(&g_dev[row8 + d]) =
            __floats2bfloat162_rn(o[nt][2] * inv8, o[nt][3] * inv8);
    }
}

// ---------------------------------------------------------------------------
// Launch
// ---------------------------------------------------------------------------
static const int GEMM1P_SMEM = 4 * 2 * TILE_B;   // 81920 (4 stages)
static const int ATTN_SMEM_BYTES = 4 * KTB + 2 * 128 * (int)sizeof(float);

extern "C" void kernel_launch(void* const* d_in, const int* in_sizes, int n_in,
                              void* d_out, int out_size)
{
    const float* x     = (const float*)d_in[0];
    const float* cls   = (const float*)d_in[1];
    const float* qkvw  = (const float*)d_in[2];
    const float* projw = (const float*)d_in[3];
    const float* projb = (const float*)d_in[4];
    const int*   um    = (const int*)d_in[5];
    float* out = (float*)d_out;

    float* qkv = nullptr;
    float *invl, *vsumw;
    __nv_bfloat16 *xh, *w1h, *w2h, *dev;
    cudaGetSymbolAddress((void**)&qkv,   g_qkv);
    cudaGetSymbolAddress((void**)&xh,    g_x_hi);
    cudaGetSymbolAddress((void**)&w1h,   g_w1_hi);
    cudaGetSymbolAddress((void**)&w2h,   g_w2_hi);
    cudaGetSymbolAddress((void**)&dev,   g_dev);
    cudaGetSymbolAddress((void**)&invl,  g_invl);
    cudaGetSymbolAddress((void**)&vsumw, g_vsumw);

    cudaFuncSetAttribute(gemm1p_kernel<0>,
                         cudaFuncAttributeMaxDynamicSharedMemorySize, GEMM1P_SMEM);
    cudaFuncSetAttribute(gemm1p_kernel<1>,
                         cudaFuncAttributeMaxDynamicSharedMemorySize, GEMM1P_SMEM);
    cudaFuncSetAttribute(attn_mma_kernel,
                         cudaFuncAttributeMaxDynamicSharedMemorySize, ATTN_SMEM_BYTES);

    dim3 blk(256);

    // fused x convert + colsum partials; weight converts
    xcvt_sum_kernel<<<dim3(BB * CC / 256, 64), blk>>>(x);
    tobf16_kernel<<<(3 * CC * CC + 255) / 256, blk>>>(qkvw, w1h, 3 * CC * CC);
    tobf16_kernel<<<(CC * CC + 255) / 256, blk>>>(projw, w2h, CC * CC);

    // exact colsum chain
    xsum_final_kernel<<<BB * CC / 256, blk>>>();
    vsumx_kernel<<<BB * CC / 8, blk>>>(qkvw);
    vsumw_kernel<<<BB * CC / 8, blk>>>(projw);

    // full qkv projection: single-pass bf16, one launch (N=3072)
    gemm1p_kernel<0><<<dim3(3 * CC / 128, M_ROWS / 128), blk, GEMM1P_SMEM>>>(
        xh, w1h, qkv, 3 * CC, nullptr, nullptr, nullptr);

    norm_split_kernel<<<(M_ROWS * HH) / 8, blk>>>();

    attn_mma_kernel<<<dim3(NN / 128, BB * HH), blk, ATTN_SMEM_BYTES>>>(cls, um);

    // output projection: out = dev.W2^T + invl*vsumw + bias
    gemm1p_kernel<1><<<dim3(CC / 128, M_ROWS / 128), blk, GEMM1P_SMEM>>>(
        dev, w2h, out, CC, invl, vsumw, projb);
}

// round 12
// speedup vs baseline: 8.9536x; 1.0146x over previous
#include <cuda_runtime.h>
#include <cuda_bf16.h>
#include <stdint.h>
#include <math.h>

#define BB 2
#define NN 2048
#define CC 1024
#define HH 16
#define HD 64
#define M_ROWS (BB*NN)   // 4096
#define LOG2E 1.4426950408889634f

// ---------------- device scratch (allocation-free) ----------------
__device__ float g_qkv[M_ROWS * 3 * CC];              // fp32 qkv [bn][3C]
__device__ __nv_bfloat16 g_x_hi[M_ROWS * CC];
__device__ __nv_bfloat16 g_w1_hi[3 * CC * CC];
__device__ __nv_bfloat16 g_w2_hi[CC * CC];
// head-major [b*H+h][sorted n][64] bf16
__device__ __nv_bfloat16 g_qn[BB * HH * NN * HD];
__device__ __nv_bfloat16 g_kn[BB * HH * NN * HD];
__device__ __nv_bfloat16 g_vh[BB * HH * NN * HD];
__device__ float g_xpart[64 * BB * CC];               // xsum partials
__device__ float g_xsum[BB * CC];
__device__ float g_vsum[BB * CC];                     // exact colsum of V
__device__ float g_vsumw[BB * CC];                    // vsum . W2^T
// score sort
__device__ float g_ssort[NN];                         // scores sorted desc
__device__ int   g_perm[NN];                          // sorted pos -> orig token
__device__ int   g_inv[NN];                           // orig token -> sorted pos
// attention deviation output (bf16) + per-row 1/l
__device__ __nv_bfloat16 g_dev[M_ROWS * CC];
__device__ float g_invl[M_ROWS];

// ---------------- elementwise / reduction kernels ----------------
__global__ __launch_bounds__(256) void tobf16_kernel(
    const float* __restrict__ in, __nv_bfloat16* __restrict__ out, int n)
{
    int i = blockIdx.x * blockDim.x + threadIdx.x;
    if (i < n) out[i] = __float2bfloat16(in[i]);
}

// Fused: x -> bf16 copy + column-sum partials.
__global__ __launch_bounds__(256) void xcvt_sum_kernel(const float* __restrict__ x)
{
    int c = blockIdx.x * 256 + threadIdx.x;
    int chunk = blockIdx.y;
    int b = c >> 10, cc = c & 1023;
    size_t base = (size_t)b * NN * CC + (size_t)chunk * 32 * CC + cc;
    float s = 0.0f;
    #pragma unroll 8
    for (int n = 0; n < 32; ++n) {
        float v = x[base + (size_t)n * CC];
        g_x_hi[base + (size_t)n * CC] = __float2bfloat16(v);
        s += v;
    }
    g_xpart[chunk * (BB * CC) + c] = s;
}
__global__ __launch_bounds__(256) void xsum_final_kernel()
{
    int c = blockIdx.x * 256 + threadIdx.x;
    float s = 0.0f;
    #pragma unroll
    for (int t = 0; t < 64; ++t) s += g_xpart[t * (BB * CC) + c];
    g_xsum[c] = s;
}

__global__ __launch_bounds__(256) void vsumx_kernel(const float* __restrict__ w)
{
    int gw = (blockIdx.x * 256 + threadIdx.x) >> 5;
    int lane = threadIdx.x & 31;
    int b = gw >> 10, dfull = gw & 1023;
    const float* wr = w + (size_t)(2048 + dfull) * CC;
    const float* xs = g_xsum + b * CC;
    float s = 0.0f;
    #pragma unroll 8
    for (int i = lane; i < CC; i += 32) s += xs[i] * wr[i];
    #pragma unroll
    for (int o = 16; o; o >>= 1) s += __shfl_xor_sync(0xffffffffu, s, o);
    if (lane == 0) g_vsum[b * CC + dfull] = s;
}

__global__ __launch_bounds__(256) void vsumw_kernel(const float* __restrict__ w2)
{
    int gw = (blockIdx.x * 256 + threadIdx.x) >> 5;
    int lane = threadIdx.x & 31;
    int b = gw >> 10, cout = gw & 1023;
    const float* wr = w2 + (size_t)cout * CC;
    const float* vs = g_vsum + b * CC;
    float s = 0.0f;
    #pragma unroll 8
    for (int i = lane; i < CC; i += 32) s += vs[i] * wr[i];
    #pragma unroll
    for (int o = 16; o; o >>= 1) s += __shfl_xor_sync(0xffffffffu, s, o);
    if (lane == 0) g_vsumw[b * CC + cout] = s;
}

// ---------------------------------------------------------------------------
// Bitonic sort of 2048 scores (descending) -> g_ssort / g_perm / g_inv.
// One CTA, 1024 threads, smem resident.
// ---------------------------------------------------------------------------
__global__ __launch_bounds__(1024) void sort_kernel(const float* __restrict__ cls)
{
    __shared__ float ss[NN];
    __shared__ int   si[NN];
    int tid = threadIdx.x;
    for (int i = tid; i < NN; i += 1024) { ss[i] = cls[i]; si[i] = i; }
    __syncthreads();
    for (int k = 2; k <= NN; k <<= 1) {
        for (int j = k >> 1; j > 0; j >>= 1) {
            for (int i = tid; i < NN; i += 1024) {
                int ixj = i ^ j;
                if (ixj > i) {
                    bool up = ((i & k) == 0);
                    float a = ss[i], c = ss[ixj];
                    bool sw = up ? (a < c) : (a > c);   // descending order
                    if (sw) {
                        ss[i] = c; ss[ixj] = a;
                        int t = si[i]; si[i] = si[ixj]; si[ixj] = t;
                    }
                }
            }
            __syncthreads();
        }
    }
    for (int i = tid; i < NN; i += 1024) {
        g_ssort[i] = ss[i];
        g_perm[i] = si[i];
        g_inv[si[i]] = i;
    }
}

// ---------------- mma helpers ----------------
__device__ __forceinline__ unsigned smem_u32(const void* p) {
    return (unsigned)__cvta_generic_to_shared(p);
}
__device__ __forceinline__ void cp16(void* smem, const void* gmem) {
    unsigned sa = smem_u32(smem);
    asm volatile("cp.async.cg.shared.global [%0], [%1], 16;\n" :: "r"(sa), "l"(gmem));
}
__device__ __forceinline__ void ldsm4(unsigned r[4], const void* p) {
    unsigned a = smem_u32(p);
    asm volatile("ldmatrix.sync.aligned.m8n8.x4.shared.b16 {%0,%1,%2,%3}, [%4];"
                 : "=r"(r[0]), "=r"(r[1]), "=r"(r[2]), "=r"(r[3]) : "r"(a));
}
__device__ __forceinline__ void ldsm4t(unsigned r[4], const void* p) {
    unsigned a = smem_u32(p);
    asm volatile("ldmatrix.sync.aligned.m8n8.x4.trans.shared.b16 {%0,%1,%2,%3}, [%4];"
                 : "=r"(r[0]), "=r"(r[1]), "=r"(r[2]), "=r"(r[3]) : "r"(a));
}
__device__ __forceinline__ void mma16816(float c[4], const unsigned a[4],
                                         unsigned b0, unsigned b1) {
    asm volatile(
        "mma.sync.aligned.m16n8k16.row.col.f32.bf16.bf16.f32 "
        "{%0,%1,%2,%3}, {%4,%5,%6,%7}, {%8,%9}, {%0,%1,%2,%3};"
        : "+f"(c[0]), "+f"(c[1]), "+f"(c[2]), "+f"(c[3])
        : "r"(a[0]), "r"(a[1]), "r"(a[2]), "r"(a[3]), "r"(b0), "r"(b1));
}
__device__ __forceinline__ float ex2f(float x) {
    float y;
    asm("ex2.approx.ftz.f32 %0, %1;" : "=f"(y) : "f"(x));
    return y;
}

#define GLDA 40
#define TILE_B (128 * GLDA * 2)   // 10240 B per 128x32 bf16 tile

// ---------------------------------------------------------------------------
// Single-pass bf16 GEMM (NT), 4-stage cp.async pipeline, 2 CTAs/SM.
// EPI=0: C = A B^T.   EPI=1: C = A B^T + invl[m]*vsumw[b][n] + bias[n].
// ---------------------------------------------------------------------------
template<int EPI>
__global__ __launch_bounds__(256, 2) void gemm1p_kernel(
    const __nv_bfloat16* __restrict__ A, const __nv_bfloat16* __restrict__ Bm,
    float* __restrict__ C, int Nn,
    const float* __restrict__ invl, const float* __restrict__ vsumw,
    const float* __restrict__ bias)
{
    extern __shared__ char sm_raw[];
    const int STAGE = 2 * TILE_B;
    int tid = threadIdx.x;
    int lane = tid & 31;
    int wid = tid >> 5;
    int warp_m = wid >> 2;
    int warp_n = wid & 3;
    int m0 = blockIdx.y * 128;
    int n0 = blockIdx.x * 128;

    float acc[4][4][4];
    #pragma unroll
    for (int mi = 0; mi < 4; ++mi)
        #pragma unroll
        for (int j = 0; j < 4; ++j)
            #pragma unroll
            for (int e = 0; e < 4; ++e) acc[mi][j][e] = 0.0f;

    auto load_stage = [&](int kt, int s) {
        char* sb = sm_raw + s * STAGE;
        int k0 = kt * 32;
        #pragma unroll
        for (int t = 0; t < 4; ++t) {
            int c = tid + t * 256;
            int arr = c >> 9;
            int r = (c >> 2) & 127;
            int c16 = c & 3;
            const __nv_bfloat16* g =
                (arr ? Bm : A) + (size_t)((arr ? n0 : m0) + r) * CC + k0 + c16 * 8;
            cp16(sb + arr * TILE_B + r * (GLDA * 2) + c16 * 16, g);
        }
    };

    const int KT = CC / 32;
    load_stage(0, 0); asm volatile("cp.async.commit_group;");
    load_stage(1, 1); asm volatile("cp.async.commit_group;");
    load_stage(2, 2); asm volatile("cp.async.commit_group;");

    for (int kt = 0; kt < KT; ++kt) {
        asm volatile("cp.async.wait_group 2;");
        __syncthreads();
        const char* As = sm_raw + (kt & 3) * STAGE;
        const char* Bs = As + TILE_B;

        #pragma unroll
        for (int ks = 0; ks < 32; ks += 16) {
            int coloff = ks + ((lane >> 4) << 3);
            unsigned ah[4][4];
            #pragma unroll
            for (int mi = 0; mi < 4; ++mi)
                ldsm4(ah[mi], As + (warp_m * 64 + mi * 16 + (lane & 15)) * (GLDA * 2)
                               + coloff * 2);
            unsigned bh[2][4];
            #pragma unroll
            for (int ni = 0; ni < 2; ++ni)
                ldsm4(bh[ni], Bs + (warp_n * 32 + ni * 16 + (lane & 15)) * (GLDA * 2)
                               + coloff * 2);
            #pragma unroll
            for (int mi = 0; mi < 4; ++mi)
                #pragma unroll
                for (int j = 0; j < 4; ++j) {
                    int ni = j >> 1, od = j & 1;
                    mma16816(acc[mi][j], ah[mi],
                             bh[ni][od ? 1 : 0], bh[ni][od ? 3 : 2]);
                }
        }
        if (kt + 3 < KT) {
            load_stage(kt + 3, (kt + 3) & 3);
            asm volatile("cp.async.commit_group;");
        }
    }

    int mb = m0 + warp_m * 64 + (lane >> 2);
    int nb = n0 + warp_n * 32 + 2 * (lane & 3);
    #pragma unroll
    for (int mi = 0; mi < 4; ++mi)
        #pragma unroll
        for (int j = 0; j < 4; ++j) {
            int col = nb + j * 8;
            int r0 = mb + mi * 16;
            float a0 = acc[mi][j][0], a1 = acc[mi][j][1];
            float a2 = acc[mi][j][2], a3 = acc[mi][j][3];
            if (EPI) {
                int b = r0 >> 11;
                float b0 = bias[col], b1 = bias[col + 1];
                float vw0 = vsumw[b * CC + col], vw1 = vsumw[b * CC + col + 1];
                float il0 = invl[r0], il8 = invl[r0 + 8];
                a0 += il0 * vw0 + b0;  a1 += il0 * vw1 + b1;
                a2 += il8 * vw0 + b0;  a3 += il8 * vw1 + b1;
            }
            *reinterpret_cast<float2*>(&C[(size_t)r0 * Nn + col]) =
                make_float2(a0, a1);
            *reinterpret_cast<float2*>(&C[(size_t)(r0 + 8) * Nn + col]) =
                make_float2(a2, a3);
        }
}

// ---------------------------------------------------------------------------
// Fused normalize + split, writing at SORTED positions (g_inv).
// ---------------------------------------------------------------------------
__global__ __launch_bounds__(256) void norm_split_kernel()
{
    int gw   = (blockIdx.x * 256 + threadIdx.x) >> 5;
    int lane = threadIdx.x & 31;
    int bn = gw >> 4;
    int h  = gw & 15;
    int b = bn >> 11, n = bn & 2047;
    int pos = g_inv[n];
    size_t src  = (size_t)bn * 3072 + h * 64;
    size_t dst  = ((size_t)(b * HH + h) * NN + pos) * 64 + 2 * lane;

    float2 q = *reinterpret_cast<const float2*>(&g_qkv[src + 2 * lane]);
    float s = q.x * q.x + q.y * q.y;
    #pragma unroll
    for (int o = 16; o; o >>= 1) s += __shfl_xor_sync(0xffffffffu, s, o);
    float inv = 0.125f / (sqrtf(s) + 1e-8f);
    *reinterpret_cast<__nv_bfloat162*>(&g_qn[dst]) =
        __floats2bfloat162_rn(q.x * inv, q.y * inv);

    float2 k = *reinterpret_cast<const float2*>(&g_qkv[src + 1024 + 2 * lane]);
    s = k.x * k.x + k.y * k.y;
    #pragma unroll
    for (int o = 16; o; o >>= 1) s += __shfl_xor_sync(0xffffffffu, s, o);
    inv = 1.0f / (sqrtf(s) + 1e-8f);
    *reinterpret_cast<__nv_bfloat162*>(&g_kn[dst]) =
        __floats2bfloat162_rn(k.x * inv, k.y * inv);

    float2 v = *reinterpret_cast<const float2*>(&g_qkv[src + 2048 + 2 * lane]);
    *reinterpret_cast<__nv_bfloat162*>(&g_vh[dst]) =
        __floats2bfloat162_rn(v.x, v.y);
}

// ---------------------------------------------------------------------------
// Tensor-core attention, delta-trick + SORTED prefix skipping.
// Tokens sorted by score desc: mask is a per-query prefix. Per CTA:
//  tiles < KT_stop processed (full tiles bypass the mask compare),
//  tiles >= KT_stop skipped entirely (delta=0; contribute count to l).
// Scores staged pre-scaled by log2e; exp via single ex2.approx.
// ---------------------------------------------------------------------------
#define ATS 72
#define KTB (128 * ATS * 2)

__global__ __launch_bounds__(256, 2) void attn_mma_kernel(const int* __restrict__ um_p)
{
    extern __shared__ char smem[];
    float* sks = (float*)(smem + 4 * KTB);
    __shared__ float sh_full[16];
    __shared__ int sh_ktstop;

    int tid = threadIdx.x;
    int lane = tid & 31;
    int warp = tid >> 5;
    int q0 = blockIdx.x * 128;
    int bh = blockIdx.y;
    int b = bh >> 4, h = bh & 15;
    int um = um_p[0];
    int r = lane >> 2;
    int c2 = 2 * (lane & 3);

    float sqmax = g_ssort[q0];
    float sqmin = g_ssort[q0 + 127];
    if (tid < 16) {
        float skmin = g_ssort[tid * 128 + 127];
        sh_full[tid] = (um == 0 || skmin > sqmax - 0.1f) ? 1.0f : 0.0f;
    }
    if (tid == 0) {
        int ks = 16;
        if (um) {
            for (int t = 1; t < 16; ++t) {
                if (g_ssort[t * 128] <= sqmin - 0.1f) { ks = t; break; }
            }
        }
        sh_ktstop = ks;
    }

    const __nv_bfloat16* qg = g_qn + ((size_t)bh * NN + q0 + warp * 16) * 64;
    unsigned qa[4][4];
    #pragma unroll
    for (int dc = 0; dc < 4; ++dc) {
        qa[dc][0] = *(const unsigned*)(qg + (size_t)r * 64 + 16 * dc + c2);
        qa[dc][1] = *(const unsigned*)(qg + (size_t)(r + 8) * 64 + 16 * dc + c2);
        qa[dc][2] = *(const unsigned*)(qg + (size_t)r * 64 + 16 * dc + 8 + c2);
        qa[dc][3] = *(const unsigned*)(qg + (size_t)(r + 8) * 64 + 16 * dc + 8 + c2);
    }
    float sq0 = (g_ssort[q0 + warp * 16 + r] - 0.1f) * LOG2E;
    float sq8 = (g_ssort[q0 + warp * 16 + r + 8] - 0.1f) * LOG2E;

    const __nv_bfloat16* kg  = g_kn + (size_t)bh * NN * 64;
    const __nv_bfloat16* vhg = g_vh + (size_t)bh * NN * 64;

    float o[8][4];
    #pragma unroll
    for (int i = 0; i < 8; ++i)
        #pragma unroll
        for (int e = 0; e < 4; ++e) o[i][e] = 0.0f;
    float l0 = 0.0f, l8 = 0.0f;

    auto stage_load = [&](int kt, int s) {
        #pragma unroll
        for (int t = 0; t < 8; ++t) {
            int cix = tid + t * 256;
            int arr = cix >> 10;
            int rr  = (cix >> 3) & 127;
            int seg = cix & 7;
            const __nv_bfloat16* gb = (arr == 0) ? kg : vhg;
            const __nv_bfloat16* g = gb + ((size_t)(kt * 128 + rr)) * 64 + seg * 8;
            cp16(smem + arr * 2 * KTB + s * KTB + rr * (ATS * 2) + seg * 16, g);
        }
        if (tid < 128) sks[s * 128 + tid] = g_ssort[kt * 128 + tid] * LOG2E;
    };

    stage_load(0, 0);
    asm volatile("cp.async.commit_group;");
    __syncthreads();                      // sh_ktstop / sh_full visible
    const int KTS = sh_ktstop;

    for (int kt = 0; kt < KTS; ++kt) {
        asm volatile("cp.async.wait_group 0;");
        __syncthreads();
        if (kt + 1 < KTS) {
            stage_load(kt + 1, (kt + 1) & 1);
            asm volatile("cp.async.commit_group;");
        }
        int s = kt & 1;
        const char* Kb  = smem + s * KTB;
        const char* Vhb = smem + 2 * KTB + s * KTB;
        const float* sk = sks + s * 128;
        // full tiles: disable the mask compare via -inf threshold
        float fullf = sh_full[kt];
        float sqe0 = (fullf != 0.0f) ? -1e30f : sq0;
        float sqe8 = (fullf != 0.0f) ? -1e30f : sq8;

        #pragma unroll
        for (int j = 0; j < 8; ++j) {
            float cc[2][4] = {{0, 0, 0, 0}, {0, 0, 0, 0}};
            int krow = 16 * j + (lane & 15);
            #pragma unroll
            for (int dc = 0; dc < 4; ++dc) {
                unsigned kb[4];
                ldsm4(kb, Kb + krow * (ATS * 2) + (16 * dc + ((lane >> 4) << 3)) * 2);
                mma16816(cc[0], qa[dc], kb[0], kb[2]);
                mma16816(cc[1], qa[dc], kb[1], kb[3]);
            }
            unsigned ad[4];
            #pragma unroll
            for (int t = 0; t < 2; ++t) {
                float2 skv = *reinterpret_cast<const float2*>(&sk[16 * j + 8 * t + c2]);
                float fx0 = (skv.x > sqe0) ? skv.x : 0.0f;
                float fy0 = (skv.y > sqe0) ? skv.y : 0.0f;
                float fx8 = (skv.x > sqe8) ? skv.x : 0.0f;
                float fy8 = (skv.y > sqe8) ? skv.y : 0.0f;
                float p00 = ex2f(cc[t][0] * fx0);
                float p01 = ex2f(cc[t][1] * fy0);
                float p80 = ex2f(cc[t][2] * fx8);
                float p81 = ex2f(cc[t][3] * fy8);
                l0 += p00 + p01;
                l8 += p80 + p81;
                __nv_bfloat162 D0 = __floats2bfloat162_rn(p00 - 1.0f, p01 - 1.0f);
                __nv_bfloat162 D8 = __floats2bfloat162_rn(p80 - 1.0f, p81 - 1.0f);
                ad[2 * t]     = *reinterpret_cast<unsigned*>(&D0);
                ad[2 * t + 1] = *reinterpret_cast<unsigned*>(&D8);
            }
            #pragma unroll
            for (int n2 = 0; n2 < 4; ++n2) {
                unsigned vb[4];
                int voff = krow * (ATS * 2) + (16 * n2 + ((lane >> 4) << 3)) * 2;
                ldsm4t(vb, Vhb + voff);
                mma16816(o[2 * n2],     ad, vb[0], vb[1]);
                mma16816(o[2 * n2 + 1], ad, vb[2], vb[3]);
            }
        }
    }

    l0 += __shfl_xor_sync(0xffffffffu, l0, 1);
    l0 += __shfl_xor_sync(0xffffffffu, l0, 2);
    l8 += __shfl_xor_sync(0xffffffffu, l8, 1);
    l8 += __shfl_xor_sync(0xffffffffu, l8, 2);
    float skipped = (float)(NN - KTS * 128);   // skipped keys: p = 1 each
    float inv0 = 1.0f / (l0 + skipped);
    float inv8 = 1.0f / (l8 + skipped);

    int qrow = q0 + warp * 16 + r;
    int orig0 = g_perm[qrow];
    int orig8 = g_perm[qrow + 8];
    size_t tok0 = (size_t)(b * NN + orig0);
    size_t tok8 = (size_t)(b * NN + orig8);
    if ((lane & 3) == 0) {
        g_invl[tok0] = inv0;
        g_invl[tok8] = inv8;
    }
    size_t row0 = tok0 * CC + h * 64;
    size_t row8 = tok8 * CC + h * 64;
    #pragma unroll
    for (int nt = 0; nt < 8; ++nt) {
        int d = 8 * nt + c2;
        *reinterpret_cast<__nv_bfloat162*>(&g_dev[row0 + d]) =
            __floats2bfloat162_rn(o[nt][0] * inv0, o[nt][1] * inv0);
        *reinterpret_cast<__nv_bfloat162*>(&g_dev[row8 + d]) =
            __floats2bfloat162_rn(o[nt][2] * inv8, o[nt][3] * inv8);
    }
}

// ---------------------------------------------------------------------------
// Launch
// ---------------------------------------------------------------------------
static const int GEMM1P_SMEM = 4 * 2 * TILE_B;   // 81920 (4 stages)
static const int ATTN_SMEM_BYTES = 4 * KTB + 2 * 128 * (int)sizeof(float);

extern "C" void kernel_launch(void* const* d_in, const int* in_sizes, int n_in,
                              void* d_out, int out_size)
{
    const float* x     = (const float*)d_in[0];
    const float* cls   = (const float*)d_in[1];
    const float* qkvw  = (const float*)d_in[2];
    const float* projw = (const float*)d_in[3];
    const float* projb = (const float*)d_in[4];
    const int*   um    = (const int*)d_in[5];
    float* out = (float*)d_out;

    float* qkv = nullptr;
    float *invl, *vsumw;
    __nv_bfloat16 *xh, *w1h, *w2h, *dev;
    cudaGetSymbolAddress((void**)&qkv,   g_qkv);
    cudaGetSymbolAddress((void**)&xh,    g_x_hi);
    cudaGetSymbolAddress((void**)&w1h,   g_w1_hi);
    cudaGetSymbolAddress((void**)&w2h,   g_w2_hi);
    cudaGetSymbolAddress((void**)&dev,   g_dev);
    cudaGetSymbolAddress((void**)&invl,  g_invl);
    cudaGetSymbolAddress((void**)&vsumw, g_vsumw);

    cudaFuncSetAttribute(gemm1p_kernel<0>,
                         cudaFuncAttributeMaxDynamicSharedMemorySize, GEMM1P_SMEM);
    cudaFuncSetAttribute(gemm1p_kernel<1>,
                         cudaFuncAttributeMaxDynamicSharedMemorySize, GEMM1P_SMEM);
    cudaFuncSetAttribute(attn_mma_kernel,
                         cudaFuncAttributeMaxDynamicSharedMemorySize, ATTN_SMEM_BYTES);

    dim3 blk(256);

    // score sort (needed by norm_split + attn)
    sort_kernel<<<1, 1024>>>(cls);

    // fused x convert + colsum partials; weight converts
    xcvt_sum_kernel<<<dim3(BB * CC / 256, 64), blk>>>(x);
    tobf16_kernel<<<(3 * CC * CC + 255) / 256, blk>>>(qkvw, w1h, 3 * CC * CC);
    tobf16_kernel<<<(CC * CC + 255) / 256, blk>>>(projw, w2h, CC * CC);

    // exact colsum chain
    xsum_final_kernel<<<BB * CC / 256, blk>>>();
    vsumx_kernel<<<BB * CC / 8, blk>>>(qkvw);
    vsumw_kernel<<<BB * CC / 8, blk>>>(projw);

    // full qkv projection: single-pass bf16, one launch (N=3072)
    gemm1p_kernel<0><<<dim3(3 * CC / 128, M_ROWS / 128), blk, GEMM1P_SMEM>>>(
        xh, w1h, qkv, 3 * CC, nullptr, nullptr, nullptr);

    norm_split_kernel<<<(M_ROWS * HH) / 8, blk>>>();

    attn_mma_kernel<<<dim3(NN / 128, BB * HH), blk, ATTN_SMEM_BYTES>>>(um);

    // output projection: out = dev.W2^T + invl*vsumw + bias
    gemm1p_kernel<1><<<dim3(CC / 128, M_ROWS / 128), blk, GEMM1P_SMEM>>>(
        dev, w2h, out, CC, invl, vsumw, projb);
}

// round 13
// speedup vs baseline: 9.5334x; 1.0648x over previous
#include <cuda_runtime.h>
#include <cuda_bf16.h>
#include <stdint.h>
#include <math.h>

#define BB 2
#define NN 2048
#define CC 1024
#define HH 16
#define HD 64
#define M_ROWS (BB*NN)   // 4096
#define LOG2E 1.4426950408889634f

// ---------------- device scratch (allocation-free) ----------------
__device__ float g_qkv[M_ROWS * 3 * CC];              // fp32 qkv [bn][3C]
__device__ __nv_bfloat16 g_x_hi[M_ROWS * CC];
__device__ __nv_bfloat16 g_w1_hi[3 * CC * CC];
__device__ __nv_bfloat16 g_w2_hi[CC * CC];
// head-major [b*H+h][sorted n][64] bf16
__device__ __nv_bfloat16 g_qn[BB * HH * NN * HD];
__device__ __nv_bfloat16 g_kn[BB * HH * NN * HD];
__device__ __nv_bfloat16 g_vh[BB * HH * NN * HD];
__device__ float g_xpart[64 * BB * CC];               // xsum partials
__device__ float g_xsum[BB * CC];
__device__ float g_vsum[BB * CC];                     // exact colsum of V
__device__ float g_vsumw[BB * CC];                    // vsum . W2^T
// score sort
__device__ float g_ssort[NN];                         // scores sorted desc
__device__ int   g_perm[NN];                          // sorted pos -> orig token
__device__ int   g_inv[NN];                           // orig token -> sorted pos
// attention deviation output (bf16) + per-row 1/l
__device__ __nv_bfloat16 g_dev[M_ROWS * CC];
__device__ float g_invl[M_ROWS];

// ---------------- elementwise / reduction kernels ----------------
__global__ __launch_bounds__(256) void tobf16_kernel(
    const float* __restrict__ in, __nv_bfloat16* __restrict__ out, int n)
{
    int i = blockIdx.x * blockDim.x + threadIdx.x;
    if (i < n) out[i] = __float2bfloat16(in[i]);
}

// Fused: x -> bf16 copy + column-sum partials.
__global__ __launch_bounds__(256) void xcvt_sum_kernel(const float* __restrict__ x)
{
    int c = blockIdx.x * 256 + threadIdx.x;
    int chunk = blockIdx.y;
    int b = c >> 10, cc = c & 1023;
    size_t base = (size_t)b * NN * CC + (size_t)chunk * 32 * CC + cc;
    float s = 0.0f;
    #pragma unroll 8
    for (int n = 0; n < 32; ++n) {
        float v = x[base + (size_t)n * CC];
        g_x_hi[base + (size_t)n * CC] = __float2bfloat16(v);
        s += v;
    }
    g_xpart[chunk * (BB * CC) + c] = s;
}
__global__ __launch_bounds__(256) void xsum_final_kernel()
{
    int c = blockIdx.x * 256 + threadIdx.x;
    float s = 0.0f;
    #pragma unroll
    for (int t = 0; t < 64; ++t) s += g_xpart[t * (BB * CC) + c];
    g_xsum[c] = s;
}

__global__ __launch_bounds__(256) void vsumx_kernel(const float* __restrict__ w)
{
    int gw = (blockIdx.x * 256 + threadIdx.x) >> 5;
    int lane = threadIdx.x & 31;
    int b = gw >> 10, dfull = gw & 1023;
    const float* wr = w + (size_t)(2048 + dfull) * CC;
    const float* xs = g_xsum + b * CC;
    float s = 0.0f;
    #pragma unroll 8
    for (int i = lane; i < CC; i += 32) s += xs[i] * wr[i];
    #pragma unroll
    for (int o = 16; o; o >>= 1) s += __shfl_xor_sync(0xffffffffu, s, o);
    if (lane == 0) g_vsum[b * CC + dfull] = s;
}

__global__ __launch_bounds__(256) void vsumw_kernel(const float* __restrict__ w2)
{
    int gw = (blockIdx.x * 256 + threadIdx.x) >> 5;
    int lane = threadIdx.x & 31;
    int b = gw >> 10, cout = gw & 1023;
    const float* wr = w2 + (size_t)cout * CC;
    const float* vs = g_vsum + b * CC;
    float s = 0.0f;
    #pragma unroll 8
    for (int i = lane; i < CC; i += 32) s += vs[i] * wr[i];
    #pragma unroll
    for (int o = 16; o; o >>= 1) s += __shfl_xor_sync(0xffffffffu, s, o);
    if (lane == 0) g_vsumw[b * CC + cout] = s;
}

// ---------------------------------------------------------------------------
// Bitonic sort of 2048 scores (descending) -> g_ssort / g_perm / g_inv.
// ---------------------------------------------------------------------------
__global__ __launch_bounds__(1024) void sort_kernel(const float* __restrict__ cls)
{
    __shared__ float ss[NN];
    __shared__ int   si[NN];
    int tid = threadIdx.x;
    for (int i = tid; i < NN; i += 1024) { ss[i] = cls[i]; si[i] = i; }
    __syncthreads();
    for (int k = 2; k <= NN; k <<= 1) {
        for (int j = k >> 1; j > 0; j >>= 1) {
            for (int i = tid; i < NN; i += 1024) {
                int ixj = i ^ j;
                if (ixj > i) {
                    bool up = ((i & k) == 0);
                    float a = ss[i], c = ss[ixj];
                    bool sw = up ? (a < c) : (a > c);
                    if (sw) {
                        ss[i] = c; ss[ixj] = a;
                        int t = si[i]; si[i] = si[ixj]; si[ixj] = t;
                    }
                }
            }
            __syncthreads();
        }
    }
    for (int i = tid; i < NN; i += 1024) {
        g_ssort[i] = ss[i];
        g_perm[i] = si[i];
        g_inv[si[i]] = i;
    }
}

// ---------------- mma helpers ----------------
__device__ __forceinline__ unsigned smem_u32(const void* p) {
    return (unsigned)__cvta_generic_to_shared(p);
}
__device__ __forceinline__ void cp16(void* smem, const void* gmem) {
    unsigned sa = smem_u32(smem);
    asm volatile("cp.async.cg.shared.global [%0], [%1], 16;\n" :: "r"(sa), "l"(gmem));
}
__device__ __forceinline__ void ldsm4(unsigned r[4], const void* p) {
    unsigned a = smem_u32(p);
    asm volatile("ldmatrix.sync.aligned.m8n8.x4.shared.b16 {%0,%1,%2,%3}, [%4];"
                 : "=r"(r[0]), "=r"(r[1]), "=r"(r[2]), "=r"(r[3]) : "r"(a));
}
__device__ __forceinline__ void ldsm4t(unsigned r[4], const void* p) {
    unsigned a = smem_u32(p);
    asm volatile("ldmatrix.sync.aligned.m8n8.x4.trans.shared.b16 {%0,%1,%2,%3}, [%4];"
                 : "=r"(r[0]), "=r"(r[1]), "=r"(r[2]), "=r"(r[3]) : "r"(a));
}
__device__ __forceinline__ void mma16816(float c[4], const unsigned a[4],
                                         unsigned b0, unsigned b1) {
    asm volatile(
        "mma.sync.aligned.m16n8k16.row.col.f32.bf16.bf16.f32 "
        "{%0,%1,%2,%3}, {%4,%5,%6,%7}, {%8,%9}, {%0,%1,%2,%3};"
        : "+f"(c[0]), "+f"(c[1]), "+f"(c[2]), "+f"(c[3])
        : "r"(a[0]), "r"(a[1]), "r"(a[2]), "r"(a[3]), "r"(b0), "r"(b1));
}
__device__ __forceinline__ float ex2f(float x) {
    float y;
    asm("ex2.approx.ftz.f32 %0, %1;" : "=f"(y) : "f"(x));
    return y;
}

#define GLDA 40
#define TILE_B (128 * GLDA * 2)   // 10240 B per 128x32 bf16 tile

// ---------------------------------------------------------------------------
// Single-pass bf16 GEMM (NT), 4-stage cp.async pipeline, 2 CTAs/SM.
// EPI=0: C = A B^T.   EPI=1: C = A B^T + invl[m]*vsumw[b][n] + bias[n].
// ---------------------------------------------------------------------------
template<int EPI>
__global__ __launch_bounds__(256, 2) void gemm1p_kernel(
    const __nv_bfloat16* __restrict__ A, const __nv_bfloat16* __restrict__ Bm,
    float* __restrict__ C, int Nn,
    const float* __restrict__ invl, const float* __restrict__ vsumw,
    const float* __restrict__ bias)
{
    extern __shared__ char sm_raw[];
    const int STAGE = 2 * TILE_B;
    int tid = threadIdx.x;
    int lane = tid & 31;
    int wid = tid >> 5;
    int warp_m = wid >> 2;
    int warp_n = wid & 3;
    int m0 = blockIdx.y * 128;
    int n0 = blockIdx.x * 128;

    float acc[4][4][4];
    #pragma unroll
    for (int mi = 0; mi < 4; ++mi)
        #pragma unroll
        for (int j = 0; j < 4; ++j)
            #pragma unroll
            for (int e = 0; e < 4; ++e) acc[mi][j][e] = 0.0f;

    auto load_stage = [&](int kt, int s) {
        char* sb = sm_raw + s * STAGE;
        int k0 = kt * 32;
        #pragma unroll
        for (int t = 0; t < 4; ++t) {
            int c = tid + t * 256;
            int arr = c >> 9;
            int r = (c >> 2) & 127;
            int c16 = c & 3;
            const __nv_bfloat16* g =
                (arr ? Bm : A) + (size_t)((arr ? n0 : m0) + r) * CC + k0 + c16 * 8;
            cp16(sb + arr * TILE_B + r * (GLDA * 2) + c16 * 16, g);
        }
    };

    const int KT = CC / 32;
    load_stage(0, 0); asm volatile("cp.async.commit_group;");
    load_stage(1, 1); asm volatile("cp.async.commit_group;");
    load_stage(2, 2); asm volatile("cp.async.commit_group;");

    for (int kt = 0; kt < KT; ++kt) {
        asm volatile("cp.async.wait_group 2;");
        __syncthreads();
        const char* As = sm_raw + (kt & 3) * STAGE;
        const char* Bs = As + TILE_B;

        #pragma unroll
        for (int ks = 0; ks < 32; ks += 16) {
            int coloff = ks + ((lane >> 4) << 3);
            unsigned ah[4][4];
            #pragma unroll
            for (int mi = 0; mi < 4; ++mi)
                ldsm4(ah[mi], As + (warp_m * 64 + mi * 16 + (lane & 15)) * (GLDA * 2)
                               + coloff * 2);
            unsigned bh[2][4];
            #pragma unroll
            for (int ni = 0; ni < 2; ++ni)
                ldsm4(bh[ni], Bs + (warp_n * 32 + ni * 16 + (lane & 15)) * (GLDA * 2)
                               + coloff * 2);
            #pragma unroll
            for (int mi = 0; mi < 4; ++mi)
                #pragma unroll
                for (int j = 0; j < 4; ++j) {
                    int ni = j >> 1, od = j & 1;
                    mma16816(acc[mi][j], ah[mi],
                             bh[ni][od ? 1 : 0], bh[ni][od ? 3 : 2]);
                }
        }
        if (kt + 3 < KT) {
            load_stage(kt + 3, (kt + 3) & 3);
            asm volatile("cp.async.commit_group;");
        }
    }

    int mb = m0 + warp_m * 64 + (lane >> 2);
    int nb = n0 + warp_n * 32 + 2 * (lane & 3);
    #pragma unroll
    for (int mi = 0; mi < 4; ++mi)
        #pragma unroll
        for (int j = 0; j < 4; ++j) {
            int col = nb + j * 8;
            int r0 = mb + mi * 16;
            float a0 = acc[mi][j][0], a1 = acc[mi][j][1];
            float a2 = acc[mi][j][2], a3 = acc[mi][j][3];
            if (EPI) {
                int b = r0 >> 11;
                float b0 = bias[col], b1 = bias[col + 1];
                float vw0 = vsumw[b * CC + col], vw1 = vsumw[b * CC + col + 1];
                float il0 = invl[r0], il8 = invl[r0 + 8];
                a0 += il0 * vw0 + b0;  a1 += il0 * vw1 + b1;
                a2 += il8 * vw0 + b0;  a3 += il8 * vw1 + b1;
            }
            *reinterpret_cast<float2*>(&C[(size_t)r0 * Nn + col]) =
                make_float2(a0, a1);
            *reinterpret_cast<float2*>(&C[(size_t)(r0 + 8) * Nn + col]) =
                make_float2(a2, a3);
        }
}

// ---------------------------------------------------------------------------
// Fused normalize + split, writing at SORTED positions (g_inv).
// ---------------------------------------------------------------------------
__global__ __launch_bounds__(256) void norm_split_kernel()
{
    int gw   = (blockIdx.x * 256 + threadIdx.x) >> 5;
    int lane = threadIdx.x & 31;
    int bn = gw >> 4;
    int h  = gw & 15;
    int b = bn >> 11, n = bn & 2047;
    int pos = g_inv[n];
    size_t src  = (size_t)bn * 3072 + h * 64;
    size_t dst  = ((size_t)(b * HH + h) * NN + pos) * 64 + 2 * lane;

    float2 q = *reinterpret_cast<const float2*>(&g_qkv[src + 2 * lane]);
    float s = q.x * q.x + q.y * q.y;
    #pragma unroll
    for (int o = 16; o; o >>= 1) s += __shfl_xor_sync(0xffffffffu, s, o);
    float inv = 0.125f / (sqrtf(s) + 1e-8f);
    *reinterpret_cast<__nv_bfloat162*>(&g_qn[dst]) =
        __floats2bfloat162_rn(q.x * inv, q.y * inv);

    float2 k = *reinterpret_cast<const float2*>(&g_qkv[src + 1024 + 2 * lane]);
    s = k.x * k.x + k.y * k.y;
    #pragma unroll
    for (int o = 16; o; o >>= 1) s += __shfl_xor_sync(0xffffffffu, s, o);
    inv = 1.0f / (sqrtf(s) + 1e-8f);
    *reinterpret_cast<__nv_bfloat162*>(&g_kn[dst]) =
        __floats2bfloat162_rn(k.x * inv, k.y * inv);

    float2 v = *reinterpret_cast<const float2*>(&g_qkv[src + 2048 + 2 * lane]);
    *reinterpret_cast<__nv_bfloat162*>(&g_vh[dst]) =
        __floats2bfloat162_rn(v.x, v.y);
}

// ---------------------------------------------------------------------------
// Tensor-core attention, delta-trick + sorted prefix skipping, PAIRED q-tiles.
// CTA(i) processes q-tiles {i, 15-i} sequentially: per-CTA work is
// KTS(i)+KTS(15-i) ~= 19-21 tiles for EVERY CTA (balanced by construction).
// Grid (8, 32) = 256 CTAs -> exactly one wave at 2 CTAs/SM.
// ---------------------------------------------------------------------------
#define ATS 72
#define KTB (128 * ATS * 2)

__global__ __launch_bounds__(256, 2) void attn_mma_kernel(const int* __restrict__ um_p)
{
    extern __shared__ char smem[];
    float* sks = (float*)(smem + 4 * KTB);
    __shared__ float sh_full[2][16];
    __shared__ int sh_ktstop[2];

    int tid = threadIdx.x;
    int lane = tid & 31;
    int warp = tid >> 5;
    int qpair = blockIdx.x;                // 0..7
    int bh = blockIdx.y;
    int b = bh >> 4, h = bh & 15;
    int um = um_p[0];
    int r = lane >> 2;
    int c2 = 2 * (lane & 3);

    // per-half metadata (half 0: q-tile qpair; half 1: q-tile 15-qpair)
    if (tid < 2) {
        int qt = tid ? (15 - qpair) : qpair;
        float sqmin = g_ssort[qt * 128 + 127];
        int ks = 16;
        if (um) {
            for (int t = 1; t < 16; ++t)
                if (g_ssort[t * 128] <= sqmin - 0.1f) { ks = t; break; }
        }
        sh_ktstop[tid] = ks;
    }
    if (tid < 32) {
        int hf = tid >> 4, t = tid & 15;
        int qt = hf ? (15 - qpair) : qpair;
        float sqmax = g_ssort[qt * 128];
        float skmin = g_ssort[t * 128 + 127];
        sh_full[hf][t] = (um == 0 || skmin > sqmax - 0.1f) ? 1.0f : 0.0f;
    }

    const __nv_bfloat16* kg  = g_kn + (size_t)bh * NN * 64;
    const __nv_bfloat16* vhg = g_vh + (size_t)bh * NN * 64;

    auto stage_load = [&](int kt, int s) {
        #pragma unroll
        for (int t = 0; t < 8; ++t) {
            int cix = tid + t * 256;
            int arr = cix >> 10;
            int rr  = (cix >> 3) & 127;
            int seg = cix & 7;
            const __nv_bfloat16* gb = (arr == 0) ? kg : vhg;
            const __nv_bfloat16* g = gb + ((size_t)(kt * 128 + rr)) * 64 + seg * 8;
            cp16(smem + arr * 2 * KTB + s * KTB + rr * (ATS * 2) + seg * 16, g);
        }
        if (tid < 128) sks[s * 128 + tid] = g_ssort[kt * 128 + tid] * LOG2E;
    };

    for (int hf = 0; hf < 2; ++hf) {
        int q0 = (hf ? (15 - qpair) : qpair) * 128;

        // Q fragments for this half
        const __nv_bfloat16* qg = g_qn + ((size_t)bh * NN + q0 + warp * 16) * 64;
        unsigned qa[4][4];
        #pragma unroll
        for (int dc = 0; dc < 4; ++dc) {
            qa[dc][0] = *(const unsigned*)(qg + (size_t)r * 64 + 16 * dc + c2);
            qa[dc][1] = *(const unsigned*)(qg + (size_t)(r + 8) * 64 + 16 * dc + c2);
            qa[dc][2] = *(const unsigned*)(qg + (size_t)r * 64 + 16 * dc + 8 + c2);
            qa[dc][3] = *(const unsigned*)(qg + (size_t)(r + 8) * 64 + 16 * dc + 8 + c2);
        }
        float sq0 = (g_ssort[q0 + warp * 16 + r] - 0.1f) * LOG2E;
        float sq8 = (g_ssort[q0 + warp * 16 + r + 8] - 0.1f) * LOG2E;

        float o[8][4];
        #pragma unroll
        for (int i = 0; i < 8; ++i)
            #pragma unroll
            for (int e = 0; e < 4; ++e) o[i][e] = 0.0f;
        float l0 = 0.0f, l8 = 0.0f;

        // barrier: metadata visible (hf=0) / previous half done with smem (hf=1)
        __syncthreads();
        const int KTS = sh_ktstop[hf];

        stage_load(0, 0);
        asm volatile("cp.async.commit_group;");

        for (int kt = 0; kt < KTS; ++kt) {
            asm volatile("cp.async.wait_group 0;");
            __syncthreads();
            if (kt + 1 < KTS) {
                stage_load(kt + 1, (kt + 1) & 1);
                asm volatile("cp.async.commit_group;");
            }
            int s = kt & 1;
            const char* Kb  = smem + s * KTB;
            const char* Vhb = smem + 2 * KTB + s * KTB;
            const float* sk = sks + s * 128;
            float fullf = sh_full[hf][kt];
            float sqe0 = (fullf != 0.0f) ? -1e30f : sq0;
            float sqe8 = (fullf != 0.0f) ? -1e30f : sq8;

            #pragma unroll
            for (int j = 0; j < 8; ++j) {
                float cc[2][4] = {{0, 0, 0, 0}, {0, 0, 0, 0}};
                int krow = 16 * j + (lane & 15);
                #pragma unroll
                for (int dc = 0; dc < 4; ++dc) {
                    unsigned kb[4];
                    ldsm4(kb, Kb + krow * (ATS * 2) + (16 * dc + ((lane >> 4) << 3)) * 2);
                    mma16816(cc[0], qa[dc], kb[0], kb[2]);
                    mma16816(cc[1], qa[dc], kb[1], kb[3]);
                }
                unsigned ad[4];
                #pragma unroll
                for (int t = 0; t < 2; ++t) {
                    float2 skv = *reinterpret_cast<const float2*>(&sk[16 * j + 8 * t + c2]);
                    float fx0 = (skv.x > sqe0) ? skv.x : 0.0f;
                    float fy0 = (skv.y > sqe0) ? skv.y : 0.0f;
                    float fx8 = (skv.x > sqe8) ? skv.x : 0.0f;
                    float fy8 = (skv.y > sqe8) ? skv.y : 0.0f;
                    float p00 = ex2f(cc[t][0] * fx0);
                    float p01 = ex2f(cc[t][1] * fy0);
                    float p80 = ex2f(cc[t][2] * fx8);
                    float p81 = ex2f(cc[t][3] * fy8);
                    l0 += p00 + p01;
                    l8 += p80 + p81;
                    __nv_bfloat162 D0 = __floats2bfloat162_rn(p00 - 1.0f, p01 - 1.0f);
                    __nv_bfloat162 D8 = __floats2bfloat162_rn(p80 - 1.0f, p81 - 1.0f);
                    ad[2 * t]     = *reinterpret_cast<unsigned*>(&D0);
                    ad[2 * t + 1] = *reinterpret_cast<unsigned*>(&D8);
                }
                #pragma unroll
                for (int n2 = 0; n2 < 4; ++n2) {
                    unsigned vb[4];
                    int voff = krow * (ATS * 2) + (16 * n2 + ((lane >> 4) << 3)) * 2;
                    ldsm4t(vb, Vhb + voff);
                    mma16816(o[2 * n2],     ad, vb[0], vb[1]);
                    mma16816(o[2 * n2 + 1], ad, vb[2], vb[3]);
                }
            }
        }

        l0 += __shfl_xor_sync(0xffffffffu, l0, 1);
        l0 += __shfl_xor_sync(0xffffffffu, l0, 2);
        l8 += __shfl_xor_sync(0xffffffffu, l8, 1);
        l8 += __shfl_xor_sync(0xffffffffu, l8, 2);
        float skipped = (float)(NN - KTS * 128);   // skipped keys: p = 1 each
        float inv0 = 1.0f / (l0 + skipped);
        float inv8 = 1.0f / (l8 + skipped);

        int qrow = q0 + warp * 16 + r;
        int orig0 = g_perm[qrow];
        int orig8 = g_perm[qrow + 8];
        size_t tok0 = (size_t)(b * NN + orig0);
        size_t tok8 = (size_t)(b * NN + orig8);
        if ((lane & 3) == 0) {
            g_invl[tok0] = inv0;
            g_invl[tok8] = inv8;
        }
        size_t row0 = tok0 * CC + h * 64;
        size_t row8 = tok8 * CC + h * 64;
        #pragma unroll
        for (int nt = 0; nt < 8; ++nt) {
            int d = 8 * nt + c2;
            *reinterpret_cast<__nv_bfloat162*>(&g_dev[row0 + d]) =
                __floats2bfloat162_rn(o[nt][0] * inv0, o[nt][1] * inv0);
            *reinterpret_cast<__nv_bfloat162*>(&g_dev[row8 + d]) =
                __floats2bfloat162_rn(o[nt][2] * inv8, o[nt][3] * inv8);
        }
    }
}

// ---------------------------------------------------------------------------
// Launch
// ---------------------------------------------------------------------------
static const int GEMM1P_SMEM = 4 * 2 * TILE_B;   // 81920 (4 stages)
static const int ATTN_SMEM_BYTES = 4 * KTB + 2 * 128 * (int)sizeof(float);

extern "C" void kernel_launch(void* const* d_in, const int* in_sizes, int n_in,
                              void* d_out, int out_size)
{
    const float* x     = (const float*)d_in[0];
    const float* cls   = (const float*)d_in[1];
    const float* qkvw  = (const float*)d_in[2];
    const float* projw = (const float*)d_in[3];
    const float* projb = (const float*)d_in[4];
    const int*   um    = (const int*)d_in[5];
    float* out = (float*)d_out;

    float* qkv = nullptr;
    float *invl, *vsumw;
    __nv_bfloat16 *xh, *w1h, *w2h, *dev;
    cudaGetSymbolAddress((void**)&qkv,   g_qkv);
    cudaGetSymbolAddress((void**)&xh,    g_x_hi);
    cudaGetSymbolAddress((void**)&w1h,   g_w1_hi);
    cudaGetSymbolAddress((void**)&w2h,   g_w2_hi);
    cudaGetSymbolAddress((void**)&dev,   g_dev);
    cudaGetSymbolAddress((void**)&invl,  g_invl);
    cudaGetSymbolAddress((void**)&vsumw, g_vsumw);

    cudaFuncSetAttribute(gemm1p_kernel<0>,
                         cudaFuncAttributeMaxDynamicSharedMemorySize, GEMM1P_SMEM);
    cudaFuncSetAttribute(gemm1p_kernel<1>,
                         cudaFuncAttributeMaxDynamicSharedMemorySize, GEMM1P_SMEM);
    cudaFuncSetAttribute(attn_mma_kernel,
                         cudaFuncAttributeMaxDynamicSharedMemorySize, ATTN_SMEM_BYTES);

    dim3 blk(256);

    // score sort (needed by norm_split + attn)
    sort_kernel<<<1, 1024>>>(cls);

    // fused x convert + colsum partials; weight converts
    xcvt_sum_kernel<<<dim3(BB * CC / 256, 64), blk>>>(x);
    tobf16_kernel<<<(3 * CC * CC + 255) / 256, blk>>>(qkvw, w1h, 3 * CC * CC);
    tobf16_kernel<<<(CC * CC + 255) / 256, blk>>>(projw, w2h, CC * CC);

    // exact colsum chain
    xsum_final_kernel<<<BB * CC / 256, blk>>>();
    vsumx_kernel<<<BB * CC / 8, blk>>>(qkvw);
    vsumw_kernel<<<BB * CC / 8, blk>>>(projw);

    // full qkv projection: single-pass bf16, one launch (N=3072)
    gemm1p_kernel<0><<<dim3(3 * CC / 128, M_ROWS / 128), blk, GEMM1P_SMEM>>>(
        xh, w1h, qkv, 3 * CC, nullptr, nullptr, nullptr);

    norm_split_kernel<<<(M_ROWS * HH) / 8, blk>>>();

    // paired-q-tile attention: one balanced wave
    attn_mma_kernel<<<dim3(8, BB * HH), blk, ATTN_SMEM_BYTES>>>(um);

    // output projection: out = dev.W2^T + invl*vsumw + bias
    gemm1p_kernel<1><<<dim3(CC / 128, M_ROWS / 128), blk, GEMM1P_SMEM>>>(
        dev, w2h, out, CC, invl, vsumw, projb);
}

// round 14
// speedup vs baseline: 10.1628x; 1.0660x over previous
#include <cuda_runtime.h>
#include <cuda_bf16.h>
#include <stdint.h>
#include <math.h>

#define BB 2
#define NN 2048
#define CC 1024
#define HH 16
#define HD 64
#define M_ROWS (BB*NN)   // 4096
#define LOG2E 1.4426950408889634f

// ---------------- device scratch (allocation-free) ----------------
__device__ __nv_bfloat16 g_x_hi[M_ROWS * CC];
__device__ __nv_bfloat16 g_w1_hi[3 * CC * CC];
__device__ __nv_bfloat16 g_w2_hi[CC * CC];
// head-major [b*H+h][sorted n][64] bf16
__device__ __nv_bfloat16 g_qn[BB * HH * NN * HD];
__device__ __nv_bfloat16 g_kn[BB * HH * NN * HD];
__device__ __nv_bfloat16 g_vh[BB * HH * NN * HD];
__device__ float g_xpart[64 * BB * CC];               // xsum partials
__device__ float g_xsum[BB * CC];
__device__ float g_vsum[BB * CC];                     // exact colsum of V
__device__ float g_vsumw[BB * CC];                    // vsum . W2^T
// score sort
__device__ float g_ssort[NN];                         // scores sorted desc
__device__ int   g_perm[NN];                          // sorted pos -> orig token
__device__ int   g_inv[NN];                           // orig token -> sorted pos
// attention deviation output (bf16) + per-row 1/l
__device__ __nv_bfloat16 g_dev[M_ROWS * CC];
__device__ float g_invl[M_ROWS];

// ---------------- elementwise / reduction kernels ----------------
// merged weight converts: [0,3CC^2) from w1, [3CC^2,4CC^2) from w2
__global__ __launch_bounds__(256) void wcvt_kernel(
    const float* __restrict__ w1, const float* __restrict__ w2)
{
    int i = blockIdx.x * blockDim.x + threadIdx.x;
    const int n1 = 3 * CC * CC;
    if (i < n1) g_w1_hi[i] = __float2bfloat16(w1[i]);
    else        g_w2_hi[i - n1] = __float2bfloat16(w2[i - n1]);
}

// Fused: x -> bf16 copy + column-sum partials.
__global__ __launch_bounds__(256) void xcvt_sum_kernel(const float* __restrict__ x)
{
    int c = blockIdx.x * 256 + threadIdx.x;
    int chunk = blockIdx.y;
    int b = c >> 10, cc = c & 1023;
    size_t base = (size_t)b * NN * CC + (size_t)chunk * 32 * CC + cc;
    float s = 0.0f;
    #pragma unroll 8
    for (int n = 0; n < 32; ++n) {
        float v = x[base + (size_t)n * CC];
        g_x_hi[base + (size_t)n * CC] = __float2bfloat16(v);
        s += v;
    }
    g_xpart[chunk * (BB * CC) + c] = s;
}
__global__ __launch_bounds__(256) void xsum_final_kernel()
{
    int c = blockIdx.x * 256 + threadIdx.x;
    float s = 0.0f;
    #pragma unroll
    for (int t = 0; t < 64; ++t) s += g_xpart[t * (BB * CC) + c];
    g_xsum[c] = s;
}

__global__ __launch_bounds__(256) void vsumx_kernel(const float* __restrict__ w)
{
    int gw = (blockIdx.x * 256 + threadIdx.x) >> 5;
    int lane = threadIdx.x & 31;
    int b = gw >> 10, dfull = gw & 1023;
    const float* wr = w + (size_t)(2048 + dfull) * CC;
    const float* xs = g_xsum + b * CC;
    float s = 0.0f;
    #pragma unroll 8
    for (int i = lane; i < CC; i += 32) s += xs[i] * wr[i];
    #pragma unroll
    for (int o = 16; o; o >>= 1) s += __shfl_xor_sync(0xffffffffu, s, o);
    if (lane == 0) g_vsum[b * CC + dfull] = s;
}

__global__ __launch_bounds__(256) void vsumw_kernel(const float* __restrict__ w2)
{
    int gw = (blockIdx.x * 256 + threadIdx.x) >> 5;
    int lane = threadIdx.x & 31;
    int b = gw >> 10, cout = gw & 1023;
    const float* wr = w2 + (size_t)cout * CC;
    const float* vs = g_vsum + b * CC;
    float s = 0.0f;
    #pragma unroll 8
    for (int i = lane; i < CC; i += 32) s += vs[i] * wr[i];
    #pragma unroll
    for (int o = 16; o; o >>= 1) s += __shfl_xor_sync(0xffffffffu, s, o);
    if (lane == 0) g_vsumw[b * CC + cout] = s;
}

// ---------------------------------------------------------------------------
// Bitonic sort of 2048 scores (descending) -> g_ssort / g_perm / g_inv.
// ---------------------------------------------------------------------------
__global__ __launch_bounds__(1024) void sort_kernel(const float* __restrict__ cls)
{
    __shared__ float ss[NN];
    __shared__ int   si[NN];
    int tid = threadIdx.x;
    for (int i = tid; i < NN; i += 1024) { ss[i] = cls[i]; si[i] = i; }
    __syncthreads();
    for (int k = 2; k <= NN; k <<= 1) {
        for (int j = k >> 1; j > 0; j >>= 1) {
            for (int i = tid; i < NN; i += 1024) {
                int ixj = i ^ j;
                if (ixj > i) {
                    bool up = ((i & k) == 0);
                    float a = ss[i], c = ss[ixj];
                    bool sw = up ? (a < c) : (a > c);
                    if (sw) {
                        ss[i] = c; ss[ixj] = a;
                        int t = si[i]; si[i] = si[ixj]; si[ixj] = t;
                    }
                }
            }
            __syncthreads();
        }
    }
    for (int i = tid; i < NN; i += 1024) {
        g_ssort[i] = ss[i];
        g_perm[i] = si[i];
        g_inv[si[i]] = i;
    }
}

// ---------------- mma helpers ----------------
__device__ __forceinline__ unsigned smem_u32(const void* p) {
    return (unsigned)__cvta_generic_to_shared(p);
}
__device__ __forceinline__ void cp16(void* smem, const void* gmem) {
    unsigned sa = smem_u32(smem);
    asm volatile("cp.async.cg.shared.global [%0], [%1], 16;\n" :: "r"(sa), "l"(gmem));
}
__device__ __forceinline__ void ldsm4(unsigned r[4], const void* p) {
    unsigned a = smem_u32(p);
    asm volatile("ldmatrix.sync.aligned.m8n8.x4.shared.b16 {%0,%1,%2,%3}, [%4];"
                 : "=r"(r[0]), "=r"(r[1]), "=r"(r[2]), "=r"(r[3]) : "r"(a));
}
__device__ __forceinline__ void ldsm4t(unsigned r[4], const void* p) {
    unsigned a = smem_u32(p);
    asm volatile("ldmatrix.sync.aligned.m8n8.x4.trans.shared.b16 {%0,%1,%2,%3}, [%4];"
                 : "=r"(r[0]), "=r"(r[1]), "=r"(r[2]), "=r"(r[3]) : "r"(a));
}
__device__ __forceinline__ void mma16816(float c[4], const unsigned a[4],
                                         unsigned b0, unsigned b1) {
    asm volatile(
        "mma.sync.aligned.m16n8k16.row.col.f32.bf16.bf16.f32 "
        "{%0,%1,%2,%3}, {%4,%5,%6,%7}, {%8,%9}, {%0,%1,%2,%3};"
        : "+f"(c[0]), "+f"(c[1]), "+f"(c[2]), "+f"(c[3])
        : "r"(a[0]), "r"(a[1]), "r"(a[2]), "r"(a[3]), "r"(b0), "r"(b1));
}
__device__ __forceinline__ float ex2f(float x) {
    float y;
    asm("ex2.approx.ftz.f32 %0, %1;" : "=f"(y) : "f"(x));
    return y;
}

#define GLDA 40
#define TILE_B (128 * GLDA * 2)   // 10240 B per 128x32 bf16 tile

// ---------------------------------------------------------------------------
// Single-pass bf16 GEMM (NT), 4-stage cp.async pipeline, 2 CTAs/SM.
// MODE=1: C = A B^T + invl[m]*vsumw[b][n] + bias[n]   (output projection)
// MODE=2: qkv fused epilogue — no C write. Normalize q,k rows per head
//         (head = 64 cols, fully inside this CTA's column tile), convert to
//         bf16, write to g_qn/g_kn/g_vh at score-sorted positions (g_inv).
// ---------------------------------------------------------------------------
template<int MODE>
__global__ __launch_bounds__(256, 2) void gemm1p_kernel(
    const __nv_bfloat16* __restrict__ A, const __nv_bfloat16* __restrict__ Bm,
    float* __restrict__ C, int Nn,
    const float* __restrict__ invl, const float* __restrict__ vsumw,
    const float* __restrict__ bias)
{
    extern __shared__ char sm_raw[];
    const int STAGE = 2 * TILE_B;
    int tid = threadIdx.x;
    int lane = tid & 31;
    int wid = tid >> 5;
    int warp_m = wid >> 2;
    int warp_n = wid & 3;
    int m0 = blockIdx.y * 128;
    int n0 = blockIdx.x * 128;

    float acc[4][4][4];
    #pragma unroll
    for (int mi = 0; mi < 4; ++mi)
        #pragma unroll
        for (int j = 0; j < 4; ++j)
            #pragma unroll
            for (int e = 0; e < 4; ++e) acc[mi][j][e] = 0.0f;

    auto load_stage = [&](int kt, int s) {
        char* sb = sm_raw + s * STAGE;
        int k0 = kt * 32;
        #pragma unroll
        for (int t = 0; t < 4; ++t) {
            int c = tid + t * 256;
            int arr = c >> 9;
            int r = (c >> 2) & 127;
            int c16 = c & 3;
            const __nv_bfloat16* g =
                (arr ? Bm : A) + (size_t)((arr ? n0 : m0) + r) * CC + k0 + c16 * 8;
            cp16(sb + arr * TILE_B + r * (GLDA * 2) + c16 * 16, g);
        }
    };

    const int KT = CC / 32;
    load_stage(0, 0); asm volatile("cp.async.commit_group;");
    load_stage(1, 1); asm volatile("cp.async.commit_group;");
    load_stage(2, 2); asm volatile("cp.async.commit_group;");

    for (int kt = 0; kt < KT; ++kt) {
        // tail-correct wait: guarantee stage kt is complete
        if (kt + 2 < KT)      asm volatile("cp.async.wait_group 2;");
        else if (kt + 1 < KT) asm volatile("cp.async.wait_group 1;");
        else                  asm volatile("cp.async.wait_group 0;");
        __syncthreads();
        const char* As = sm_raw + (kt & 3) * STAGE;
        const char* Bs = As + TILE_B;

        #pragma unroll
        for (int ks = 0; ks < 32; ks += 16) {
            int coloff = ks + ((lane >> 4) << 3);
            unsigned ah[4][4];
            #pragma unroll
            for (int mi = 0; mi < 4; ++mi)
                ldsm4(ah[mi], As + (warp_m * 64 + mi * 16 + (lane & 15)) * (GLDA * 2)
                               + coloff * 2);
            unsigned bh[2][4];
            #pragma unroll
            for (int ni = 0; ni < 2; ++ni)
                ldsm4(bh[ni], Bs + (warp_n * 32 + ni * 16 + (lane & 15)) * (GLDA * 2)
                               + coloff * 2);
            #pragma unroll
            for (int mi = 0; mi < 4; ++mi)
                #pragma unroll
                for (int j = 0; j < 4; ++j) {
                    int ni = j >> 1, od = j & 1;
                    mma16816(acc[mi][j], ah[mi],
                             bh[ni][od ? 1 : 0], bh[ni][od ? 3 : 2]);
                }
        }
        if (kt + 3 < KT) {
            load_stage(kt + 3, (kt + 3) & 3);
            asm volatile("cp.async.commit_group;");
        }
    }

    if (MODE == 1) {
        int mb = m0 + warp_m * 64 + (lane >> 2);
        int nb = n0 + warp_n * 32 + 2 * (lane & 3);
        #pragma unroll
        for (int mi = 0; mi < 4; ++mi)
            #pragma unroll
            for (int j = 0; j < 4; ++j) {
                int col = nb + j * 8;
                int r0 = mb + mi * 16;
                int b = r0 >> 11;
                float b0 = bias[col], b1 = bias[col + 1];
                float vw0 = vsumw[b * CC + col], vw1 = vsumw[b * CC + col + 1];
                float il0 = invl[r0], il8 = invl[r0 + 8];
                float a0 = acc[mi][j][0] + il0 * vw0 + b0;
                float a1 = acc[mi][j][1] + il0 * vw1 + b1;
                float a2 = acc[mi][j][2] + il8 * vw0 + b0;
                float a3 = acc[mi][j][3] + il8 * vw1 + b1;
                *reinterpret_cast<float2*>(&C[(size_t)r0 * Nn + col]) =
                    make_float2(a0, a1);
                *reinterpret_cast<float2*>(&C[(size_t)(r0 + 8) * Nn + col]) =
                    make_float2(a2, a3);
            }
    } else {
        // MODE == 2: fused norm/split/sort-permute epilogue
        int part = n0 >> 10;                     // 0=q, 1=k, 2=v
        int h = ((n0 & 1023) >> 6) + (warp_n >> 1);
        float* red = (float*)sm_raw;             // [4 warps_n][128 rows]
        __syncthreads();                         // smem stages no longer needed

        if (part < 2) {
            #pragma unroll
            for (int mi = 0; mi < 4; ++mi) {
                float s0 = 0.0f, s8 = 0.0f;
                #pragma unroll
                for (int j = 0; j < 4; ++j) {
                    s0 += acc[mi][j][0] * acc[mi][j][0] + acc[mi][j][1] * acc[mi][j][1];
                    s8 += acc[mi][j][2] * acc[mi][j][2] + acc[mi][j][3] * acc[mi][j][3];
                }
                s0 += __shfl_xor_sync(0xffffffffu, s0, 1);
                s0 += __shfl_xor_sync(0xffffffffu, s0, 2);
                s8 += __shfl_xor_sync(0xffffffffu, s8, 1);
                s8 += __shfl_xor_sync(0xffffffffu, s8, 2);
                if ((lane & 3) == 0) {
                    int lr = warp_m * 64 + mi * 16 + (lane >> 2);
                    red[warp_n * 128 + lr] = s0;
                    red[warp_n * 128 + lr + 8] = s8;
                }
            }
            __syncthreads();
        }

        float qsc = (part == 0) ? 0.125f : 1.0f;
        __nv_bfloat16* dst = (part == 0) ? g_qn : (part == 1 ? g_kn : g_vh);
        int pbase = (warp_n & 2) * 128;
        int dbase = (warp_n & 1) * 32 + 2 * (lane & 3);

        #pragma unroll
        for (int mi = 0; mi < 4; ++mi) {
            int lr0 = warp_m * 64 + mi * 16 + (lane >> 2);
            int r0 = m0 + lr0;
            float inv0 = 1.0f, inv8 = 1.0f;
            if (part < 2) {
                float s0 = red[pbase + lr0] + red[pbase + 128 + lr0];
                float s8 = red[pbase + lr0 + 8] + red[pbase + 128 + lr0 + 8];
                inv0 = qsc / (sqrtf(s0) + 1e-8f);
                inv8 = qsc / (sqrtf(s8) + 1e-8f);
            }
            int b = r0 >> 11;
            int pos0 = g_inv[r0 & 2047];
            int pos8 = g_inv[(r0 + 8) & 2047];
            size_t base0 = ((size_t)(b * HH + h) * NN + pos0) * 64;
            size_t base8 = ((size_t)(b * HH + h) * NN + pos8) * 64;
            #pragma unroll
            for (int j = 0; j < 4; ++j) {
                int d = dbase + j * 8;
                __nv_bfloat162 v0 =
                    __floats2bfloat162_rn(acc[mi][j][0] * inv0, acc[mi][j][1] * inv0);
                __nv_bfloat162 v8 =
                    __floats2bfloat162_rn(acc[mi][j][2] * inv8, acc[mi][j][3] * inv8);
                *reinterpret_cast<__nv_bfloat162*>(dst + base0 + d) = v0;
                *reinterpret_cast<__nv_bfloat162*>(dst + base8 + d) = v8;
            }
        }
    }
}

// ---------------------------------------------------------------------------
// Attention tile body: MASK=false is the full-tile fast path (no SELs).
// ---------------------------------------------------------------------------
#define ATS 72
#define KTB (128 * ATS * 2)

template<bool MASK>
__device__ __forceinline__ void attn_tile(
    const char* Kb, const char* Vhb, const float* sk,
    const unsigned qa[4][4], float sq0, float sq8,
    float o[8][4], float& l0, float& l8, int lane, int c2)
{
    #pragma unroll
    for (int j = 0; j < 8; ++j) {
        float cc[2][4] = {{0, 0, 0, 0}, {0, 0, 0, 0}};
        int krow = 16 * j + (lane & 15);
        #pragma unroll
        for (int dc = 0; dc < 4; ++dc) {
            unsigned kb[4];
            ldsm4(kb, Kb + krow * (ATS * 2) + (16 * dc + ((lane >> 4) << 3)) * 2);
            mma16816(cc[0], qa[dc], kb[0], kb[2]);
            mma16816(cc[1], qa[dc], kb[1], kb[3]);
        }
        unsigned ad[4];
        #pragma unroll
        for (int t = 0; t < 2; ++t) {
            float2 skv = *reinterpret_cast<const float2*>(&sk[16 * j + 8 * t + c2]);
            float fx0 = skv.x, fy0 = skv.y, fx8 = skv.x, fy8 = skv.y;
            if (MASK) {
                fx0 = (skv.x > sq0) ? skv.x : 0.0f;
                fy0 = (skv.y > sq0) ? skv.y : 0.0f;
                fx8 = (skv.x > sq8) ? skv.x : 0.0f;
                fy8 = (skv.y > sq8) ? skv.y : 0.0f;
            }
            float p00 = ex2f(cc[t][0] * fx0);
            float p01 = ex2f(cc[t][1] * fy0);
            float p80 = ex2f(cc[t][2] * fx8);
            float p81 = ex2f(cc[t][3] * fy8);
            l0 += p00 + p01;
            l8 += p80 + p81;
            __nv_bfloat162 D0 = __floats2bfloat162_rn(p00 - 1.0f, p01 - 1.0f);
            __nv_bfloat162 D8 = __floats2bfloat162_rn(p80 - 1.0f, p81 - 1.0f);
            ad[2 * t]     = *reinterpret_cast<unsigned*>(&D0);
            ad[2 * t + 1] = *reinterpret_cast<unsigned*>(&D8);
        }
        #pragma unroll
        for (int n2 = 0; n2 < 4; ++n2) {
            unsigned vb[4];
            int voff = krow * (ATS * 2) + (16 * n2 + ((lane >> 4) << 3)) * 2;
            ldsm4t(vb, Vhb + voff);
            mma16816(o[2 * n2],     ad, vb[0], vb[1]);
            mma16816(o[2 * n2 + 1], ad, vb[2], vb[3]);
        }
    }
}

// ---------------------------------------------------------------------------
// Tensor-core attention, delta-trick + sorted prefix skipping, PAIRED q-tiles.
// ---------------------------------------------------------------------------
__global__ __launch_bounds__(256, 2) void attn_mma_kernel(const int* __restrict__ um_p)
{
    extern __shared__ char smem[];
    float* sks = (float*)(smem + 4 * KTB);
    __shared__ float sh_full[2][16];
    __shared__ int sh_ktstop[2];

    int tid = threadIdx.x;
    int lane = tid & 31;
    int warp = tid >> 5;
    int qpair = blockIdx.x;                // 0..7
    int bh = blockIdx.y;
    int b = bh >> 4, h = bh & 15;
    int um = um_p[0];
    int r = lane >> 2;
    int c2 = 2 * (lane & 3);

    if (tid < 2) {
        int qt = tid ? (15 - qpair) : qpair;
        float sqmin = g_ssort[qt * 128 + 127];
        int ks = 16;
        if (um) {
            for (int t = 1; t < 16; ++t)
                if (g_ssort[t * 128] <= sqmin - 0.1f) { ks = t; break; }
        }
        sh_ktstop[tid] = ks;
    }
    if (tid < 32) {
        int hf = tid >> 4, t = tid & 15;
        int qt = hf ? (15 - qpair) : qpair;
        float sqmax = g_ssort[qt * 128];
        float skmin = g_ssort[t * 128 + 127];
        sh_full[hf][t] = (um == 0 || skmin > sqmax - 0.1f) ? 1.0f : 0.0f;
    }

    const __nv_bfloat16* kg  = g_kn + (size_t)bh * NN * 64;
    const __nv_bfloat16* vhg = g_vh + (size_t)bh * NN * 64;

    auto stage_load = [&](int kt, int s) {
        #pragma unroll
        for (int t = 0; t < 8; ++t) {
            int cix = tid + t * 256;
            int arr = cix >> 10;
            int rr  = (cix >> 3) & 127;
            int seg = cix & 7;
            const __nv_bfloat16* gb = (arr == 0) ? kg : vhg;
            const __nv_bfloat16* g = gb + ((size_t)(kt * 128 + rr)) * 64 + seg * 8;
            cp16(smem + arr * 2 * KTB + s * KTB + rr * (ATS * 2) + seg * 16, g);
        }
        if (tid < 128) sks[s * 128 + tid] = g_ssort[kt * 128 + tid] * LOG2E;
    };

    for (int hf = 0; hf < 2; ++hf) {
        int q0 = (hf ? (15 - qpair) : qpair) * 128;

        const __nv_bfloat16* qg = g_qn + ((size_t)bh * NN + q0 + warp * 16) * 64;
        unsigned qa[4][4];
        #pragma unroll
        for (int dc = 0; dc < 4; ++dc) {
            qa[dc][0] = *(const unsigned*)(qg + (size_t)r * 64 + 16 * dc + c2);
            qa[dc][1] = *(const unsigned*)(qg + (size_t)(r + 8) * 64 + 16 * dc + c2);
            qa[dc][2] = *(const unsigned*)(qg + (size_t)r * 64 + 16 * dc + 8 + c2);
            qa[dc][3] = *(const unsigned*)(qg + (size_t)(r + 8) * 64 + 16 * dc + 8 + c2);
        }
        float sq0 = (g_ssort[q0 + warp * 16 + r] - 0.1f) * LOG2E;
        float sq8 = (g_ssort[q0 + warp * 16 + r + 8] - 0.1f) * LOG2E;

        float o[8][4];
        #pragma unroll
        for (int i = 0; i < 8; ++i)
            #pragma unroll
            for (int e = 0; e < 4; ++e) o[i][e] = 0.0f;
        float l0 = 0.0f, l8 = 0.0f;

        __syncthreads();
        const int KTS = sh_ktstop[hf];

        stage_load(0, 0);
        asm volatile("cp.async.commit_group;");

        for (int kt = 0; kt < KTS; ++kt) {
            asm volatile("cp.async.wait_group 0;");
            __syncthreads();
            if (kt + 1 < KTS) {
                stage_load(kt + 1, (kt + 1) & 1);
                asm volatile("cp.async.commit_group;");
            }
            int s = kt & 1;
            const char* Kb  = smem + s * KTB;
            const char* Vhb = smem + 2 * KTB + s * KTB;
            const float* sk = sks + s * 128;
            if (sh_full[hf][kt] != 0.0f)
                attn_tile<false>(Kb, Vhb, sk, qa, sq0, sq8, o, l0, l8, lane, c2);
            else
                attn_tile<true>(Kb, Vhb, sk, qa, sq0, sq8, o, l0, l8, lane, c2);
        }

        l0 += __shfl_xor_sync(0xffffffffu, l0, 1);
        l0 += __shfl_xor_sync(0xffffffffu, l0, 2);
        l8 += __shfl_xor_sync(0xffffffffu, l8, 1);
        l8 += __shfl_xor_sync(0xffffffffu, l8, 2);
        float skipped = (float)(NN - KTS * 128);
        float inv0 = 1.0f / (l0 + skipped);
        float inv8 = 1.0f / (l8 + skipped);

        int qrow = q0 + warp * 16 + r;
        int orig0 = g_perm[qrow];
        int orig8 = g_perm[qrow + 8];
        size_t tok0 = (size_t)(b * NN + orig0);
        size_t tok8 = (size_t)(b * NN + orig8);
        if ((lane & 3) == 0) {
            g_invl[tok0] = inv0;
            g_invl[tok8] = inv8;
        }
        size_t row0 = tok0 * CC + h * 64;
        size_t row8 = tok8 * CC + h * 64;
        #pragma unroll
        for (int nt = 0; nt < 8; ++nt) {
            int d = 8 * nt + c2;
            *reinterpret_cast<__nv_bfloat162*>(&g_dev[row0 + d]) =
                __floats2bfloat162_rn(o[nt][0] * inv0, o[nt][1] * inv0);
            *reinterpret_cast<__nv_bfloat162*>(&g_dev[row8 + d]) =
                __floats2bfloat162_rn(o[nt][2] * inv8, o[nt][3] * inv8);
        }
    }
}

// ---------------------------------------------------------------------------
// Launch
// ---------------------------------------------------------------------------
static const int GEMM1P_SMEM = 4 * 2 * TILE_B;   // 81920 (4 stages)
static const int ATTN_SMEM_BYTES = 4 * KTB + 2 * 128 * (int)sizeof(float);

extern "C" void kernel_launch(void* const* d_in, const int* in_sizes, int n_in,
                              void* d_out, int out_size)
{
    const float* x     = (const float*)d_in[0];
    const float* cls   = (const float*)d_in[1];
    const float* qkvw  = (const float*)d_in[2];
    const float* projw = (const float*)d_in[3];
    const float* projb = (const float*)d_in[4];
    const int*   um    = (const int*)d_in[5];
    float* out = (float*)d_out;

    float *invl, *vsumw;
    __nv_bfloat16 *xh, *w1h, *w2h, *dev;
    cudaGetSymbolAddress((void**)&xh,    g_x_hi);
    cudaGetSymbolAddress((void**)&w1h,   g_w1_hi);
    cudaGetSymbolAddress((void**)&w2h,   g_w2_hi);
    cudaGetSymbolAddress((void**)&dev,   g_dev);
    cudaGetSymbolAddress((void**)&invl,  g_invl);
    cudaGetSymbolAddress((void**)&vsumw, g_vsumw);

    cudaFuncSetAttribute(gemm1p_kernel<1>,
                         cudaFuncAttributeMaxDynamicSharedMemorySize, GEMM1P_SMEM);
    cudaFuncSetAttribute(gemm1p_kernel<2>,
                         cudaFuncAttributeMaxDynamicSharedMemorySize, GEMM1P_SMEM);
    cudaFuncSetAttribute(attn_mma_kernel,
                         cudaFuncAttributeMaxDynamicSharedMemorySize, ATTN_SMEM_BYTES);

    dim3 blk(256);

    // score sort (g_inv needed by qkv gemm epilogue)
    sort_kernel<<<1, 1024>>>(cls);

    // fused x convert + colsum partials; merged weight converts
    xcvt_sum_kernel<<<dim3(BB * CC / 256, 64), blk>>>(x);
    wcvt_kernel<<<(4 * CC * CC) / 256, blk>>>(qkvw, projw);

    // exact colsum chain
    xsum_final_kernel<<<BB * CC / 256, blk>>>();
    vsumx_kernel<<<BB * CC / 8, blk>>>(qkvw);
    vsumw_kernel<<<BB * CC / 8, blk>>>(projw);

    // qkv projection with fused norm/split/sort epilogue (no fp32 round trip)
    gemm1p_kernel<2><<<dim3(3 * CC / 128, M_ROWS / 128), blk, GEMM1P_SMEM>>>(
        xh, w1h, nullptr, 0, nullptr, nullptr, nullptr);

    // paired-q-tile attention: one balanced wave
    attn_mma_kernel<<<dim3(8, BB * HH), blk, ATTN_SMEM_BYTES>>>(um);

    // output projection: out = dev.W2^T + invl*vsumw + bias
    gemm1p_kernel<1><<<dim3(CC / 128, M_ROWS / 128), blk, GEMM1P_SMEM>>>(
        dev, w2h, out, CC, invl, vsumw, projb);
}